// round 1
// baseline (speedup 1.0000x reference)
#include <cuda_runtime.h>
#include <cuda_bf16.h>
#include <math.h>

// ---------------------------------------------------------------------------
// SALAD pipeline, fp32 SIMT baseline.
// Shapes: B=32, C=1536, HW=1024, hidden=512, L=128, M=64 (+dustbin), G=256.
// ---------------------------------------------------------------------------

#define B_SZ 32
#define C_SZ 1536
#define HW   1024
#define HID  512
#define L_D  128
#define M_CL 64
#define G_D  256
#define EPSV 1e-12f

// Scratch (device globals; allocation-free rule)
__device__ float g_H[(size_t)B_SZ * 1024 * HW];     // [B][1024][HW]: rows 0-511 cf hidden, 512-1023 sc hidden
__device__ float g_F[(size_t)B_SZ * L_D * HW];      // [B][128][HW]
__device__ float g_Z[(size_t)B_SZ * (M_CL + 1) * HW]; // [B][65][HW]: Z0, then P in rows 0..63
__device__ float g_AGG[(size_t)B_SZ * L_D * M_CL];  // [B][128][64]
__device__ float g_TKH[(size_t)B_SZ * HID];         // token hidden
__device__ float g_TK[(size_t)B_SZ * G_D];          // token out

// ---------------------------------------------------------------------------
// Tiled fp32 GEMM:  C[b] = act(A @ B[b] + bias)
//   A: [M,K] row-major (weights, shared across batch)
//   B: [K,N] row-major per batch (row stride = N)
//   C: [M,N] row-major per batch
// 128x128x16 tiles, 256 threads, 8x8 per thread. N,K must be multiples of
// tile dims; M is guarded.
// ---------------------------------------------------------------------------
#define GBM 128
#define GBN 128
#define GBK 16
#define GTM 8
#define GTN 8

template<bool RELU>
__global__ __launch_bounds__(256)
void gemm_bias(const float* __restrict__ A, const float* __restrict__ Bg,
               const float* __restrict__ bias, float* __restrict__ Cg,
               int M, int N, int K, long bStride, long cStride)
{
    __shared__ float As[GBK][GBM + 4];
    __shared__ float Bs[GBK][GBN + 4];

    const int bx = blockIdx.x, by = blockIdx.y, bz = blockIdx.z;
    const float* Bp = Bg + (size_t)bz * bStride;
    float*       Cp = Cg + (size_t)bz * cStride;

    const int tid = threadIdx.x;
    const int tx = tid & 15, ty = tid >> 4;
    const int row0 = by * GBM, col0 = bx * GBN;

    float acc[GTM][GTN];
    #pragma unroll
    for (int i = 0; i < GTM; ++i)
        #pragma unroll
        for (int j = 0; j < GTN; ++j) acc[i][j] = 0.f;

    for (int k0 = 0; k0 < K; k0 += GBK) {
        // load A tile (transposed into As[k][m]) and B tile
        #pragma unroll
        for (int r = 0; r < 2; ++r) {
            int id = tid + 256 * r;
            // A: id in [0,512): m = id/4, kv = (id%4)*4
            int m  = id >> 2;
            int kv = (id & 3) << 2;
            float4 av = make_float4(0.f, 0.f, 0.f, 0.f);
            if (row0 + m < M)
                av = *reinterpret_cast<const float4*>(&A[(size_t)(row0 + m) * K + k0 + kv]);
            As[kv + 0][m] = av.x; As[kv + 1][m] = av.y;
            As[kv + 2][m] = av.z; As[kv + 3][m] = av.w;
            // B: id in [0,512): k = id/32, nv = (id%32)*4
            int kk = id >> 5;
            int nv = (id & 31) << 2;
            float4 bv = *reinterpret_cast<const float4*>(&Bp[(size_t)(k0 + kk) * N + col0 + nv]);
            *reinterpret_cast<float4*>(&Bs[kk][nv]) = bv;
        }
        __syncthreads();

        #pragma unroll
        for (int k = 0; k < GBK; ++k) {
            float ra[GTM], rb[GTN];
            #pragma unroll
            for (int i = 0; i < GTM; ++i) ra[i] = As[k][ty * GTM + i];
            #pragma unroll
            for (int j = 0; j < GTN; ++j) rb[j] = Bs[k][tx * GTN + j];
            #pragma unroll
            for (int i = 0; i < GTM; ++i)
                #pragma unroll
                for (int j = 0; j < GTN; ++j)
                    acc[i][j] = fmaf(ra[i], rb[j], acc[i][j]);
        }
        __syncthreads();
    }

    #pragma unroll
    for (int i = 0; i < GTM; ++i) {
        int row = row0 + ty * GTM + i;
        if (row < M) {
            float bb = bias[row];
            #pragma unroll
            for (int j = 0; j < GTN; j += 4) {
                float4 o;
                o.x = acc[i][j + 0] + bb;
                o.y = acc[i][j + 1] + bb;
                o.z = acc[i][j + 2] + bb;
                o.w = acc[i][j + 3] + bb;
                if (RELU) {
                    o.x = fmaxf(o.x, 0.f); o.y = fmaxf(o.y, 0.f);
                    o.z = fmaxf(o.z, 0.f); o.w = fmaxf(o.w, 0.f);
                }
                *reinterpret_cast<float4*>(&Cp[(size_t)row * N + col0 + tx * GTN + j]) = o;
            }
        }
    }
}

// ---------------------------------------------------------------------------
// Token MLP: hidden = relu(t @ W1^T + b1), out = hidden @ W2^T + b2
// One block per batch, warp-per-output dot products.
// ---------------------------------------------------------------------------
__global__ __launch_bounds__(256)
void token_hidden_kernel(const float* __restrict__ t, const float* __restrict__ w1,
                         const float* __restrict__ b1)
{
    __shared__ float ts[C_SZ];
    const int b = blockIdx.x;
    for (int c = threadIdx.x; c < C_SZ; c += 256) ts[c] = t[(size_t)b * C_SZ + c];
    __syncthreads();
    const int wid = threadIdx.x >> 5, lane = threadIdx.x & 31;
    for (int o = wid; o < HID; o += 8) {
        const float* wr = w1 + (size_t)o * C_SZ;
        float s = 0.f;
        for (int c = lane; c < C_SZ; c += 32) s = fmaf(ts[c], wr[c], s);
        #pragma unroll
        for (int off = 16; off; off >>= 1) s += __shfl_xor_sync(0xFFFFFFFFu, s, off);
        if (lane == 0) g_TKH[(size_t)b * HID + o] = fmaxf(s + b1[o], 0.f);
    }
}

__global__ __launch_bounds__(256)
void token_out_kernel(const float* __restrict__ w2, const float* __restrict__ b2)
{
    __shared__ float hs[HID];
    const int b = blockIdx.x;
    for (int c = threadIdx.x; c < HID; c += 256) hs[c] = g_TKH[(size_t)b * HID + c];
    __syncthreads();
    const int wid = threadIdx.x >> 5, lane = threadIdx.x & 31;
    for (int o = wid; o < G_D; o += 8) {
        const float* wr = w2 + (size_t)o * HID;
        float s = 0.f;
        for (int c = lane; c < HID; c += 32) s = fmaf(hs[c], wr[c], s);
        #pragma unroll
        for (int off = 16; off; off >>= 1) s += __shfl_xor_sync(0xFFFFFFFFu, s, off);
        if (lane == 0) g_TK[(size_t)b * G_D + o] = s + b2[o];
    }
}

// ---------------------------------------------------------------------------
// Log-space Sinkhorn, one block per batch. Z rows 0..63 already hold scores;
// row 64 is set to alpha here. After 3 iterations the first 64 rows are
// overwritten with P = exp(Z + u + v - norm).
// ---------------------------------------------------------------------------
__global__ __launch_bounds__(256)
void sinkhorn_kernel(const float* __restrict__ alpha_p)
{
    const int b = blockIdx.x;
    float* Zb = g_Z + (size_t)b * (M_CL + 1) * HW;

    __shared__ float u[M_CL + 1];
    __shared__ float v[HW];

    const int tid = threadIdx.x;
    const float alpha = *alpha_p;
    const float norm = -logf((float)(M_CL + HW));              // -log(1088)
    const float log_mu_last = logf((float)(HW - M_CL)) + norm; // log(960) + norm

    for (int j = tid; j < HW; j += 256) {
        Zb[(size_t)M_CL * HW + j] = alpha;
        v[j] = 0.f;
    }
    __syncthreads();

    const int wid = tid >> 5, lane = tid & 31;

    for (int it = 0; it < 3; ++it) {
        // --- u update: rows 0..64, warp per row ---
        for (int i = wid; i < M_CL + 1; i += 8) {
            const float* zr = Zb + (size_t)i * HW;
            float vals[32];
            float mx = -INFINITY;
            #pragma unroll
            for (int k = 0; k < 32; ++k) {
                float z = zr[lane + 32 * k] + v[lane + 32 * k];
                vals[k] = z;
                mx = fmaxf(mx, z);
            }
            #pragma unroll
            for (int off = 16; off; off >>= 1)
                mx = fmaxf(mx, __shfl_xor_sync(0xFFFFFFFFu, mx, off));
            float s = 0.f;
            #pragma unroll
            for (int k = 0; k < 32; ++k) s += __expf(vals[k] - mx);
            #pragma unroll
            for (int off = 16; off; off >>= 1) s += __shfl_xor_sync(0xFFFFFFFFu, s, off);
            if (lane == 0) {
                float lm = (i < M_CL) ? norm : log_mu_last;
                u[i] = lm - (mx + logf(s));
            }
        }
        __syncthreads();

        // --- v update: streaming LSE down each column ---
        for (int j = tid; j < HW; j += 256) {
            float mx = Zb[j] + u[0];
            float s = 1.f;
            for (int i = 1; i < M_CL + 1; ++i) {
                float z = Zb[(size_t)i * HW + j] + u[i];
                if (z > mx) { s = s * __expf(mx - z) + 1.f; mx = z; }
                else        { s += __expf(z - mx); }
            }
            v[j] = norm - (mx + logf(s));
        }
        __syncthreads();
    }

    // --- P = exp(Z + u + v - norm) for rows 0..63 (in place) ---
    for (int idx = tid; idx < M_CL * HW; idx += 256) {
        int i = idx >> 10, j = idx & (HW - 1);
        Zb[idx] = __expf(Zb[idx] + u[i] + v[j] - norm);
    }
}

// ---------------------------------------------------------------------------
// agg[b][l][m] = sum_n F[b][l][n] * P[b][m][n]   (NT GEMM, one block/batch)
// ---------------------------------------------------------------------------
__global__ __launch_bounds__(256)
void agg_kernel()
{
    const int b = blockIdx.x;
    const float* Fb = g_F + (size_t)b * L_D * HW;
    const float* Pb = g_Z + (size_t)b * (M_CL + 1) * HW;
    float*       Cb = g_AGG + (size_t)b * L_D * M_CL;

    __shared__ float Fs[32][L_D + 4];   // [k][l]
    __shared__ float Ps[32][M_CL + 4];  // [k][m]

    const int tid = threadIdx.x;
    const int tx = tid & 15, ty = tid >> 4;   // tx -> m (4 each), ty -> l (8 each)

    float acc[8][4];
    #pragma unroll
    for (int i = 0; i < 8; ++i)
        #pragma unroll
        for (int j = 0; j < 4; ++j) acc[i][j] = 0.f;

    for (int n0 = 0; n0 < HW; n0 += 32) {
        #pragma unroll
        for (int r = 0; r < 4; ++r) {   // F tile: 128 x 32
            int id = tid + 256 * r;
            int l = id >> 3, kq = (id & 7) << 2;
            float4 fv = *reinterpret_cast<const float4*>(&Fb[(size_t)l * HW + n0 + kq]);
            Fs[kq + 0][l] = fv.x; Fs[kq + 1][l] = fv.y;
            Fs[kq + 2][l] = fv.z; Fs[kq + 3][l] = fv.w;
        }
        #pragma unroll
        for (int r = 0; r < 2; ++r) {   // P tile: 64 x 32
            int id = tid + 256 * r;
            int m = id >> 3, kq = (id & 7) << 2;
            float4 pv = *reinterpret_cast<const float4*>(&Pb[(size_t)m * HW + n0 + kq]);
            Ps[kq + 0][m] = pv.x; Ps[kq + 1][m] = pv.y;
            Ps[kq + 2][m] = pv.z; Ps[kq + 3][m] = pv.w;
        }
        __syncthreads();

        #pragma unroll
        for (int k = 0; k < 32; ++k) {
            float rl[8], rm[4];
            #pragma unroll
            for (int i = 0; i < 8; ++i) rl[i] = Fs[k][ty * 8 + i];
            #pragma unroll
            for (int j = 0; j < 4; ++j) rm[j] = Ps[k][tx * 4 + j];
            #pragma unroll
            for (int i = 0; i < 8; ++i)
                #pragma unroll
                for (int j = 0; j < 4; ++j)
                    acc[i][j] = fmaf(rl[i], rm[j], acc[i][j]);
        }
        __syncthreads();
    }

    #pragma unroll
    for (int i = 0; i < 8; ++i)
        #pragma unroll
        for (int j = 0; j < 4; ++j)
            Cb[(size_t)(ty * 8 + i) * M_CL + tx * 4 + j] = acc[i][j];
}

// ---------------------------------------------------------------------------
// Finalize: per-(b,m) L2 norm of agg over l, L2 norm of tk, concat, global L2.
// Output layout per batch: [tk_norm (256), agg.reshape(l*64+m) (8192)]
// ---------------------------------------------------------------------------
__device__ __forceinline__ float block_sum256(float val, float* red)
{
    const int lane = threadIdx.x & 31, wid = threadIdx.x >> 5;
    #pragma unroll
    for (int off = 16; off; off >>= 1) val += __shfl_xor_sync(0xFFFFFFFFu, val, off);
    if (lane == 0) red[wid] = val;
    __syncthreads();
    float s = red[0] + red[1] + red[2] + red[3] + red[4] + red[5] + red[6] + red[7];
    __syncthreads();
    return s;
}

__global__ __launch_bounds__(256)
void finalize_kernel(float* __restrict__ out)
{
    const int b = blockIdx.x;
    const int tid = threadIdx.x;
    __shared__ float an[L_D * M_CL];
    __shared__ float tkn[G_D];
    __shared__ float cn[M_CL];
    __shared__ float red[8];

    const float* aggb = g_AGG + (size_t)b * L_D * M_CL;

    // tk L2 norm (exactly 256 threads = G_D elements)
    float tv = g_TK[(size_t)b * G_D + tid];
    float tk_ss = block_sum256(tv * tv, red);
    tkn[tid] = tv / fmaxf(sqrtf(tk_ss), EPSV);

    // per-column norms over l
    if (tid < M_CL) {
        float s = 0.f;
        for (int l = 0; l < L_D; ++l) {
            float a = aggb[(size_t)l * M_CL + tid];
            s = fmaf(a, a, s);
        }
        cn[tid] = fmaxf(sqrtf(s), EPSV);
    }
    __syncthreads();

    // normalized agg + global sum of squares
    float gs = tkn[tid] * tkn[tid];
    for (int idx = tid; idx < L_D * M_CL; idx += 256) {
        float a = aggb[idx] / cn[idx & (M_CL - 1)];
        an[idx] = a;
        gs = fmaf(a, a, gs);
    }
    float total = block_sum256(gs, red);
    float scale = 1.f / fmaxf(sqrtf(total), EPSV);

    float* ob = out + (size_t)b * (G_D + L_D * M_CL);
    ob[tid] = tkn[tid] * scale;
    for (int idx = tid; idx < L_D * M_CL; idx += 256)
        ob[G_D + idx] = an[idx] * scale;
}

// ---------------------------------------------------------------------------
// Launch
// ---------------------------------------------------------------------------
extern "C" void kernel_launch(void* const* d_in, const int* in_sizes, int n_in,
                              void* d_out, int out_size)
{
    const float* x      = (const float*)d_in[0];
    const float* t      = (const float*)d_in[1];
    const float* cf_w1  = (const float*)d_in[2];
    const float* cf_b1  = (const float*)d_in[3];
    const float* cf_w2  = (const float*)d_in[4];
    const float* cf_b2  = (const float*)d_in[5];
    const float* sc_w1  = (const float*)d_in[6];
    const float* sc_b1  = (const float*)d_in[7];
    const float* sc_w2  = (const float*)d_in[8];
    const float* sc_b2  = (const float*)d_in[9];
    const float* tk_w1  = (const float*)d_in[10];
    const float* tk_b1  = (const float*)d_in[11];
    const float* tk_w2  = (const float*)d_in[12];
    const float* tk_b2  = (const float*)d_in[13];
    const float* dust   = (const float*)d_in[14];

    float *H, *F, *Z;
    cudaGetSymbolAddress((void**)&H, g_H);
    cudaGetSymbolAddress((void**)&F, g_F);
    cudaGetSymbolAddress((void**)&Z, g_Z);

    const long bS1 = (long)C_SZ * HW;        // x batch stride
    const long hS  = (long)1024 * HW;        // g_H batch stride

    // Hidden GEMMs: relu(W1 @ x + b1), K=1536
    gemm_bias<true ><<<dim3(HW / GBN, HID / GBM, B_SZ), 256>>>(
        cf_w1, x, cf_b1, H, HID, HW, C_SZ, bS1, hS);
    gemm_bias<true ><<<dim3(HW / GBN, HID / GBM, B_SZ), 256>>>(
        sc_w1, x, sc_b1, H + (size_t)HID * HW, HID, HW, C_SZ, bS1, hS);

    // Second-level GEMMs, K=512
    gemm_bias<false><<<dim3(HW / GBN, 1, B_SZ), 256>>>(
        cf_w2, H, cf_b2, F, L_D, HW, HID, hS, (long)L_D * HW);
    gemm_bias<false><<<dim3(HW / GBN, 1, B_SZ), 256>>>(
        sc_w2, H + (size_t)HID * HW, sc_b2, Z, M_CL, HW, HID, hS,
        (long)(M_CL + 1) * HW);

    // Token MLP (independent of the above; tiny)
    token_hidden_kernel<<<B_SZ, 256>>>(t, tk_w1, tk_b1);
    token_out_kernel<<<B_SZ, 256>>>(tk_w2, tk_b2);

    // Sinkhorn + aggregation + normalization
    sinkhorn_kernel<<<B_SZ, 256>>>(dust);
    agg_kernel<<<B_SZ, 256>>>();
    finalize_kernel<<<B_SZ, 256>>>((float*)d_out);
}

// round 3
// speedup vs baseline: 2.3405x; 2.3405x over previous
#include <cuda_runtime.h>
#include <cuda_bf16.h>
#include <math.h>
#include <stdint.h>

// ---------------------------------------------------------------------------
// SALAD pipeline. Round 3: hidden GEMMs on HMMA (mma.sync bf16, family-common
// PTX only -- tcgen05 is unavailable at .target sm_103). bf16 hi/lo split,
// 3 products -> ~fp32 precision.
// Shapes: B=32, C=1536, HW=1024, hidden=512, L=128, M=64 (+dustbin), G=256.
// ---------------------------------------------------------------------------

#define B_SZ 32
#define C_SZ 1536
#define HW   1024
#define HID  512
#define L_D  128
#define M_CL 64
#define G_D  256
#define EPSV 1e-12f

// Scratch (device globals; allocation-free rule)
__device__ __align__(256) float g_H[(size_t)B_SZ * 1024 * HW];       // [B][1024][HW]
__device__ __align__(256) float g_F[(size_t)B_SZ * L_D * HW];        // [B][128][HW]
__device__ __align__(256) float g_Z[(size_t)B_SZ * (M_CL + 1) * HW]; // [B][65][HW]
__device__ __align__(256) float g_AGG[(size_t)B_SZ * L_D * M_CL];
__device__ __align__(256) float g_TKH[(size_t)B_SZ * HID];
__device__ __align__(256) float g_TK[(size_t)B_SZ * G_D];

// bf16 split operands for the tensor-core GEMM
__device__ __align__(256) __nv_bfloat16 g_Xh[(size_t)B_SZ * HW * C_SZ]; // x^T [b][n][c] hi
__device__ __align__(256) __nv_bfloat16 g_Xl[(size_t)B_SZ * HW * C_SZ]; // x^T lo
__device__ __align__(256) __nv_bfloat16 g_Wh[(size_t)1024 * C_SZ];      // [cf_w1; sc_w1] hi
__device__ __align__(256) __nv_bfloat16 g_Wl[(size_t)1024 * C_SZ];      // lo
__device__ __align__(256) float g_B1c[1024];                            // [cf_b1; sc_b1]

// ---------------------------------------------------------------------------
// PTX helpers (family-common only)
// ---------------------------------------------------------------------------
__device__ __forceinline__ uint32_t smem_u32(const void* p) {
    uint32_t a;
    asm("{ .reg .u64 t; cvta.to.shared.u64 t, %1; cvt.u32.u64 %0, t; }"
        : "=r"(a) : "l"(p));
    return a;
}

__device__ __forceinline__ void cp16(uint32_t saddr, const void* gaddr) {
    asm volatile("cp.async.cg.shared.global [%0], [%1], 16;"
                 :: "r"(saddr), "l"(gaddr) : "memory");
}

#define LDSM_X4(r0, r1, r2, r3, addr) \
    asm volatile("ldmatrix.sync.aligned.m8n8.x4.shared.b16 {%0,%1,%2,%3}, [%4];" \
                 : "=r"(r0), "=r"(r1), "=r"(r2), "=r"(r3) : "r"(addr))

#define MMA_BF16(d, a, b0, b1) \
    asm volatile("mma.sync.aligned.m16n8k16.row.col.f32.bf16.bf16.f32 " \
                 "{%0,%1,%2,%3}, {%4,%5,%6,%7}, {%8,%9}, {%0,%1,%2,%3};" \
                 : "+f"((d)[0]), "+f"((d)[1]), "+f"((d)[2]), "+f"((d)[3]) \
                 : "r"((a)[0]), "r"((a)[1]), "r"((a)[2]), "r"((a)[3]), \
                   "r"(b0), "r"(b1))

// ---------------------------------------------------------------------------
// Conversion kernels: fp32 -> bf16 hi/lo split
// ---------------------------------------------------------------------------
__device__ __forceinline__ void split_bf16(float v, __nv_bfloat16& hi, __nv_bfloat16& lo) {
    hi = __float2bfloat16(v);
    lo = __float2bfloat16(v - __bfloat162float(hi));
}

__global__ __launch_bounds__(256)
void convert_w_kernel(const float* __restrict__ cf_w1, const float* __restrict__ sc_w1,
                      const float* __restrict__ cf_b1, const float* __restrict__ sc_b1)
{
    size_t idx = (size_t)blockIdx.x * 256 + threadIdx.x;
    const size_t total = (size_t)1024 * C_SZ;
    if (idx < total) {
        size_t row = idx / C_SZ;
        float v = (row < HID) ? cf_w1[idx] : sc_w1[idx - (size_t)HID * C_SZ];
        __nv_bfloat16 hi, lo; split_bf16(v, hi, lo);
        g_Wh[idx] = hi; g_Wl[idx] = lo;
    }
    if (idx < 1024)
        g_B1c[idx] = (idx < HID) ? cf_b1[idx] : sc_b1[idx - HID];
}

// Transpose x [b][c][n] -> x^T [b][n][c], split into bf16 hi/lo. 32x32 tiles.
__global__ __launch_bounds__(256)
void convert_x_kernel(const float* __restrict__ x)
{
    __shared__ float t[32][33];
    const int n0 = blockIdx.x * 32, c0 = blockIdx.y * 32, b = blockIdx.z;
    const int tx = threadIdx.x & 31, ty = threadIdx.x >> 5; // 32x8

    const float* xb = x + (size_t)b * C_SZ * HW;
    #pragma unroll
    for (int i = 0; i < 4; ++i) {
        int c = c0 + ty + 8 * i;
        t[ty + 8 * i][tx] = xb[(size_t)c * HW + n0 + tx];
    }
    __syncthreads();
    #pragma unroll
    for (int i = 0; i < 4; ++i) {
        int n = n0 + ty + 8 * i;
        float v = t[tx][ty + 8 * i];
        __nv_bfloat16 hi, lo; split_bf16(v, hi, lo);
        size_t o = ((size_t)b * HW + n) * C_SZ + c0 + tx;
        g_Xh[o] = hi; g_Xl[o] = lo;
    }
}

// ---------------------------------------------------------------------------
// HMMA GEMM:  H[b] = relu(Wc @ X[b]^T + b1c)
//   Wc: [1024,1536] bf16 hi/lo, K-major;  X^T: [b][n][c] bf16 hi/lo, K-major
//   CTA tile M=128 x N=128, K-chunk 64 bf16 (128 B/row), double buffer.
//   8 warps: 2(m) x 4(n), warp tile 64x32.
//   Per k16 step: hi*hi + lo*hi + hi*lo into fp32 accumulators.
// ---------------------------------------------------------------------------
#define MT 128
#define NT 128
#define KC 64
#define NCHUNK (C_SZ / KC)            // 24
#define TILE16K (128 * 128)           // bytes per 128x64-bf16 matrix
#define OFF_AH 0
#define OFF_AL (1 * TILE16K)
#define OFF_BH (2 * TILE16K)
#define OFF_BL (3 * TILE16K)
#define STAGE_BYTES (4 * TILE16K)     // 64 KB
#define GEMM1_SMEM (2 * STAGE_BYTES)  // 128 KB

__global__ __launch_bounds__(256, 1)
void mma_gemm1_kernel(const __nv_bfloat16* __restrict__ Wh, const __nv_bfloat16* __restrict__ Wl,
                      const __nv_bfloat16* __restrict__ Xh, const __nv_bfloat16* __restrict__ Xl,
                      const float* __restrict__ bias, float* __restrict__ Hout)
{
    extern __shared__ char dsmem[];
    const uint32_t smem_base = smem_u32(dsmem);

    const int tid = threadIdx.x;
    const int b  = blockIdx.z;
    const int n0 = blockIdx.x * NT;
    const int m0 = blockIdx.y * MT;

    const __nv_bfloat16* Whb = Wh + (size_t)m0 * C_SZ;
    const __nv_bfloat16* Wlb = Wl + (size_t)m0 * C_SZ;
    const __nv_bfloat16* Xhb = Xh + ((size_t)b * HW + n0) * C_SZ;
    const __nv_bfloat16* Xlb = Xl + ((size_t)b * HW + n0) * C_SZ;

    const int lane = tid & 31, warp = tid >> 5;
    const int wm = warp >> 2, wn = warp & 3;   // warp tile: rows wm*64, cols wn*32

    // ldmatrix lane addressing (byte offsets within a 128x64bf16 tile)
    // A atoms: lanes 0-15 -> rows +0..15 (k lo 16B grp), lanes 16-31 -> same rows, k hi grp
    const uint32_t lx = (uint32_t)(lane & 7);                   // xor key
    const uint32_t aRow = (uint32_t)(wm * 64 + (lane & 15));
    const uint32_t aG   = (uint32_t)(lane >> 4);
    const uint32_t aRowOff = aRow * 128u;
    // B atoms (two n8 atoms per ldmatrix.x4)
    const uint32_t bRow = (uint32_t)(wn * 32 + ((lane >> 4) << 3) + (lane & 7));
    const uint32_t bG   = (uint32_t)((lane >> 3) & 1);
    const uint32_t bRowOff = bRow * 128u;

    float acc[4][4][4];
    #pragma unroll
    for (int i = 0; i < 4; ++i)
        #pragma unroll
        for (int j = 0; j < 4; ++j)
            #pragma unroll
            for (int q = 0; q < 4; ++q) acc[i][j][q] = 0.f;

    // chunk loader: 1024 16B groups per matrix, 4 matrices, 256 threads
    auto load_chunk = [&](int c, uint32_t sb) {
        const size_t kk = (size_t)c * KC;
        #pragma unroll
        for (int i = 0; i < 4; ++i) {
            int idx = tid + 256 * i;
            int r = idx >> 3, g = idx & 7;
            uint32_t so = (uint32_t)r * 128u + (uint32_t)((g ^ (r & 7)) << 4);
            const char* wh = (const char*)(Whb + (size_t)r * C_SZ + kk) + g * 16;
            const char* wl = (const char*)(Wlb + (size_t)r * C_SZ + kk) + g * 16;
            const char* xh = (const char*)(Xhb + (size_t)r * C_SZ + kk) + g * 16;
            const char* xl = (const char*)(Xlb + (size_t)r * C_SZ + kk) + g * 16;
            cp16(sb + OFF_AH + so, wh);
            cp16(sb + OFF_AL + so, wl);
            cp16(sb + OFF_BH + so, xh);
            cp16(sb + OFF_BL + so, xl);
        }
        asm volatile("cp.async.commit_group;" ::: "memory");
    };

    load_chunk(0, smem_base);

    for (int c = 0; c < NCHUNK; ++c) {
        const uint32_t sb = smem_base + (uint32_t)(c & 1) * STAGE_BYTES;
        if (c + 1 < NCHUNK) {
            load_chunk(c + 1, smem_base + (uint32_t)((c + 1) & 1) * STAGE_BYTES);
            asm volatile("cp.async.wait_group 1;" ::: "memory");
        } else {
            asm volatile("cp.async.wait_group 0;" ::: "memory");
        }
        __syncthreads();

        #pragma unroll
        for (int ks = 0; ks < 4; ++ks) {
            const uint32_t gA = ((uint32_t)(ks * 2) + aG) ^ lx;
            const uint32_t gB = ((uint32_t)(ks * 2) + bG) ^ lx;

            uint32_t ah[16], bh[8];
            #pragma unroll
            for (int ma = 0; ma < 4; ++ma) {
                uint32_t ad = sb + OFF_AH + aRowOff + (uint32_t)(ma * 16 * 128) + (gA << 4);
                LDSM_X4(ah[4*ma+0], ah[4*ma+1], ah[4*ma+2], ah[4*ma+3], ad);
            }
            #pragma unroll
            for (int nb = 0; nb < 2; ++nb) {
                uint32_t bd = sb + OFF_BH + bRowOff + (uint32_t)(nb * 16 * 128) + (gB << 4);
                LDSM_X4(bh[4*nb+0], bh[4*nb+1], bh[4*nb+2], bh[4*nb+3], bd);
            }
            // hi * hi
            #pragma unroll
            for (int ma = 0; ma < 4; ++ma)
                #pragma unroll
                for (int na = 0; na < 4; ++na)
                    MMA_BF16(acc[ma][na], &ah[4*ma], bh[2*na], bh[2*na+1]);

            // lo * hi
            {
                uint32_t al[16];
                #pragma unroll
                for (int ma = 0; ma < 4; ++ma) {
                    uint32_t ad = sb + OFF_AL + aRowOff + (uint32_t)(ma * 16 * 128) + (gA << 4);
                    LDSM_X4(al[4*ma+0], al[4*ma+1], al[4*ma+2], al[4*ma+3], ad);
                }
                #pragma unroll
                for (int ma = 0; ma < 4; ++ma)
                    #pragma unroll
                    for (int na = 0; na < 4; ++na)
                        MMA_BF16(acc[ma][na], &al[4*ma], bh[2*na], bh[2*na+1]);
            }
            // hi * lo
            {
                uint32_t bl[8];
                #pragma unroll
                for (int nb = 0; nb < 2; ++nb) {
                    uint32_t bd = sb + OFF_BL + bRowOff + (uint32_t)(nb * 16 * 128) + (gB << 4);
                    LDSM_X4(bl[4*nb+0], bl[4*nb+1], bl[4*nb+2], bl[4*nb+3], bd);
                }
                #pragma unroll
                for (int ma = 0; ma < 4; ++ma)
                    #pragma unroll
                    for (int na = 0; na < 4; ++na)
                        MMA_BF16(acc[ma][na], &ah[4*ma], bl[2*na], bl[2*na+1]);
            }
        }
        __syncthreads();
    }

    // epilogue: bias + relu + fp32 store
    const int g  = lane >> 2;       // row within atom
    const int tc = lane & 3;        // col pair within atom
    #pragma unroll
    for (int ma = 0; ma < 4; ++ma) {
        const int r0 = m0 + wm * 64 + ma * 16 + g;
        const int r1 = r0 + 8;
        const float bb0 = bias[r0];
        const float bb1 = bias[r1];
        float* p0 = Hout + (size_t)b * (1024 * HW) + (size_t)r0 * HW + n0 + wn * 32 + tc * 2;
        float* p1 = Hout + (size_t)b * (1024 * HW) + (size_t)r1 * HW + n0 + wn * 32 + tc * 2;
        #pragma unroll
        for (int na = 0; na < 4; ++na) {
            float2 v0, v1;
            v0.x = fmaxf(acc[ma][na][0] + bb0, 0.f);
            v0.y = fmaxf(acc[ma][na][1] + bb0, 0.f);
            v1.x = fmaxf(acc[ma][na][2] + bb1, 0.f);
            v1.y = fmaxf(acc[ma][na][3] + bb1, 0.f);
            *reinterpret_cast<float2*>(p0 + na * 8) = v0;
            *reinterpret_cast<float2*>(p1 + na * 8) = v1;
        }
    }
}

// ---------------------------------------------------------------------------
// Tiled fp32 GEMM (second-level, K=512):  C[b] = A @ B[b] + bias
// ---------------------------------------------------------------------------
#define GBM 128
#define GBN 128
#define GBK 16
#define GTM 8
#define GTN 8

template<bool RELU>
__global__ __launch_bounds__(256)
void gemm_bias(const float* __restrict__ A, const float* __restrict__ Bg,
               const float* __restrict__ bias, float* __restrict__ Cg,
               int M, int N, int K, long bStride, long cStride)
{
    __shared__ float As[GBK][GBM + 4];
    __shared__ float Bs[GBK][GBN + 4];

    const int bx = blockIdx.x, by = blockIdx.y, bz = blockIdx.z;
    const float* Bp = Bg + (size_t)bz * bStride;
    float*       Cp = Cg + (size_t)bz * cStride;

    const int tid = threadIdx.x;
    const int tx = tid & 15, ty = tid >> 4;
    const int row0 = by * GBM, col0 = bx * GBN;

    float acc[GTM][GTN];
    #pragma unroll
    for (int i = 0; i < GTM; ++i)
        #pragma unroll
        for (int j = 0; j < GTN; ++j) acc[i][j] = 0.f;

    for (int k0 = 0; k0 < K; k0 += GBK) {
        #pragma unroll
        for (int r = 0; r < 2; ++r) {
            int id = tid + 256 * r;
            int m  = id >> 2;
            int kv = (id & 3) << 2;
            float4 av = make_float4(0.f, 0.f, 0.f, 0.f);
            if (row0 + m < M)
                av = *reinterpret_cast<const float4*>(&A[(size_t)(row0 + m) * K + k0 + kv]);
            As[kv + 0][m] = av.x; As[kv + 1][m] = av.y;
            As[kv + 2][m] = av.z; As[kv + 3][m] = av.w;
            int kk = id >> 5;
            int nv = (id & 31) << 2;
            float4 bv = *reinterpret_cast<const float4*>(&Bp[(size_t)(k0 + kk) * N + col0 + nv]);
            *reinterpret_cast<float4*>(&Bs[kk][nv]) = bv;
        }
        __syncthreads();

        #pragma unroll
        for (int k = 0; k < GBK; ++k) {
            float ra[GTM], rb[GTN];
            #pragma unroll
            for (int i = 0; i < GTM; ++i) ra[i] = As[k][ty * GTM + i];
            #pragma unroll
            for (int j = 0; j < GTN; ++j) rb[j] = Bs[k][tx * GTN + j];
            #pragma unroll
            for (int i = 0; i < GTM; ++i)
                #pragma unroll
                for (int j = 0; j < GTN; ++j)
                    acc[i][j] = fmaf(ra[i], rb[j], acc[i][j]);
        }
        __syncthreads();
    }

    #pragma unroll
    for (int i = 0; i < GTM; ++i) {
        int row = row0 + ty * GTM + i;
        if (row < M) {
            float bb = bias[row];
            #pragma unroll
            for (int j = 0; j < GTN; j += 4) {
                float4 o;
                o.x = acc[i][j + 0] + bb;
                o.y = acc[i][j + 1] + bb;
                o.z = acc[i][j + 2] + bb;
                o.w = acc[i][j + 3] + bb;
                if (RELU) {
                    o.x = fmaxf(o.x, 0.f); o.y = fmaxf(o.y, 0.f);
                    o.z = fmaxf(o.z, 0.f); o.w = fmaxf(o.w, 0.f);
                }
                *reinterpret_cast<float4*>(&Cp[(size_t)row * N + col0 + tx * GTN + j]) = o;
            }
        }
    }
}

// ---------------------------------------------------------------------------
// Token MLP
// ---------------------------------------------------------------------------
__global__ __launch_bounds__(256)
void token_hidden_kernel(const float* __restrict__ t, const float* __restrict__ w1,
                         const float* __restrict__ b1)
{
    __shared__ float ts[C_SZ];
    const int b = blockIdx.x;
    for (int c = threadIdx.x; c < C_SZ; c += 256) ts[c] = t[(size_t)b * C_SZ + c];
    __syncthreads();
    const int wid = threadIdx.x >> 5, lane = threadIdx.x & 31;
    for (int o = wid; o < HID; o += 8) {
        const float* wr = w1 + (size_t)o * C_SZ;
        float s = 0.f;
        for (int c = lane; c < C_SZ; c += 32) s = fmaf(ts[c], wr[c], s);
        #pragma unroll
        for (int off = 16; off; off >>= 1) s += __shfl_xor_sync(0xFFFFFFFFu, s, off);
        if (lane == 0) g_TKH[(size_t)b * HID + o] = fmaxf(s + b1[o], 0.f);
    }
}

__global__ __launch_bounds__(256)
void token_out_kernel(const float* __restrict__ w2, const float* __restrict__ b2)
{
    __shared__ float hs[HID];
    const int b = blockIdx.x;
    for (int c = threadIdx.x; c < HID; c += 256) hs[c] = g_TKH[(size_t)b * HID + c];
    __syncthreads();
    const int wid = threadIdx.x >> 5, lane = threadIdx.x & 31;
    for (int o = wid; o < G_D; o += 8) {
        const float* wr = w2 + (size_t)o * HID;
        float s = 0.f;
        for (int c = lane; c < HID; c += 32) s = fmaf(hs[c], wr[c], s);
        #pragma unroll
        for (int off = 16; off; off >>= 1) s += __shfl_xor_sync(0xFFFFFFFFu, s, off);
        if (lane == 0) g_TK[(size_t)b * G_D + o] = s + b2[o];
    }
}

// ---------------------------------------------------------------------------
// Sinkhorn (log-space), one block per batch
// ---------------------------------------------------------------------------
__global__ __launch_bounds__(256)
void sinkhorn_kernel(const float* __restrict__ alpha_p)
{
    const int b = blockIdx.x;
    float* Zb = g_Z + (size_t)b * (M_CL + 1) * HW;

    __shared__ float u[M_CL + 1];
    __shared__ float v[HW];

    const int tid = threadIdx.x;
    const float alpha = *alpha_p;
    const float norm = -logf((float)(M_CL + HW));
    const float log_mu_last = logf((float)(HW - M_CL)) + norm;

    for (int j = tid; j < HW; j += 256) {
        Zb[(size_t)M_CL * HW + j] = alpha;
        v[j] = 0.f;
    }
    __syncthreads();

    const int wid = tid >> 5, lane = tid & 31;

    for (int it = 0; it < 3; ++it) {
        for (int i = wid; i < M_CL + 1; i += 8) {
            const float* zr = Zb + (size_t)i * HW;
            float vals[32];
            float mx = -INFINITY;
            #pragma unroll
            for (int k = 0; k < 32; ++k) {
                float z = zr[lane + 32 * k] + v[lane + 32 * k];
                vals[k] = z;
                mx = fmaxf(mx, z);
            }
            #pragma unroll
            for (int off = 16; off; off >>= 1)
                mx = fmaxf(mx, __shfl_xor_sync(0xFFFFFFFFu, mx, off));
            float s = 0.f;
            #pragma unroll
            for (int k = 0; k < 32; ++k) s += __expf(vals[k] - mx);
            #pragma unroll
            for (int off = 16; off; off >>= 1) s += __shfl_xor_sync(0xFFFFFFFFu, s, off);
            if (lane == 0) {
                float lm = (i < M_CL) ? norm : log_mu_last;
                u[i] = lm - (mx + logf(s));
            }
        }
        __syncthreads();

        for (int j = tid; j < HW; j += 256) {
            float mx = Zb[j] + u[0];
            float s = 1.f;
            for (int i = 1; i < M_CL + 1; ++i) {
                float z = Zb[(size_t)i * HW + j] + u[i];
                if (z > mx) { s = s * __expf(mx - z) + 1.f; mx = z; }
                else        { s += __expf(z - mx); }
            }
            v[j] = norm - (mx + logf(s));
        }
        __syncthreads();
    }

    for (int idx = tid; idx < M_CL * HW; idx += 256) {
        int i = idx >> 10, j = idx & (HW - 1);
        Zb[idx] = __expf(Zb[idx] + u[i] + v[j] - norm);
    }
}

// ---------------------------------------------------------------------------
// agg[b][l][m] = sum_n F[b][l][n] * P[b][m][n]
// ---------------------------------------------------------------------------
__global__ __launch_bounds__(256)
void agg_kernel()
{
    const int b = blockIdx.x;
    const float* Fb = g_F + (size_t)b * L_D * HW;
    const float* Pb = g_Z + (size_t)b * (M_CL + 1) * HW;
    float*       Cb = g_AGG + (size_t)b * L_D * M_CL;

    __shared__ float Fs[32][L_D + 4];
    __shared__ float Ps[32][M_CL + 4];

    const int tid = threadIdx.x;
    const int tx = tid & 15, ty = tid >> 4;

    float acc[8][4];
    #pragma unroll
    for (int i = 0; i < 8; ++i)
        #pragma unroll
        for (int j = 0; j < 4; ++j) acc[i][j] = 0.f;

    for (int n0 = 0; n0 < HW; n0 += 32) {
        #pragma unroll
        for (int r = 0; r < 4; ++r) {
            int id = tid + 256 * r;
            int l = id >> 3, kq = (id & 7) << 2;
            float4 fv = *reinterpret_cast<const float4*>(&Fb[(size_t)l * HW + n0 + kq]);
            Fs[kq + 0][l] = fv.x; Fs[kq + 1][l] = fv.y;
            Fs[kq + 2][l] = fv.z; Fs[kq + 3][l] = fv.w;
        }
        #pragma unroll
        for (int r = 0; r < 2; ++r) {
            int id = tid + 256 * r;
            int m = id >> 3, kq = (id & 7) << 2;
            float4 pv = *reinterpret_cast<const float4*>(&Pb[(size_t)m * HW + n0 + kq]);
            Ps[kq + 0][m] = pv.x; Ps[kq + 1][m] = pv.y;
            Ps[kq + 2][m] = pv.z; Ps[kq + 3][m] = pv.w;
        }
        __syncthreads();

        #pragma unroll
        for (int k = 0; k < 32; ++k) {
            float rl[8], rm[4];
            #pragma unroll
            for (int i = 0; i < 8; ++i) rl[i] = Fs[k][ty * 8 + i];
            #pragma unroll
            for (int j = 0; j < 4; ++j) rm[j] = Ps[k][tx * 4 + j];
            #pragma unroll
            for (int i = 0; i < 8; ++i)
                #pragma unroll
                for (int j = 0; j < 4; ++j)
                    acc[i][j] = fmaf(rl[i], rm[j], acc[i][j]);
        }
        __syncthreads();
    }

    #pragma unroll
    for (int i = 0; i < 8; ++i)
        #pragma unroll
        for (int j = 0; j < 4; ++j)
            Cb[(size_t)(ty * 8 + i) * M_CL + tx * 4 + j] = acc[i][j];
}

// ---------------------------------------------------------------------------
// Finalize
// ---------------------------------------------------------------------------
__device__ __forceinline__ float block_sum256(float val, float* red)
{
    const int lane = threadIdx.x & 31, wid = threadIdx.x >> 5;
    #pragma unroll
    for (int off = 16; off; off >>= 1) val += __shfl_xor_sync(0xFFFFFFFFu, val, off);
    if (lane == 0) red[wid] = val;
    __syncthreads();
    float s = red[0] + red[1] + red[2] + red[3] + red[4] + red[5] + red[6] + red[7];
    __syncthreads();
    return s;
}

__global__ __launch_bounds__(256)
void finalize_kernel(float* __restrict__ out)
{
    const int b = blockIdx.x;
    const int tid = threadIdx.x;
    __shared__ float an[L_D * M_CL];
    __shared__ float tkn[G_D];
    __shared__ float cn[M_CL];
    __shared__ float red[8];

    const float* aggb = g_AGG + (size_t)b * L_D * M_CL;

    float tv = g_TK[(size_t)b * G_D + tid];
    float tk_ss = block_sum256(tv * tv, red);
    tkn[tid] = tv / fmaxf(sqrtf(tk_ss), EPSV);

    if (tid < M_CL) {
        float s = 0.f;
        for (int l = 0; l < L_D; ++l) {
            float a = aggb[(size_t)l * M_CL + tid];
            s = fmaf(a, a, s);
        }
        cn[tid] = fmaxf(sqrtf(s), EPSV);
    }
    __syncthreads();

    float gs = tkn[tid] * tkn[tid];
    for (int idx = tid; idx < L_D * M_CL; idx += 256) {
        float a = aggb[idx] / cn[idx & (M_CL - 1)];
        an[idx] = a;
        gs = fmaf(a, a, gs);
    }
    float total = block_sum256(gs, red);
    float scale = 1.f / fmaxf(sqrtf(total), EPSV);

    float* ob = out + (size_t)b * (G_D + L_D * M_CL);
    ob[tid] = tkn[tid] * scale;
    for (int idx = tid; idx < L_D * M_CL; idx += 256)
        ob[G_D + idx] = an[idx] * scale;
}

// ---------------------------------------------------------------------------
// Launch
// ---------------------------------------------------------------------------
extern "C" void kernel_launch(void* const* d_in, const int* in_sizes, int n_in,
                              void* d_out, int out_size)
{
    const float* x      = (const float*)d_in[0];
    const float* t      = (const float*)d_in[1];
    const float* cf_w1  = (const float*)d_in[2];
    const float* cf_b1  = (const float*)d_in[3];
    const float* cf_w2  = (const float*)d_in[4];
    const float* cf_b2  = (const float*)d_in[5];
    const float* sc_w1  = (const float*)d_in[6];
    const float* sc_b1  = (const float*)d_in[7];
    const float* sc_w2  = (const float*)d_in[8];
    const float* sc_b2  = (const float*)d_in[9];
    const float* tk_w1  = (const float*)d_in[10];
    const float* tk_b1  = (const float*)d_in[11];
    const float* tk_w2  = (const float*)d_in[12];
    const float* tk_b2  = (const float*)d_in[13];
    const float* dust   = (const float*)d_in[14];

    float *H, *F, *Z, *B1;
    __nv_bfloat16 *Xh, *Xl, *Wh, *Wl;
    cudaGetSymbolAddress((void**)&H,  g_H);
    cudaGetSymbolAddress((void**)&F,  g_F);
    cudaGetSymbolAddress((void**)&Z,  g_Z);
    cudaGetSymbolAddress((void**)&B1, g_B1c);
    cudaGetSymbolAddress((void**)&Xh, g_Xh);
    cudaGetSymbolAddress((void**)&Xl, g_Xl);
    cudaGetSymbolAddress((void**)&Wh, g_Wh);
    cudaGetSymbolAddress((void**)&Wl, g_Wl);

    cudaFuncSetAttribute(mma_gemm1_kernel,
                         cudaFuncAttributeMaxDynamicSharedMemorySize, GEMM1_SMEM);

    const long hS = (long)1024 * HW;   // g_H batch stride

    // bf16 hi/lo conversion
    convert_w_kernel<<<(1024 * C_SZ + 255) / 256, 256>>>(cf_w1, sc_w1, cf_b1, sc_b1);
    convert_x_kernel<<<dim3(HW / 32, C_SZ / 32, B_SZ), 256>>>(x);

    // fused hidden GEMM (cf + sc) on tensor cores (HMMA)
    mma_gemm1_kernel<<<dim3(HW / NT, 1024 / MT, B_SZ), 256, GEMM1_SMEM>>>(
        Wh, Wl, Xh, Xl, B1, H);

    // Second-level GEMMs, K=512 (fp32 SIMT)
    gemm_bias<false><<<dim3(HW / GBN, 1, B_SZ), 256>>>(
        cf_w2, H, cf_b2, F, L_D, HW, HID, hS, (long)L_D * HW);
    gemm_bias<false><<<dim3(HW / GBN, 1, B_SZ), 256>>>(
        sc_w2, H + (size_t)HID * HW, sc_b2, Z, M_CL, HW, HID, hS,
        (long)(M_CL + 1) * HW);

    // Token MLP
    token_hidden_kernel<<<B_SZ, 256>>>(t, tk_w1, tk_b1);
    token_out_kernel<<<B_SZ, 256>>>(tk_w2, tk_b2);

    // Sinkhorn + aggregation + normalization
    sinkhorn_kernel<<<B_SZ, 256>>>(dust);
    agg_kernel<<<B_SZ, 256>>>();
    finalize_kernel<<<B_SZ, 256>>>((float*)d_out);
}

// round 5
// speedup vs baseline: 2.7096x; 1.1577x over previous
#include <cuda_runtime.h>
#include <cuda_bf16.h>
#include <math.h>
#include <stdint.h>

// ---------------------------------------------------------------------------
// SALAD pipeline. Round 5: both GEMM levels on HMMA bf16 hi/lo (3 products).
// Fix vs R4: gemm2 B-tile warp group base wn*4 (was wn*8 -> smem OOB trap).
// Shapes: B=32, C=1536, HW=1024, hidden=512, L=128, M=64 (+dustbin), G=256.
// ---------------------------------------------------------------------------

#define B_SZ 32
#define C_SZ 1536
#define HW   1024
#define HID  512
#define L_D  128
#define M_CL 64
#define G_D  256
#define EPSV 1e-12f

// Scratch (device globals; allocation-free rule)
__device__ __align__(256) __nv_bfloat16 g_Hh[(size_t)B_SZ * 1024 * HW]; // H hi [b][k][n]
__device__ __align__(256) __nv_bfloat16 g_Hl[(size_t)B_SZ * 1024 * HW]; // H lo
__device__ __align__(256) float g_F[(size_t)B_SZ * L_D * HW];        // [B][128][HW]
__device__ __align__(256) float g_Z[(size_t)B_SZ * (M_CL + 1) * HW]; // [B][65][HW]
__device__ __align__(256) float g_AGG[(size_t)B_SZ * L_D * M_CL];
__device__ __align__(256) float g_TKH[(size_t)B_SZ * HID];
__device__ __align__(256) float g_TK[(size_t)B_SZ * G_D];

// bf16 split operands
__device__ __align__(256) __nv_bfloat16 g_Xh[(size_t)B_SZ * HW * C_SZ]; // x^T [b][n][c] hi
__device__ __align__(256) __nv_bfloat16 g_Xl[(size_t)B_SZ * HW * C_SZ]; // x^T lo
__device__ __align__(256) __nv_bfloat16 g_Wh[(size_t)1024 * C_SZ];      // [cf_w1; sc_w1] hi
__device__ __align__(256) __nv_bfloat16 g_Wl[(size_t)1024 * C_SZ];      // lo
__device__ __align__(256) __nv_bfloat16 g_W2h[(size_t)192 * HID];       // [cf_w2; sc_w2] hi
__device__ __align__(256) __nv_bfloat16 g_W2l[(size_t)192 * HID];       // lo
__device__ __align__(256) float g_B1c[1024];                            // [cf_b1; sc_b1]
__device__ __align__(256) float g_B2c[192];                             // [cf_b2; sc_b2]

// ---------------------------------------------------------------------------
// PTX helpers (family-common only)
// ---------------------------------------------------------------------------
__device__ __forceinline__ uint32_t smem_u32(const void* p) {
    uint32_t a;
    asm("{ .reg .u64 t; cvta.to.shared.u64 t, %1; cvt.u32.u64 %0, t; }"
        : "=r"(a) : "l"(p));
    return a;
}

__device__ __forceinline__ void cp16(uint32_t saddr, const void* gaddr) {
    asm volatile("cp.async.cg.shared.global [%0], [%1], 16;"
                 :: "r"(saddr), "l"(gaddr) : "memory");
}

#define LDSM_X4(r0, r1, r2, r3, addr) \
    asm volatile("ldmatrix.sync.aligned.m8n8.x4.shared.b16 {%0,%1,%2,%3}, [%4];" \
                 : "=r"(r0), "=r"(r1), "=r"(r2), "=r"(r3) : "r"(addr))

#define LDSM_X4_T(r0, r1, r2, r3, addr) \
    asm volatile("ldmatrix.sync.aligned.m8n8.x4.trans.shared.b16 {%0,%1,%2,%3}, [%4];" \
                 : "=r"(r0), "=r"(r1), "=r"(r2), "=r"(r3) : "r"(addr))

#define MMA_BF16(d, a, b0, b1) \
    asm volatile("mma.sync.aligned.m16n8k16.row.col.f32.bf16.bf16.f32 " \
                 "{%0,%1,%2,%3}, {%4,%5,%6,%7}, {%8,%9}, {%0,%1,%2,%3};" \
                 : "+f"((d)[0]), "+f"((d)[1]), "+f"((d)[2]), "+f"((d)[3]) \
                 : "r"((a)[0]), "r"((a)[1]), "r"((a)[2]), "r"((a)[3]), \
                   "r"(b0), "r"(b1))

// ---------------------------------------------------------------------------
// Conversions: fp32 -> bf16 hi/lo split
// ---------------------------------------------------------------------------
__device__ __forceinline__ void split_bf16(float v, __nv_bfloat16& hi, __nv_bfloat16& lo) {
    hi = __float2bfloat16(v);
    lo = __float2bfloat16(v - __bfloat162float(hi));
}

__global__ __launch_bounds__(256)
void convert_w_kernel(const float* __restrict__ cf_w1, const float* __restrict__ sc_w1,
                      const float* __restrict__ cf_b1, const float* __restrict__ sc_b1)
{
    size_t idx = (size_t)blockIdx.x * 256 + threadIdx.x;
    const size_t total = (size_t)1024 * C_SZ;
    if (idx < total) {
        size_t row = idx / C_SZ;
        float v = (row < HID) ? cf_w1[idx] : sc_w1[idx - (size_t)HID * C_SZ];
        __nv_bfloat16 hi, lo; split_bf16(v, hi, lo);
        g_Wh[idx] = hi; g_Wl[idx] = lo;
    }
    if (idx < 1024)
        g_B1c[idx] = (idx < HID) ? cf_b1[idx] : sc_b1[idx - HID];
}

__global__ __launch_bounds__(256)
void convert_w2_kernel(const float* __restrict__ cf_w2, const float* __restrict__ sc_w2,
                       const float* __restrict__ cf_b2, const float* __restrict__ sc_b2)
{
    size_t idx = (size_t)blockIdx.x * 256 + threadIdx.x;
    const size_t total = (size_t)192 * HID;
    if (idx < total) {
        size_t row = idx / HID;
        float v = (row < L_D) ? cf_w2[idx] : sc_w2[idx - (size_t)L_D * HID];
        __nv_bfloat16 hi, lo; split_bf16(v, hi, lo);
        g_W2h[idx] = hi; g_W2l[idx] = lo;
    }
    if (idx < 192)
        g_B2c[idx] = (idx < L_D) ? cf_b2[idx] : sc_b2[idx - L_D];
}

// Transpose x [b][c][n] -> x^T [b][n][c], split into bf16 hi/lo. 32x32 tiles.
__global__ __launch_bounds__(256)
void convert_x_kernel(const float* __restrict__ x)
{
    __shared__ float t[32][33];
    const int n0 = blockIdx.x * 32, c0 = blockIdx.y * 32, b = blockIdx.z;
    const int tx = threadIdx.x & 31, ty = threadIdx.x >> 5; // 32x8

    const float* xb = x + (size_t)b * C_SZ * HW;
    #pragma unroll
    for (int i = 0; i < 4; ++i) {
        int c = c0 + ty + 8 * i;
        t[ty + 8 * i][tx] = xb[(size_t)c * HW + n0 + tx];
    }
    __syncthreads();
    #pragma unroll
    for (int i = 0; i < 4; ++i) {
        int n = n0 + ty + 8 * i;
        float v = t[tx][ty + 8 * i];
        __nv_bfloat16 hi, lo; split_bf16(v, hi, lo);
        size_t o = ((size_t)b * HW + n) * C_SZ + c0 + tx;
        g_Xh[o] = hi; g_Xl[o] = lo;
    }
}

// ---------------------------------------------------------------------------
// GEMM1 (HMMA):  H[b] = relu(Wc @ X[b]^T + b1c), output bf16 hi/lo [b][k][n]
//   CTA tile 128(m) x 256(n), K-chunk 64, double buffer cp.async.
//   8 warps: 2(m) x 4(n), warp tile 64x64.
// ---------------------------------------------------------------------------
#define MT 128
#define NT 256
#define KC 64
#define NCHUNK (C_SZ / KC)            // 24
#define A16K (128 * 128)              // 16 KB (128 rows x 128B)
#define B16K (256 * 128)              // 32 KB
#define OFF_AH 0
#define OFF_AL (A16K)
#define OFF_BH (2 * A16K)
#define OFF_BL (2 * A16K + B16K)
#define STAGE_BYTES (2 * A16K + 2 * B16K)   // 96 KB
#define GEMM1_SMEM (2 * STAGE_BYTES)        // 192 KB

__global__ __launch_bounds__(256, 1)
void mma_gemm1_kernel(const __nv_bfloat16* __restrict__ Wh, const __nv_bfloat16* __restrict__ Wl,
                      const __nv_bfloat16* __restrict__ Xh, const __nv_bfloat16* __restrict__ Xl,
                      const float* __restrict__ bias,
                      __nv_bfloat16* __restrict__ Hh, __nv_bfloat16* __restrict__ Hl)
{
    extern __shared__ char dsmem[];
    const uint32_t smem_base = smem_u32(dsmem);

    const int tid = threadIdx.x;
    const int b  = blockIdx.z;
    const int n0 = blockIdx.x * NT;
    const int m0 = blockIdx.y * MT;

    const __nv_bfloat16* Whb = Wh + (size_t)m0 * C_SZ;
    const __nv_bfloat16* Wlb = Wl + (size_t)m0 * C_SZ;
    const __nv_bfloat16* Xhb = Xh + ((size_t)b * HW + n0) * C_SZ;
    const __nv_bfloat16* Xlb = Xl + ((size_t)b * HW + n0) * C_SZ;

    const int lane = tid & 31, warp = tid >> 5;
    const int wm = warp >> 2, wn = warp & 3;   // warp tile: rows wm*64, cols wn*64

    const uint32_t lx = (uint32_t)(lane & 7);                 // xor key (== row&7)
    const uint32_t aG   = (uint32_t)(lane >> 4);
    const uint32_t aRowOff = (uint32_t)(wm * 64 + (lane & 15)) * 128u;
    const uint32_t bG   = (uint32_t)((lane >> 3) & 1);
    const uint32_t bRowBase = (uint32_t)(wn * 64 + ((lane >> 4) << 3) + (lane & 7)) * 128u;

    float acc[4][8][4];
    #pragma unroll
    for (int i = 0; i < 4; ++i)
        #pragma unroll
        for (int j = 0; j < 8; ++j)
            #pragma unroll
            for (int q = 0; q < 4; ++q) acc[i][j][q] = 0.f;

    auto load_chunk = [&](int c, uint32_t sb) {
        const size_t kk = (size_t)c * KC;
        // A hi/lo: 128 rows x 8 groups = 1024 entries each
        #pragma unroll
        for (int i = 0; i < 4; ++i) {
            int idx = tid + 256 * i;
            int r = idx >> 3, g = idx & 7;
            uint32_t so = (uint32_t)r * 128u + (uint32_t)((g ^ (r & 7)) << 4);
            cp16(sb + OFF_AH + so, (const char*)(Whb + (size_t)r * C_SZ + kk) + g * 16);
            cp16(sb + OFF_AL + so, (const char*)(Wlb + (size_t)r * C_SZ + kk) + g * 16);
        }
        // B hi/lo: 256 rows x 8 groups = 2048 entries each
        #pragma unroll
        for (int i = 0; i < 8; ++i) {
            int idx = tid + 256 * i;
            int r = idx >> 3, g = idx & 7;
            uint32_t so = (uint32_t)r * 128u + (uint32_t)((g ^ (r & 7)) << 4);
            cp16(sb + OFF_BH + so, (const char*)(Xhb + (size_t)r * C_SZ + kk) + g * 16);
            cp16(sb + OFF_BL + so, (const char*)(Xlb + (size_t)r * C_SZ + kk) + g * 16);
        }
        asm volatile("cp.async.commit_group;" ::: "memory");
    };

    load_chunk(0, smem_base);

    for (int c = 0; c < NCHUNK; ++c) {
        const uint32_t sb = smem_base + (uint32_t)(c & 1) * STAGE_BYTES;
        if (c + 1 < NCHUNK) {
            load_chunk(c + 1, smem_base + (uint32_t)((c + 1) & 1) * STAGE_BYTES);
            asm volatile("cp.async.wait_group 1;" ::: "memory");
        } else {
            asm volatile("cp.async.wait_group 0;" ::: "memory");
        }
        __syncthreads();

        #pragma unroll
        for (int ks = 0; ks < 4; ++ks) {
            const uint32_t gA = ((uint32_t)(ks * 2) + aG) ^ lx;
            const uint32_t gB = ((uint32_t)(ks * 2) + bG) ^ lx;

            uint32_t ah[16], bh[16];
            #pragma unroll
            for (int ma = 0; ma < 4; ++ma) {
                uint32_t ad = sb + OFF_AH + aRowOff + (uint32_t)(ma * 16 * 128) + (gA << 4);
                LDSM_X4(ah[4*ma+0], ah[4*ma+1], ah[4*ma+2], ah[4*ma+3], ad);
            }
            #pragma unroll
            for (int nb = 0; nb < 4; ++nb) {
                uint32_t bd = sb + OFF_BH + bRowBase + (uint32_t)(nb * 16 * 128) + (gB << 4);
                LDSM_X4(bh[4*nb+0], bh[4*nb+1], bh[4*nb+2], bh[4*nb+3], bd);
            }
            // hi * hi
            #pragma unroll
            for (int ma = 0; ma < 4; ++ma)
                #pragma unroll
                for (int na = 0; na < 8; ++na)
                    MMA_BF16(acc[ma][na], &ah[4*ma], bh[2*na], bh[2*na+1]);

            // lo * hi (A lo)
            {
                uint32_t al[16];
                #pragma unroll
                for (int ma = 0; ma < 4; ++ma) {
                    uint32_t ad = sb + OFF_AL + aRowOff + (uint32_t)(ma * 16 * 128) + (gA << 4);
                    LDSM_X4(al[4*ma+0], al[4*ma+1], al[4*ma+2], al[4*ma+3], ad);
                }
                #pragma unroll
                for (int ma = 0; ma < 4; ++ma)
                    #pragma unroll
                    for (int na = 0; na < 8; ++na)
                        MMA_BF16(acc[ma][na], &al[4*ma], bh[2*na], bh[2*na+1]);
            }
            // hi * lo (B lo)
            {
                uint32_t bl[16];
                #pragma unroll
                for (int nb = 0; nb < 4; ++nb) {
                    uint32_t bd = sb + OFF_BL + bRowBase + (uint32_t)(nb * 16 * 128) + (gB << 4);
                    LDSM_X4(bl[4*nb+0], bl[4*nb+1], bl[4*nb+2], bl[4*nb+3], bd);
                }
                #pragma unroll
                for (int ma = 0; ma < 4; ++ma)
                    #pragma unroll
                    for (int na = 0; na < 8; ++na)
                        MMA_BF16(acc[ma][na], &ah[4*ma], bl[2*na], bl[2*na+1]);
            }
        }
        __syncthreads();
    }

    // epilogue: bias + relu -> bf16 hi/lo stores, layout [b][k=row][n]
    const int g  = lane >> 2;       // row within atom
    const int tc = lane & 3;        // col pair within atom
    #pragma unroll
    for (int ma = 0; ma < 4; ++ma) {
        const int r0 = m0 + wm * 64 + ma * 16 + g;
        const int r1 = r0 + 8;
        const float bb0 = bias[r0];
        const float bb1 = bias[r1];
        const size_t base0 = ((size_t)b * 1024 + r0) * HW + n0 + wn * 64 + tc * 2;
        const size_t base1 = ((size_t)b * 1024 + r1) * HW + n0 + wn * 64 + tc * 2;
        #pragma unroll
        for (int na = 0; na < 8; ++na) {
            float v00 = fmaxf(acc[ma][na][0] + bb0, 0.f);
            float v01 = fmaxf(acc[ma][na][1] + bb0, 0.f);
            float v10 = fmaxf(acc[ma][na][2] + bb1, 0.f);
            float v11 = fmaxf(acc[ma][na][3] + bb1, 0.f);
            __nv_bfloat16 h00, l00, h01, l01, h10, l10, h11, l11;
            split_bf16(v00, h00, l00); split_bf16(v01, h01, l01);
            split_bf16(v10, h10, l10); split_bf16(v11, h11, l11);
            *reinterpret_cast<__nv_bfloat162*>(Hh + base0 + na * 8) = __nv_bfloat162(h00, h01);
            *reinterpret_cast<__nv_bfloat162*>(Hl + base0 + na * 8) = __nv_bfloat162(l00, l01);
            *reinterpret_cast<__nv_bfloat162*>(Hh + base1 + na * 8) = __nv_bfloat162(h10, h11);
            *reinterpret_cast<__nv_bfloat162*>(Hl + base1 + na * 8) = __nv_bfloat162(l10, l11);
        }
    }
}

// ---------------------------------------------------------------------------
// GEMM2 (HMMA): [F; Z] = W2c @ H + b2c
//   A = W2c [192][512] bf16 hi/lo K-major. B = H [b][k][n] bf16 hi/lo,
//   loaded k-row-major and fed via ldmatrix.x4.trans.
//   CTA tile 64(m) x 256(n), K=512 in 8 chunks of 64. 8 warps: 1(m) x 8(n).
//   m-tile 2 (rows 128..191) reads H rows 512.. (sc hidden) and writes Z.
// ---------------------------------------------------------------------------
#define MT2 64
#define NT2 256
#define NCH2 (HID / KC)               // 8
#define S2_AH 0
#define S2_AL (8 * 1024)
#define S2_BH (16 * 1024)
#define S2_BL (48 * 1024)
#define S2_STAGE (80 * 1024)
#define GEMM2_SMEM (2 * S2_STAGE)     // 160 KB

__global__ __launch_bounds__(256, 1)
void mma_gemm2_kernel(const __nv_bfloat16* __restrict__ W2h, const __nv_bfloat16* __restrict__ W2l,
                      const __nv_bfloat16* __restrict__ Hh, const __nv_bfloat16* __restrict__ Hl,
                      const float* __restrict__ bias,
                      float* __restrict__ Fout, float* __restrict__ Zout)
{
    extern __shared__ char dsmem[];
    const uint32_t smem_base = smem_u32(dsmem);

    const int tid = threadIdx.x;
    const int b  = blockIdx.z;
    const int n0 = blockIdx.x * NT2;
    const int m0 = blockIdx.y * MT2;               // 0, 64, 128
    const int koff = (m0 == 128) ? 512 : 0;        // sc hidden rows

    const __nv_bfloat16* Ahg = W2h + (size_t)m0 * HID;
    const __nv_bfloat16* Alg = W2l + (size_t)m0 * HID;
    const __nv_bfloat16* Bhg = Hh + ((size_t)b * 1024 + koff) * HW + n0;
    const __nv_bfloat16* Blg = Hl + ((size_t)b * 1024 + koff) * HW + n0;

    const int lane = tid & 31, wn = tid >> 5;      // 8 warps along n

    float acc[4][4][4];
    #pragma unroll
    for (int i = 0; i < 4; ++i)
        #pragma unroll
        for (int j = 0; j < 4; ++j)
            #pragma unroll
            for (int q = 0; q < 4; ++q) acc[i][j][q] = 0.f;

    auto load_chunk = [&](int c, uint32_t sb) {
        const int kk = c * KC;
        // A hi/lo: 64 rows x 8 groups = 512 entries each
        #pragma unroll
        for (int i = 0; i < 2; ++i) {
            int idx = tid + 256 * i;
            int r = idx >> 3, g = idx & 7;
            uint32_t so = (uint32_t)r * 128u + (uint32_t)((g ^ (r & 7)) << 4);
            cp16(sb + S2_AH + so, (const char*)(Ahg + (size_t)r * HID + kk) + g * 16);
            cp16(sb + S2_AL + so, (const char*)(Alg + (size_t)r * HID + kk) + g * 16);
        }
        // B hi/lo: 64 k-rows x 32 groups (512B rows) = 2048 entries each
        #pragma unroll
        for (int i = 0; i < 8; ++i) {
            int idx = tid + 256 * i;
            int r = idx >> 5, g = idx & 31;
            uint32_t so = (uint32_t)r * 512u + (uint32_t)((g ^ (r & 7)) << 4);
            cp16(sb + S2_BH + so, (const char*)(Bhg + (size_t)(kk + r) * HW) + g * 16);
            cp16(sb + S2_BL + so, (const char*)(Blg + (size_t)(kk + r) * HW) + g * 16);
        }
        asm volatile("cp.async.commit_group;" ::: "memory");
    };

    load_chunk(0, smem_base);

    const uint32_t lx = (uint32_t)(lane & 7);
    const uint32_t aG = (uint32_t)(lane >> 4);
    const uint32_t aRowOff = (uint32_t)(lane & 15) * 128u;
    // B trans addressing: row = ks*16 + (lane&15); warp covers 4 groups (32 cols)
    const uint32_t bRowOff = (uint32_t)(lane & 15) * 512u;
    const uint32_t bGbase = (uint32_t)(wn * 4) + (uint32_t)(lane >> 4);

    for (int c = 0; c < NCH2; ++c) {
        const uint32_t sb = smem_base + (uint32_t)(c & 1) * S2_STAGE;
        if (c + 1 < NCH2) {
            load_chunk(c + 1, smem_base + (uint32_t)((c + 1) & 1) * S2_STAGE);
            asm volatile("cp.async.wait_group 1;" ::: "memory");
        } else {
            asm volatile("cp.async.wait_group 0;" ::: "memory");
        }
        __syncthreads();

        #pragma unroll
        for (int ks = 0; ks < 4; ++ks) {
            const uint32_t gA = ((uint32_t)(ks * 2) + aG) ^ lx;
            const uint32_t bRow = (uint32_t)(ks * 16) * 512u + bRowOff;

            uint32_t ah[16], bh[8];
            #pragma unroll
            for (int ma = 0; ma < 4; ++ma) {
                uint32_t ad = sb + S2_AH + aRowOff + (uint32_t)(ma * 16 * 128) + (gA << 4);
                LDSM_X4(ah[4*ma+0], ah[4*ma+1], ah[4*ma+2], ah[4*ma+3], ad);
            }
            #pragma unroll
            for (int nb = 0; nb < 2; ++nb) {
                uint32_t gB = (bGbase + (uint32_t)(nb * 2)) ^ lx;
                uint32_t bd = sb + S2_BH + bRow + (gB << 4);
                LDSM_X4_T(bh[4*nb+0], bh[4*nb+1], bh[4*nb+2], bh[4*nb+3], bd);
            }
            // hi*hi
            #pragma unroll
            for (int ma = 0; ma < 4; ++ma)
                #pragma unroll
                for (int na = 0; na < 4; ++na)
                    MMA_BF16(acc[ma][na], &ah[4*ma], bh[2*na], bh[2*na+1]);
            // lo*hi
            {
                uint32_t al[16];
                #pragma unroll
                for (int ma = 0; ma < 4; ++ma) {
                    uint32_t ad = sb + S2_AL + aRowOff + (uint32_t)(ma * 16 * 128) + (gA << 4);
                    LDSM_X4(al[4*ma+0], al[4*ma+1], al[4*ma+2], al[4*ma+3], ad);
                }
                #pragma unroll
                for (int ma = 0; ma < 4; ++ma)
                    #pragma unroll
                    for (int na = 0; na < 4; ++na)
                        MMA_BF16(acc[ma][na], &al[4*ma], bh[2*na], bh[2*na+1]);
            }
            // hi*lo
            {
                uint32_t bl[8];
                #pragma unroll
                for (int nb = 0; nb < 2; ++nb) {
                    uint32_t gB = (bGbase + (uint32_t)(nb * 2)) ^ lx;
                    uint32_t bd = sb + S2_BL + bRow + (gB << 4);
                    LDSM_X4_T(bl[4*nb+0], bl[4*nb+1], bl[4*nb+2], bl[4*nb+3], bd);
                }
                #pragma unroll
                for (int ma = 0; ma < 4; ++ma)
                    #pragma unroll
                    for (int na = 0; na < 4; ++na)
                        MMA_BF16(acc[ma][na], &ah[4*ma], bl[2*na], bl[2*na+1]);
            }
        }
        __syncthreads();
    }

    // epilogue: bias + fp32 store into F (rows<128) or Z (rows>=128)
    const int g  = lane >> 2;
    const int tc = lane & 3;
    #pragma unroll
    for (int ma = 0; ma < 4; ++ma) {
        const int r0 = m0 + ma * 16 + g;
        const int r1 = r0 + 8;
        const float bb0 = bias[r0];
        const float bb1 = bias[r1];
        float* p0 = (r0 < L_D)
            ? Fout + ((size_t)b * L_D + r0) * HW
            : Zout + ((size_t)b * (M_CL + 1) + (r0 - L_D)) * HW;
        float* p1 = (r1 < L_D)
            ? Fout + ((size_t)b * L_D + r1) * HW
            : Zout + ((size_t)b * (M_CL + 1) + (r1 - L_D)) * HW;
        p0 += n0 + wn * 32 + tc * 2;
        p1 += n0 + wn * 32 + tc * 2;
        #pragma unroll
        for (int na = 0; na < 4; ++na) {
            float2 v0, v1;
            v0.x = acc[ma][na][0] + bb0;
            v0.y = acc[ma][na][1] + bb0;
            v1.x = acc[ma][na][2] + bb1;
            v1.y = acc[ma][na][3] + bb1;
            *reinterpret_cast<float2*>(p0 + na * 8) = v0;
            *reinterpret_cast<float2*>(p1 + na * 8) = v1;
        }
    }
}

// ---------------------------------------------------------------------------
// Token MLP
// ---------------------------------------------------------------------------
__global__ __launch_bounds__(256)
void token_hidden_kernel(const float* __restrict__ t, const float* __restrict__ w1,
                         const float* __restrict__ b1)
{
    __shared__ float ts[C_SZ];
    const int b = blockIdx.x;
    for (int c = threadIdx.x; c < C_SZ; c += 256) ts[c] = t[(size_t)b * C_SZ + c];
    __syncthreads();
    const int wid = threadIdx.x >> 5, lane = threadIdx.x & 31;
    for (int o = wid; o < HID; o += 8) {
        const float* wr = w1 + (size_t)o * C_SZ;
        float s = 0.f;
        for (int c = lane; c < C_SZ; c += 32) s = fmaf(ts[c], wr[c], s);
        #pragma unroll
        for (int off = 16; off; off >>= 1) s += __shfl_xor_sync(0xFFFFFFFFu, s, off);
        if (lane == 0) g_TKH[(size_t)b * HID + o] = fmaxf(s + b1[o], 0.f);
    }
}

__global__ __launch_bounds__(256)
void token_out_kernel(const float* __restrict__ w2, const float* __restrict__ b2)
{
    __shared__ float hs[HID];
    const int b = blockIdx.x;
    for (int c = threadIdx.x; c < HID; c += 256) hs[c] = g_TKH[(size_t)b * HID + c];
    __syncthreads();
    const int wid = threadIdx.x >> 5, lane = threadIdx.x & 31;
    for (int o = wid; o < G_D; o += 8) {
        const float* wr = w2 + (size_t)o * HID;
        float s = 0.f;
        for (int c = lane; c < HID; c += 32) s = fmaf(hs[c], wr[c], s);
        #pragma unroll
        for (int off = 16; off; off >>= 1) s += __shfl_xor_sync(0xFFFFFFFFu, s, off);
        if (lane == 0) g_TK[(size_t)b * G_D + o] = s + b2[o];
    }
}

// ---------------------------------------------------------------------------
// Sinkhorn (log-space), one block per batch
// ---------------------------------------------------------------------------
__global__ __launch_bounds__(256)
void sinkhorn_kernel(const float* __restrict__ alpha_p)
{
    const int b = blockIdx.x;
    float* Zb = g_Z + (size_t)b * (M_CL + 1) * HW;

    __shared__ float u[M_CL + 1];
    __shared__ float v[HW];

    const int tid = threadIdx.x;
    const float alpha = *alpha_p;
    const float norm = -logf((float)(M_CL + HW));
    const float log_mu_last = logf((float)(HW - M_CL)) + norm;

    for (int j = tid; j < HW; j += 256) {
        Zb[(size_t)M_CL * HW + j] = alpha;
        v[j] = 0.f;
    }
    __syncthreads();

    const int wid = tid >> 5, lane = tid & 31;

    for (int it = 0; it < 3; ++it) {
        for (int i = wid; i < M_CL + 1; i += 8) {
            const float* zr = Zb + (size_t)i * HW;
            float vals[32];
            float mx = -INFINITY;
            #pragma unroll
            for (int k = 0; k < 32; ++k) {
                float z = zr[lane + 32 * k] + v[lane + 32 * k];
                vals[k] = z;
                mx = fmaxf(mx, z);
            }
            #pragma unroll
            for (int off = 16; off; off >>= 1)
                mx = fmaxf(mx, __shfl_xor_sync(0xFFFFFFFFu, mx, off));
            float s = 0.f;
            #pragma unroll
            for (int k = 0; k < 32; ++k) s += __expf(vals[k] - mx);
            #pragma unroll
            for (int off = 16; off; off >>= 1) s += __shfl_xor_sync(0xFFFFFFFFu, s, off);
            if (lane == 0) {
                float lm = (i < M_CL) ? norm : log_mu_last;
                u[i] = lm - (mx + logf(s));
            }
        }
        __syncthreads();

        for (int j = tid; j < HW; j += 256) {
            float mx = Zb[j] + u[0];
            float s = 1.f;
            for (int i = 1; i < M_CL + 1; ++i) {
                float z = Zb[(size_t)i * HW + j] + u[i];
                if (z > mx) { s = s * __expf(mx - z) + 1.f; mx = z; }
                else        { s += __expf(z - mx); }
            }
            v[j] = norm - (mx + logf(s));
        }
        __syncthreads();
    }

    for (int idx = tid; idx < M_CL * HW; idx += 256) {
        int i = idx >> 10, j = idx & (HW - 1);
        Zb[idx] = __expf(Zb[idx] + u[i] + v[j] - norm);
    }
}

// ---------------------------------------------------------------------------
// agg[b][l][m] = sum_n F[b][l][n] * P[b][m][n]
// ---------------------------------------------------------------------------
__global__ __launch_bounds__(256)
void agg_kernel()
{
    const int b = blockIdx.x;
    const float* Fb = g_F + (size_t)b * L_D * HW;
    const float* Pb = g_Z + (size_t)b * (M_CL + 1) * HW;
    float*       Cb = g_AGG + (size_t)b * L_D * M_CL;

    __shared__ float Fs[32][L_D + 4];
    __shared__ float Ps[32][M_CL + 4];

    const int tid = threadIdx.x;
    const int tx = tid & 15, ty = tid >> 4;

    float acc[8][4];
    #pragma unroll
    for (int i = 0; i < 8; ++i)
        #pragma unroll
        for (int j = 0; j < 4; ++j) acc[i][j] = 0.f;

    for (int n0 = 0; n0 < HW; n0 += 32) {
        #pragma unroll
        for (int r = 0; r < 4; ++r) {
            int id = tid + 256 * r;
            int l = id >> 3, kq = (id & 7) << 2;
            float4 fv = *reinterpret_cast<const float4*>(&Fb[(size_t)l * HW + n0 + kq]);
            Fs[kq + 0][l] = fv.x; Fs[kq + 1][l] = fv.y;
            Fs[kq + 2][l] = fv.z; Fs[kq + 3][l] = fv.w;
        }
        #pragma unroll
        for (int r = 0; r < 2; ++r) {
            int id = tid + 256 * r;
            int m = id >> 3, kq = (id & 7) << 2;
            float4 pv = *reinterpret_cast<const float4*>(&Pb[(size_t)m * HW + n0 + kq]);
            Ps[kq + 0][m] = pv.x; Ps[kq + 1][m] = pv.y;
            Ps[kq + 2][m] = pv.z; Ps[kq + 3][m] = pv.w;
        }
        __syncthreads();

        #pragma unroll
        for (int k = 0; k < 32; ++k) {
            float rl[8], rm[4];
            #pragma unroll
            for (int i = 0; i < 8; ++i) rl[i] = Fs[k][ty * 8 + i];
            #pragma unroll
            for (int j = 0; j < 4; ++j) rm[j] = Ps[k][tx * 4 + j];
            #pragma unroll
            for (int i = 0; i < 8; ++i)
                #pragma unroll
                for (int j = 0; j < 4; ++j)
                    acc[i][j] = fmaf(rl[i], rm[j], acc[i][j]);
        }
        __syncthreads();
    }

    #pragma unroll
    for (int i = 0; i < 8; ++i)
        #pragma unroll
        for (int j = 0; j < 4; ++j)
            Cb[(size_t)(ty * 8 + i) * M_CL + tx * 4 + j] = acc[i][j];
}

// ---------------------------------------------------------------------------
// Finalize
// ---------------------------------------------------------------------------
__device__ __forceinline__ float block_sum256(float val, float* red)
{
    const int lane = threadIdx.x & 31, wid = threadIdx.x >> 5;
    #pragma unroll
    for (int off = 16; off; off >>= 1) val += __shfl_xor_sync(0xFFFFFFFFu, val, off);
    if (lane == 0) red[wid] = val;
    __syncthreads();
    float s = red[0] + red[1] + red[2] + red[3] + red[4] + red[5] + red[6] + red[7];
    __syncthreads();
    return s;
}

__global__ __launch_bounds__(256)
void finalize_kernel(float* __restrict__ out)
{
    const int b = blockIdx.x;
    const int tid = threadIdx.x;
    __shared__ float an[L_D * M_CL];
    __shared__ float tkn[G_D];
    __shared__ float cn[M_CL];
    __shared__ float red[8];

    const float* aggb = g_AGG + (size_t)b * L_D * M_CL;

    float tv = g_TK[(size_t)b * G_D + tid];
    float tk_ss = block_sum256(tv * tv, red);
    tkn[tid] = tv / fmaxf(sqrtf(tk_ss), EPSV);

    if (tid < M_CL) {
        float s = 0.f;
        for (int l = 0; l < L_D; ++l) {
            float a = aggb[(size_t)l * M_CL + tid];
            s = fmaf(a, a, s);
        }
        cn[tid] = fmaxf(sqrtf(s), EPSV);
    }
    __syncthreads();

    float gs = tkn[tid] * tkn[tid];
    for (int idx = tid; idx < L_D * M_CL; idx += 256) {
        float a = aggb[idx] / cn[idx & (M_CL - 1)];
        an[idx] = a;
        gs = fmaf(a, a, gs);
    }
    float total = block_sum256(gs, red);
    float scale = 1.f / fmaxf(sqrtf(total), EPSV);

    float* ob = out + (size_t)b * (G_D + L_D * M_CL);
    ob[tid] = tkn[tid] * scale;
    for (int idx = tid; idx < L_D * M_CL; idx += 256)
        ob[G_D + idx] = an[idx] * scale;
}

// ---------------------------------------------------------------------------
// Launch
// ---------------------------------------------------------------------------
extern "C" void kernel_launch(void* const* d_in, const int* in_sizes, int n_in,
                              void* d_out, int out_size)
{
    const float* x      = (const float*)d_in[0];
    const float* t      = (const float*)d_in[1];
    const float* cf_w1  = (const float*)d_in[2];
    const float* cf_b1  = (const float*)d_in[3];
    const float* cf_w2  = (const float*)d_in[4];
    const float* cf_b2  = (const float*)d_in[5];
    const float* sc_w1  = (const float*)d_in[6];
    const float* sc_b1  = (const float*)d_in[7];
    const float* sc_w2  = (const float*)d_in[8];
    const float* sc_b2  = (const float*)d_in[9];
    const float* tk_w1  = (const float*)d_in[10];
    const float* tk_b1  = (const float*)d_in[11];
    const float* tk_w2  = (const float*)d_in[12];
    const float* tk_b2  = (const float*)d_in[13];
    const float* dust   = (const float*)d_in[14];

    float *F, *Z, *B1, *B2;
    __nv_bfloat16 *Xh, *Xl, *Wh, *Wl, *W2h, *W2l, *Hh, *Hl;
    cudaGetSymbolAddress((void**)&F,   g_F);
    cudaGetSymbolAddress((void**)&Z,   g_Z);
    cudaGetSymbolAddress((void**)&B1,  g_B1c);
    cudaGetSymbolAddress((void**)&B2,  g_B2c);
    cudaGetSymbolAddress((void**)&Xh,  g_Xh);
    cudaGetSymbolAddress((void**)&Xl,  g_Xl);
    cudaGetSymbolAddress((void**)&Wh,  g_Wh);
    cudaGetSymbolAddress((void**)&Wl,  g_Wl);
    cudaGetSymbolAddress((void**)&W2h, g_W2h);
    cudaGetSymbolAddress((void**)&W2l, g_W2l);
    cudaGetSymbolAddress((void**)&Hh,  g_Hh);
    cudaGetSymbolAddress((void**)&Hl,  g_Hl);

    cudaFuncSetAttribute(mma_gemm1_kernel,
                         cudaFuncAttributeMaxDynamicSharedMemorySize, GEMM1_SMEM);
    cudaFuncSetAttribute(mma_gemm2_kernel,
                         cudaFuncAttributeMaxDynamicSharedMemorySize, GEMM2_SMEM);

    // conversions
    convert_w_kernel<<<(1024 * C_SZ + 255) / 256, 256>>>(cf_w1, sc_w1, cf_b1, sc_b1);
    convert_w2_kernel<<<(192 * HID + 255) / 256, 256>>>(cf_w2, sc_w2, cf_b2, sc_b2);
    convert_x_kernel<<<dim3(HW / 32, C_SZ / 32, B_SZ), 256>>>(x);

    // GEMM1: hidden layers (cf + sc fused), HMMA
    mma_gemm1_kernel<<<dim3(HW / NT, 1024 / MT, B_SZ), 256, GEMM1_SMEM>>>(
        Wh, Wl, Xh, Xl, B1, Hh, Hl);

    // GEMM2: F and Z from H, HMMA
    mma_gemm2_kernel<<<dim3(HW / NT2, 3, B_SZ), 256, GEMM2_SMEM>>>(
        W2h, W2l, Hh, Hl, B2, F, Z);

    // Token MLP
    token_hidden_kernel<<<B_SZ, 256>>>(t, tk_w1, tk_b1);
    token_out_kernel<<<B_SZ, 256>>>(tk_w2, tk_b2);

    // Sinkhorn + aggregation + normalization
    sinkhorn_kernel<<<B_SZ, 256>>>(dust);
    agg_kernel<<<B_SZ, 256>>>();
    finalize_kernel<<<B_SZ, 256>>>((float*)d_out);
}

// round 6
// speedup vs baseline: 3.3655x; 1.2421x over previous
#include <cuda_runtime.h>
#include <cuda_fp16.h>
#include <cuda_bf16.h>
#include <math.h>
#include <stdint.h>

// ---------------------------------------------------------------------------
// SALAD pipeline. Round 6:
//   gemm1: fp16 HMMA, 2 products (W hi/lo x Xh single)  -> 2/3 tensor work
//   gemm2: fp16 HMMA, 3 products (W2 hi/lo x H hi/lo)   -> no extra error
//   sinkhorn: 1024-thread block, register v, block-reduce u
// Shapes: B=32, C=1536, HW=1024, hidden=512, L=128, M=64 (+dustbin), G=256.
// ---------------------------------------------------------------------------

#define B_SZ 32
#define C_SZ 1536
#define HW   1024
#define HID  512
#define L_D  128
#define M_CL 64
#define G_D  256
#define EPSV 1e-12f

// Scratch (device globals; allocation-free rule)
__device__ __align__(256) __half g_Hh[(size_t)B_SZ * 1024 * HW]; // H hi [b][k][n]
__device__ __align__(256) __half g_Hl[(size_t)B_SZ * 1024 * HW]; // H lo
__device__ __align__(256) float g_F[(size_t)B_SZ * L_D * HW];        // [B][128][HW]
__device__ __align__(256) float g_Z[(size_t)B_SZ * (M_CL + 1) * HW]; // [B][65][HW]
__device__ __align__(256) float g_AGG[(size_t)B_SZ * L_D * M_CL];
__device__ __align__(256) float g_TKH[(size_t)B_SZ * HID];
__device__ __align__(256) float g_TK[(size_t)B_SZ * G_D];

// fp16 operands
__device__ __align__(256) __half g_Xh[(size_t)B_SZ * HW * C_SZ]; // x^T [b][n][c] fp16
__device__ __align__(256) __half g_Wh[(size_t)1024 * C_SZ];      // [cf_w1; sc_w1] hi
__device__ __align__(256) __half g_Wl[(size_t)1024 * C_SZ];      // lo
__device__ __align__(256) __half g_W2h[(size_t)192 * HID];       // [cf_w2; sc_w2] hi
__device__ __align__(256) __half g_W2l[(size_t)192 * HID];       // lo
__device__ __align__(256) float g_B1c[1024];                     // [cf_b1; sc_b1]
__device__ __align__(256) float g_B2c[192];                      // [cf_b2; sc_b2]

// ---------------------------------------------------------------------------
// PTX helpers (family-common only)
// ---------------------------------------------------------------------------
__device__ __forceinline__ uint32_t smem_u32(const void* p) {
    uint32_t a;
    asm("{ .reg .u64 t; cvta.to.shared.u64 t, %1; cvt.u32.u64 %0, t; }"
        : "=r"(a) : "l"(p));
    return a;
}

__device__ __forceinline__ void cp16(uint32_t saddr, const void* gaddr) {
    asm volatile("cp.async.cg.shared.global [%0], [%1], 16;"
                 :: "r"(saddr), "l"(gaddr) : "memory");
}

#define LDSM_X4(r0, r1, r2, r3, addr) \
    asm volatile("ldmatrix.sync.aligned.m8n8.x4.shared.b16 {%0,%1,%2,%3}, [%4];" \
                 : "=r"(r0), "=r"(r1), "=r"(r2), "=r"(r3) : "r"(addr))

#define LDSM_X4_T(r0, r1, r2, r3, addr) \
    asm volatile("ldmatrix.sync.aligned.m8n8.x4.trans.shared.b16 {%0,%1,%2,%3}, [%4];" \
                 : "=r"(r0), "=r"(r1), "=r"(r2), "=r"(r3) : "r"(addr))

#define MMA_F16(d, a, b0, b1) \
    asm volatile("mma.sync.aligned.m16n8k16.row.col.f32.f16.f16.f32 " \
                 "{%0,%1,%2,%3}, {%4,%5,%6,%7}, {%8,%9}, {%0,%1,%2,%3};" \
                 : "+f"((d)[0]), "+f"((d)[1]), "+f"((d)[2]), "+f"((d)[3]) \
                 : "r"((a)[0]), "r"((a)[1]), "r"((a)[2]), "r"((a)[3]), \
                   "r"(b0), "r"(b1))

// ---------------------------------------------------------------------------
// Conversions: fp32 -> fp16 (hi/lo split where needed)
// ---------------------------------------------------------------------------
__device__ __forceinline__ void split_h(float v, __half& hi, __half& lo) {
    hi = __float2half_rn(v);
    lo = __float2half_rn(v - __half2float(hi));
}

__global__ __launch_bounds__(256)
void convert_w_kernel(const float* __restrict__ cf_w1, const float* __restrict__ sc_w1,
                      const float* __restrict__ cf_b1, const float* __restrict__ sc_b1)
{
    size_t idx = (size_t)blockIdx.x * 256 + threadIdx.x;
    const size_t total = (size_t)1024 * C_SZ;
    if (idx < total) {
        size_t row = idx / C_SZ;
        float v = (row < HID) ? cf_w1[idx] : sc_w1[idx - (size_t)HID * C_SZ];
        __half hi, lo; split_h(v, hi, lo);
        g_Wh[idx] = hi; g_Wl[idx] = lo;
    }
    if (idx < 1024)
        g_B1c[idx] = (idx < HID) ? cf_b1[idx] : sc_b1[idx - HID];
}

__global__ __launch_bounds__(256)
void convert_w2_kernel(const float* __restrict__ cf_w2, const float* __restrict__ sc_w2,
                       const float* __restrict__ cf_b2, const float* __restrict__ sc_b2)
{
    size_t idx = (size_t)blockIdx.x * 256 + threadIdx.x;
    const size_t total = (size_t)192 * HID;
    if (idx < total) {
        size_t row = idx / HID;
        float v = (row < L_D) ? cf_w2[idx] : sc_w2[idx - (size_t)L_D * HID];
        __half hi, lo; split_h(v, hi, lo);
        g_W2h[idx] = hi; g_W2l[idx] = lo;
    }
    if (idx < 192)
        g_B2c[idx] = (idx < L_D) ? cf_b2[idx] : sc_b2[idx - L_D];
}

// Transpose x [b][c][n] -> x^T [b][n][c] fp16. 32x32 tiles.
__global__ __launch_bounds__(256)
void convert_x_kernel(const float* __restrict__ x)
{
    __shared__ float t[32][33];
    const int n0 = blockIdx.x * 32, c0 = blockIdx.y * 32, b = blockIdx.z;
    const int tx = threadIdx.x & 31, ty = threadIdx.x >> 5; // 32x8

    const float* xb = x + (size_t)b * C_SZ * HW;
    #pragma unroll
    for (int i = 0; i < 4; ++i) {
        int c = c0 + ty + 8 * i;
        t[ty + 8 * i][tx] = xb[(size_t)c * HW + n0 + tx];
    }
    __syncthreads();
    #pragma unroll
    for (int i = 0; i < 4; ++i) {
        int n = n0 + ty + 8 * i;
        size_t o = ((size_t)b * HW + n) * C_SZ + c0 + tx;
        g_Xh[o] = __float2half_rn(t[tx][ty + 8 * i]);
    }
}

// ---------------------------------------------------------------------------
// GEMM1 (fp16 HMMA, 2 products):  H[b] = relu(W @ X[b]^T + b1), H fp16 hi/lo
//   CTA tile 128(m) x 256(n), K-chunk 64, double buffer cp.async.
//   8 warps: 2(m) x 4(n), warp tile 64x64. Products: Wh*Xh + Wl*Xh.
// ---------------------------------------------------------------------------
#define MT 128
#define NT 256
#define KC 64
#define NCHUNK (C_SZ / KC)            // 24
#define OFF_AH 0
#define OFF_AL (16 * 1024)
#define OFF_BH (32 * 1024)
#define STAGE_BYTES (64 * 1024)
#define GEMM1_SMEM (2 * STAGE_BYTES)  // 128 KB

__global__ __launch_bounds__(256, 1)
void mma_gemm1_kernel(const __half* __restrict__ Wh, const __half* __restrict__ Wl,
                      const __half* __restrict__ Xh,
                      const float* __restrict__ bias,
                      __half* __restrict__ Hh, __half* __restrict__ Hl)
{
    extern __shared__ char dsmem[];
    const uint32_t smem_base = smem_u32(dsmem);

    const int tid = threadIdx.x;
    const int b  = blockIdx.z;
    const int n0 = blockIdx.x * NT;
    const int m0 = blockIdx.y * MT;

    const __half* Whb = Wh + (size_t)m0 * C_SZ;
    const __half* Wlb = Wl + (size_t)m0 * C_SZ;
    const __half* Xhb = Xh + ((size_t)b * HW + n0) * C_SZ;

    const int lane = tid & 31, warp = tid >> 5;
    const int wm = warp >> 2, wn = warp & 3;   // warp tile: rows wm*64, cols wn*64

    const uint32_t lx = (uint32_t)(lane & 7);
    const uint32_t aG   = (uint32_t)(lane >> 4);
    const uint32_t aRowOff = (uint32_t)(wm * 64 + (lane & 15)) * 128u;
    const uint32_t bG   = (uint32_t)((lane >> 3) & 1);
    const uint32_t bRowBase = (uint32_t)(wn * 64 + ((lane >> 4) << 3) + (lane & 7)) * 128u;

    float acc[4][8][4];
    #pragma unroll
    for (int i = 0; i < 4; ++i)
        #pragma unroll
        for (int j = 0; j < 8; ++j)
            #pragma unroll
            for (int q = 0; q < 4; ++q) acc[i][j][q] = 0.f;

    auto load_chunk = [&](int c, uint32_t sb) {
        const size_t kk = (size_t)c * KC;
        // A hi/lo: 128 rows x 8 groups = 1024 entries each
        #pragma unroll
        for (int i = 0; i < 4; ++i) {
            int idx = tid + 256 * i;
            int r = idx >> 3, g = idx & 7;
            uint32_t so = (uint32_t)r * 128u + (uint32_t)((g ^ (r & 7)) << 4);
            cp16(sb + OFF_AH + so, (const char*)(Whb + (size_t)r * C_SZ + kk) + g * 16);
            cp16(sb + OFF_AL + so, (const char*)(Wlb + (size_t)r * C_SZ + kk) + g * 16);
        }
        // B hi: 256 rows x 8 groups = 2048 entries
        #pragma unroll
        for (int i = 0; i < 8; ++i) {
            int idx = tid + 256 * i;
            int r = idx >> 3, g = idx & 7;
            uint32_t so = (uint32_t)r * 128u + (uint32_t)((g ^ (r & 7)) << 4);
            cp16(sb + OFF_BH + so, (const char*)(Xhb + (size_t)r * C_SZ + kk) + g * 16);
        }
        asm volatile("cp.async.commit_group;" ::: "memory");
    };

    load_chunk(0, smem_base);

    for (int c = 0; c < NCHUNK; ++c) {
        const uint32_t sb = smem_base + (uint32_t)(c & 1) * STAGE_BYTES;
        if (c + 1 < NCHUNK) {
            load_chunk(c + 1, smem_base + (uint32_t)((c + 1) & 1) * STAGE_BYTES);
            asm volatile("cp.async.wait_group 1;" ::: "memory");
        } else {
            asm volatile("cp.async.wait_group 0;" ::: "memory");
        }
        __syncthreads();

        #pragma unroll
        for (int ks = 0; ks < 4; ++ks) {
            const uint32_t gA = ((uint32_t)(ks * 2) + aG) ^ lx;
            const uint32_t gB = ((uint32_t)(ks * 2) + bG) ^ lx;

            uint32_t ah[16], bh[16];
            #pragma unroll
            for (int ma = 0; ma < 4; ++ma) {
                uint32_t ad = sb + OFF_AH + aRowOff + (uint32_t)(ma * 16 * 128) + (gA << 4);
                LDSM_X4(ah[4*ma+0], ah[4*ma+1], ah[4*ma+2], ah[4*ma+3], ad);
            }
            #pragma unroll
            for (int nb = 0; nb < 4; ++nb) {
                uint32_t bd = sb + OFF_BH + bRowBase + (uint32_t)(nb * 16 * 128) + (gB << 4);
                LDSM_X4(bh[4*nb+0], bh[4*nb+1], bh[4*nb+2], bh[4*nb+3], bd);
            }
            // hi * hi
            #pragma unroll
            for (int ma = 0; ma < 4; ++ma)
                #pragma unroll
                for (int na = 0; na < 8; ++na)
                    MMA_F16(acc[ma][na], &ah[4*ma], bh[2*na], bh[2*na+1]);
            // lo * hi
            {
                uint32_t al[16];
                #pragma unroll
                for (int ma = 0; ma < 4; ++ma) {
                    uint32_t ad = sb + OFF_AL + aRowOff + (uint32_t)(ma * 16 * 128) + (gA << 4);
                    LDSM_X4(al[4*ma+0], al[4*ma+1], al[4*ma+2], al[4*ma+3], ad);
                }
                #pragma unroll
                for (int ma = 0; ma < 4; ++ma)
                    #pragma unroll
                    for (int na = 0; na < 8; ++na)
                        MMA_F16(acc[ma][na], &al[4*ma], bh[2*na], bh[2*na+1]);
            }
        }
        __syncthreads();
    }

    // epilogue: bias + relu -> fp16 hi/lo stores, layout [b][k=row][n]
    const int g  = lane >> 2;
    const int tc = lane & 3;
    #pragma unroll
    for (int ma = 0; ma < 4; ++ma) {
        const int r0 = m0 + wm * 64 + ma * 16 + g;
        const int r1 = r0 + 8;
        const float bb0 = bias[r0];
        const float bb1 = bias[r1];
        const size_t base0 = ((size_t)b * 1024 + r0) * HW + n0 + wn * 64 + tc * 2;
        const size_t base1 = ((size_t)b * 1024 + r1) * HW + n0 + wn * 64 + tc * 2;
        #pragma unroll
        for (int na = 0; na < 8; ++na) {
            float v00 = fmaxf(acc[ma][na][0] + bb0, 0.f);
            float v01 = fmaxf(acc[ma][na][1] + bb0, 0.f);
            float v10 = fmaxf(acc[ma][na][2] + bb1, 0.f);
            float v11 = fmaxf(acc[ma][na][3] + bb1, 0.f);
            __half h00, l00, h01, l01, h10, l10, h11, l11;
            split_h(v00, h00, l00); split_h(v01, h01, l01);
            split_h(v10, h10, l10); split_h(v11, h11, l11);
            *reinterpret_cast<__half2*>(Hh + base0 + na * 8) = __half2(h00, h01);
            *reinterpret_cast<__half2*>(Hl + base0 + na * 8) = __half2(l00, l01);
            *reinterpret_cast<__half2*>(Hh + base1 + na * 8) = __half2(h10, h11);
            *reinterpret_cast<__half2*>(Hl + base1 + na * 8) = __half2(l10, l11);
        }
    }
}

// ---------------------------------------------------------------------------
// GEMM2 (fp16 HMMA, 3 products): [F; Z] = W2 @ H + b2
//   A = W2 [192][512] fp16 hi/lo K-major. B = H [b][k][n] fp16 hi/lo,
//   fed via ldmatrix.x4.trans. CTA tile 64(m) x 256(n), 8 warps along n.
// ---------------------------------------------------------------------------
#define NT2 256
#define NCH2 (HID / KC)               // 8
#define S2_AH 0
#define S2_AL (8 * 1024)
#define S2_BH (16 * 1024)
#define S2_BL (48 * 1024)
#define S2_STAGE (80 * 1024)
#define GEMM2_SMEM (2 * S2_STAGE)     // 160 KB

__global__ __launch_bounds__(256, 1)
void mma_gemm2_kernel(const __half* __restrict__ W2h, const __half* __restrict__ W2l,
                      const __half* __restrict__ Hh, const __half* __restrict__ Hl,
                      const float* __restrict__ bias,
                      float* __restrict__ Fout, float* __restrict__ Zout)
{
    extern __shared__ char dsmem[];
    const uint32_t smem_base = smem_u32(dsmem);

    const int tid = threadIdx.x;
    const int b  = blockIdx.z;
    const int n0 = blockIdx.x * NT2;
    const int m0 = blockIdx.y * 64;                // 0, 64, 128
    const int koff = (m0 == 128) ? 512 : 0;        // sc hidden rows

    const __half* Ahg = W2h + (size_t)m0 * HID;
    const __half* Alg = W2l + (size_t)m0 * HID;
    const __half* Bhg = Hh + ((size_t)b * 1024 + koff) * HW + n0;
    const __half* Blg = Hl + ((size_t)b * 1024 + koff) * HW + n0;

    const int lane = tid & 31, wn = tid >> 5;      // 8 warps along n

    float acc[4][4][4];
    #pragma unroll
    for (int i = 0; i < 4; ++i)
        #pragma unroll
        for (int j = 0; j < 4; ++j)
            #pragma unroll
            for (int q = 0; q < 4; ++q) acc[i][j][q] = 0.f;

    auto load_chunk = [&](int c, uint32_t sb) {
        const int kk = c * KC;
        #pragma unroll
        for (int i = 0; i < 2; ++i) {
            int idx = tid + 256 * i;
            int r = idx >> 3, g = idx & 7;
            uint32_t so = (uint32_t)r * 128u + (uint32_t)((g ^ (r & 7)) << 4);
            cp16(sb + S2_AH + so, (const char*)(Ahg + (size_t)r * HID + kk) + g * 16);
            cp16(sb + S2_AL + so, (const char*)(Alg + (size_t)r * HID + kk) + g * 16);
        }
        #pragma unroll
        for (int i = 0; i < 8; ++i) {
            int idx = tid + 256 * i;
            int r = idx >> 5, g = idx & 31;
            uint32_t so = (uint32_t)r * 512u + (uint32_t)((g ^ (r & 7)) << 4);
            cp16(sb + S2_BH + so, (const char*)(Bhg + (size_t)(kk + r) * HW) + g * 16);
            cp16(sb + S2_BL + so, (const char*)(Blg + (size_t)(kk + r) * HW) + g * 16);
        }
        asm volatile("cp.async.commit_group;" ::: "memory");
    };

    load_chunk(0, smem_base);

    const uint32_t lx = (uint32_t)(lane & 7);
    const uint32_t aG = (uint32_t)(lane >> 4);
    const uint32_t aRowOff = (uint32_t)(lane & 15) * 128u;
    const uint32_t bRowOff = (uint32_t)(lane & 15) * 512u;
    const uint32_t bGbase = (uint32_t)(wn * 4) + (uint32_t)(lane >> 4);

    for (int c = 0; c < NCH2; ++c) {
        const uint32_t sb = smem_base + (uint32_t)(c & 1) * S2_STAGE;
        if (c + 1 < NCH2) {
            load_chunk(c + 1, smem_base + (uint32_t)((c + 1) & 1) * S2_STAGE);
            asm volatile("cp.async.wait_group 1;" ::: "memory");
        } else {
            asm volatile("cp.async.wait_group 0;" ::: "memory");
        }
        __syncthreads();

        #pragma unroll
        for (int ks = 0; ks < 4; ++ks) {
            const uint32_t gA = ((uint32_t)(ks * 2) + aG) ^ lx;
            const uint32_t bRow = (uint32_t)(ks * 16) * 512u + bRowOff;

            uint32_t ah[16], bh[8];
            #pragma unroll
            for (int ma = 0; ma < 4; ++ma) {
                uint32_t ad = sb + S2_AH + aRowOff + (uint32_t)(ma * 16 * 128) + (gA << 4);
                LDSM_X4(ah[4*ma+0], ah[4*ma+1], ah[4*ma+2], ah[4*ma+3], ad);
            }
            #pragma unroll
            for (int nb = 0; nb < 2; ++nb) {
                uint32_t gB = (bGbase + (uint32_t)(nb * 2)) ^ lx;
                uint32_t bd = sb + S2_BH + bRow + (gB << 4);
                LDSM_X4_T(bh[4*nb+0], bh[4*nb+1], bh[4*nb+2], bh[4*nb+3], bd);
            }
            // hi*hi
            #pragma unroll
            for (int ma = 0; ma < 4; ++ma)
                #pragma unroll
                for (int na = 0; na < 4; ++na)
                    MMA_F16(acc[ma][na], &ah[4*ma], bh[2*na], bh[2*na+1]);
            // lo*hi
            {
                uint32_t al[16];
                #pragma unroll
                for (int ma = 0; ma < 4; ++ma) {
                    uint32_t ad = sb + S2_AL + aRowOff + (uint32_t)(ma * 16 * 128) + (gA << 4);
                    LDSM_X4(al[4*ma+0], al[4*ma+1], al[4*ma+2], al[4*ma+3], ad);
                }
                #pragma unroll
                for (int ma = 0; ma < 4; ++ma)
                    #pragma unroll
                    for (int na = 0; na < 4; ++na)
                        MMA_F16(acc[ma][na], &al[4*ma], bh[2*na], bh[2*na+1]);
            }
            // hi*lo
            {
                uint32_t bl[8];
                #pragma unroll
                for (int nb = 0; nb < 2; ++nb) {
                    uint32_t gB = (bGbase + (uint32_t)(nb * 2)) ^ lx;
                    uint32_t bd = sb + S2_BL + bRow + (gB << 4);
                    LDSM_X4_T(bl[4*nb+0], bl[4*nb+1], bl[4*nb+2], bl[4*nb+3], bd);
                }
                #pragma unroll
                for (int ma = 0; ma < 4; ++ma)
                    #pragma unroll
                    for (int na = 0; na < 4; ++na)
                        MMA_F16(acc[ma][na], &ah[4*ma], bl[2*na], bl[2*na+1]);
            }
        }
        __syncthreads();
    }

    // epilogue: bias + fp32 store into F (rows<128) or Z (rows>=128)
    const int g  = lane >> 2;
    const int tc = lane & 3;
    #pragma unroll
    for (int ma = 0; ma < 4; ++ma) {
        const int r0 = m0 + ma * 16 + g;
        const int r1 = r0 + 8;
        const float bb0 = bias[r0];
        const float bb1 = bias[r1];
        float* p0 = (r0 < L_D)
            ? Fout + ((size_t)b * L_D + r0) * HW
            : Zout + ((size_t)b * (M_CL + 1) + (r0 - L_D)) * HW;
        float* p1 = (r1 < L_D)
            ? Fout + ((size_t)b * L_D + r1) * HW
            : Zout + ((size_t)b * (M_CL + 1) + (r1 - L_D)) * HW;
        p0 += n0 + wn * 32 + tc * 2;
        p1 += n0 + wn * 32 + tc * 2;
        #pragma unroll
        for (int na = 0; na < 4; ++na) {
            float2 v0, v1;
            v0.x = acc[ma][na][0] + bb0;
            v0.y = acc[ma][na][1] + bb0;
            v1.x = acc[ma][na][2] + bb1;
            v1.y = acc[ma][na][3] + bb1;
            *reinterpret_cast<float2*>(p0 + na * 8) = v0;
            *reinterpret_cast<float2*>(p1 + na * 8) = v1;
        }
    }
}

// ---------------------------------------------------------------------------
// Token MLP
// ---------------------------------------------------------------------------
__global__ __launch_bounds__(256)
void token_hidden_kernel(const float* __restrict__ t, const float* __restrict__ w1,
                         const float* __restrict__ b1)
{
    __shared__ float ts[C_SZ];
    const int b = blockIdx.x;
    for (int c = threadIdx.x; c < C_SZ; c += 256) ts[c] = t[(size_t)b * C_SZ + c];
    __syncthreads();
    const int wid = threadIdx.x >> 5, lane = threadIdx.x & 31;
    for (int o = wid; o < HID; o += 8) {
        const float* wr = w1 + (size_t)o * C_SZ;
        float s = 0.f;
        for (int c = lane; c < C_SZ; c += 32) s = fmaf(ts[c], wr[c], s);
        #pragma unroll
        for (int off = 16; off; off >>= 1) s += __shfl_xor_sync(0xFFFFFFFFu, s, off);
        if (lane == 0) g_TKH[(size_t)b * HID + o] = fmaxf(s + b1[o], 0.f);
    }
}

__global__ __launch_bounds__(256)
void token_out_kernel(const float* __restrict__ w2, const float* __restrict__ b2)
{
    __shared__ float hs[HID];
    const int b = blockIdx.x;
    for (int c = threadIdx.x; c < HID; c += 256) hs[c] = g_TKH[(size_t)b * HID + c];
    __syncthreads();
    const int wid = threadIdx.x >> 5, lane = threadIdx.x & 31;
    for (int o = wid; o < G_D; o += 8) {
        const float* wr = w2 + (size_t)o * HID;
        float s = 0.f;
        for (int c = lane; c < HID; c += 32) s = fmaf(hs[c], wr[c], s);
        #pragma unroll
        for (int off = 16; off; off >>= 1) s += __shfl_xor_sync(0xFFFFFFFFu, s, off);
        if (lane == 0) g_TK[(size_t)b * G_D + o] = s + b2[o];
    }
}

// ---------------------------------------------------------------------------
// Sinkhorn (log-space), 1024 threads/block, one block per batch.
// Thread j owns column j. v lives in a register; u in smem; Z stays L2-hot.
// Score magnitudes are O(1) so plain (max-free) logsumexp is safe in fp32.
// ---------------------------------------------------------------------------
__global__ __launch_bounds__(1024)
void sinkhorn_kernel(const float* __restrict__ alpha_p)
{
    const int b = blockIdx.x;
    float* Zb = g_Z + (size_t)b * (M_CL + 1) * HW;

    __shared__ float u[M_CL + 1];
    __shared__ float wsum[M_CL + 1][33];

    const int j = threadIdx.x;
    const int lane = j & 31, warp = j >> 5;
    const float alpha = *alpha_p;
    const float norm = -logf((float)(M_CL + HW));              // -log(1088)
    const float log_mu_last = logf((float)(HW - M_CL)) + norm; // log(960)+norm

    float v = 0.f;

    for (int it = 0; it < 3; ++it) {
        // u-phase: per-row block LSE (sum of exp; values are O(1))
        #pragma unroll 4
        for (int i = 0; i <= M_CL; ++i) {
            float z = ((i < M_CL) ? Zb[(size_t)i * HW + j] : alpha) + v;
            float e = __expf(z);
            #pragma unroll
            for (int off = 16; off; off >>= 1) e += __shfl_xor_sync(0xFFFFFFFFu, e, off);
            if (lane == 0) wsum[i][warp] = e;
        }
        __syncthreads();
        if (j <= M_CL) {
            float s = 0.f;
            #pragma unroll
            for (int w = 0; w < 32; ++w) s += wsum[j][w];
            u[j] = ((j < M_CL) ? norm : log_mu_last) - logf(s);
        }
        __syncthreads();

        // v-phase: column LSE, fully per-thread
        float s = 0.f;
        #pragma unroll 8
        for (int i = 0; i < M_CL; ++i)
            s += __expf(Zb[(size_t)i * HW + j] + u[i]);
        s += __expf(alpha + u[M_CL]);
        v = norm - logf(s);
    }

    // P = exp(Z + u + v - norm), rows 0..63 in place
    #pragma unroll 8
    for (int i = 0; i < M_CL; ++i)
        Zb[(size_t)i * HW + j] = __expf(Zb[(size_t)i * HW + j] + u[i] + v - norm);
}

// ---------------------------------------------------------------------------
// agg[b][l][m] = sum_n F[b][l][n] * P[b][m][n]
// ---------------------------------------------------------------------------
__global__ __launch_bounds__(256)
void agg_kernel()
{
    const int b = blockIdx.x;
    const float* Fb = g_F + (size_t)b * L_D * HW;
    const float* Pb = g_Z + (size_t)b * (M_CL + 1) * HW;
    float*       Cb = g_AGG + (size_t)b * L_D * M_CL;

    __shared__ float Fs[32][L_D + 4];
    __shared__ float Ps[32][M_CL + 4];

    const int tid = threadIdx.x;
    const int tx = tid & 15, ty = tid >> 4;

    float acc[8][4];
    #pragma unroll
    for (int i = 0; i < 8; ++i)
        #pragma unroll
        for (int j = 0; j < 4; ++j) acc[i][j] = 0.f;

    for (int n0 = 0; n0 < HW; n0 += 32) {
        #pragma unroll
        for (int r = 0; r < 4; ++r) {
            int id = tid + 256 * r;
            int l = id >> 3, kq = (id & 7) << 2;
            float4 fv = *reinterpret_cast<const float4*>(&Fb[(size_t)l * HW + n0 + kq]);
            Fs[kq + 0][l] = fv.x; Fs[kq + 1][l] = fv.y;
            Fs[kq + 2][l] = fv.z; Fs[kq + 3][l] = fv.w;
        }
        #pragma unroll
        for (int r = 0; r < 2; ++r) {
            int id = tid + 256 * r;
            int m = id >> 3, kq = (id & 7) << 2;
            float4 pv = *reinterpret_cast<const float4*>(&Pb[(size_t)m * HW + n0 + kq]);
            Ps[kq + 0][m] = pv.x; Ps[kq + 1][m] = pv.y;
            Ps[kq + 2][m] = pv.z; Ps[kq + 3][m] = pv.w;
        }
        __syncthreads();

        #pragma unroll
        for (int k = 0; k < 32; ++k) {
            float rl[8], rm[4];
            #pragma unroll
            for (int i = 0; i < 8; ++i) rl[i] = Fs[k][ty * 8 + i];
            #pragma unroll
            for (int j = 0; j < 4; ++j) rm[j] = Ps[k][tx * 4 + j];
            #pragma unroll
            for (int i = 0; i < 8; ++i)
                #pragma unroll
                for (int j = 0; j < 4; ++j)
                    acc[i][j] = fmaf(rl[i], rm[j], acc[i][j]);
        }
        __syncthreads();
    }

    #pragma unroll
    for (int i = 0; i < 8; ++i)
        #pragma unroll
        for (int j = 0; j < 4; ++j)
            Cb[(size_t)(ty * 8 + i) * M_CL + tx * 4 + j] = acc[i][j];
}

// ---------------------------------------------------------------------------
// Finalize
// ---------------------------------------------------------------------------
__device__ __forceinline__ float block_sum256(float val, float* red)
{
    const int lane = threadIdx.x & 31, wid = threadIdx.x >> 5;
    #pragma unroll
    for (int off = 16; off; off >>= 1) val += __shfl_xor_sync(0xFFFFFFFFu, val, off);
    if (lane == 0) red[wid] = val;
    __syncthreads();
    float s = red[0] + red[1] + red[2] + red[3] + red[4] + red[5] + red[6] + red[7];
    __syncthreads();
    return s;
}

__global__ __launch_bounds__(256)
void finalize_kernel(float* __restrict__ out)
{
    const int b = blockIdx.x;
    const int tid = threadIdx.x;
    __shared__ float an[L_D * M_CL];
    __shared__ float tkn[G_D];
    __shared__ float cn[M_CL];
    __shared__ float red[8];

    const float* aggb = g_AGG + (size_t)b * L_D * M_CL;

    float tv = g_TK[(size_t)b * G_D + tid];
    float tk_ss = block_sum256(tv * tv, red);
    tkn[tid] = tv / fmaxf(sqrtf(tk_ss), EPSV);

    if (tid < M_CL) {
        float s = 0.f;
        for (int l = 0; l < L_D; ++l) {
            float a = aggb[(size_t)l * M_CL + tid];
            s = fmaf(a, a, s);
        }
        cn[tid] = fmaxf(sqrtf(s), EPSV);
    }
    __syncthreads();

    float gs = tkn[tid] * tkn[tid];
    for (int idx = tid; idx < L_D * M_CL; idx += 256) {
        float a = aggb[idx] / cn[idx & (M_CL - 1)];
        an[idx] = a;
        gs = fmaf(a, a, gs);
    }
    float total = block_sum256(gs, red);
    float scale = 1.f / fmaxf(sqrtf(total), EPSV);

    float* ob = out + (size_t)b * (G_D + L_D * M_CL);
    ob[tid] = tkn[tid] * scale;
    for (int idx = tid; idx < L_D * M_CL; idx += 256)
        ob[G_D + idx] = an[idx] * scale;
}

// ---------------------------------------------------------------------------
// Launch
// ---------------------------------------------------------------------------
extern "C" void kernel_launch(void* const* d_in, const int* in_sizes, int n_in,
                              void* d_out, int out_size)
{
    const float* x      = (const float*)d_in[0];
    const float* t      = (const float*)d_in[1];
    const float* cf_w1  = (const float*)d_in[2];
    const float* cf_b1  = (const float*)d_in[3];
    const float* cf_w2  = (const float*)d_in[4];
    const float* cf_b2  = (const float*)d_in[5];
    const float* sc_w1  = (const float*)d_in[6];
    const float* sc_b1  = (const float*)d_in[7];
    const float* sc_w2  = (const float*)d_in[8];
    const float* sc_b2  = (const float*)d_in[9];
    const float* tk_w1  = (const float*)d_in[10];
    const float* tk_b1  = (const float*)d_in[11];
    const float* tk_w2  = (const float*)d_in[12];
    const float* tk_b2  = (const float*)d_in[13];
    const float* dust   = (const float*)d_in[14];

    float *F, *Z, *B1, *B2;
    __half *Xh, *Wh, *Wl, *W2h, *W2l, *Hh, *Hl;
    cudaGetSymbolAddress((void**)&F,   g_F);
    cudaGetSymbolAddress((void**)&Z,   g_Z);
    cudaGetSymbolAddress((void**)&B1,  g_B1c);
    cudaGetSymbolAddress((void**)&B2,  g_B2c);
    cudaGetSymbolAddress((void**)&Xh,  g_Xh);
    cudaGetSymbolAddress((void**)&Wh,  g_Wh);
    cudaGetSymbolAddress((void**)&Wl,  g_Wl);
    cudaGetSymbolAddress((void**)&W2h, g_W2h);
    cudaGetSymbolAddress((void**)&W2l, g_W2l);
    cudaGetSymbolAddress((void**)&Hh,  g_Hh);
    cudaGetSymbolAddress((void**)&Hl,  g_Hl);

    cudaFuncSetAttribute(mma_gemm1_kernel,
                         cudaFuncAttributeMaxDynamicSharedMemorySize, GEMM1_SMEM);
    cudaFuncSetAttribute(mma_gemm2_kernel,
                         cudaFuncAttributeMaxDynamicSharedMemorySize, GEMM2_SMEM);

    // conversions
    convert_w_kernel<<<(1024 * C_SZ + 255) / 256, 256>>>(cf_w1, sc_w1, cf_b1, sc_b1);
    convert_w2_kernel<<<(192 * HID + 255) / 256, 256>>>(cf_w2, sc_w2, cf_b2, sc_b2);
    convert_x_kernel<<<dim3(HW / 32, C_SZ / 32, B_SZ), 256>>>(x);

    // GEMM1: hidden layers (cf + sc fused), fp16 HMMA, 2 products
    mma_gemm1_kernel<<<dim3(HW / NT, 1024 / MT, B_SZ), 256, GEMM1_SMEM>>>(
        Wh, Wl, Xh, B1, Hh, Hl);

    // GEMM2: F and Z from H, fp16 HMMA, 3 products
    mma_gemm2_kernel<<<dim3(HW / NT2, 3, B_SZ), 256, GEMM2_SMEM>>>(
        W2h, W2l, Hh, Hl, B2, F, Z);

    // Token MLP
    token_hidden_kernel<<<B_SZ, 256>>>(t, tk_w1, tk_b1);
    token_out_kernel<<<B_SZ, 256>>>(tk_w2, tk_b2);

    // Sinkhorn + aggregation + normalization
    sinkhorn_kernel<<<B_SZ, 1024>>>(dust);
    agg_kernel<<<B_SZ, 256>>>();
    finalize_kernel<<<B_SZ, 256>>>((float*)d_out);
}

// round 7
// speedup vs baseline: 4.9350x; 1.4664x over previous
#include <cuda_runtime.h>
#include <cuda_fp16.h>
#include <math.h>
#include <stdint.h>

// ---------------------------------------------------------------------------
// SALAD pipeline. Round 7: single-product fp16 HMMA for both GEMM levels
// (empirically each fp16-quantized operand adds ~1e-5 rel_err; budget 1e-3).
// gemm1 reads x in native [c][n] layout via ldmatrix.trans (no transpose).
// Shapes: B=32, C=1536, HW=1024, hidden=512, L=128, M=64 (+dustbin), G=256.
// ---------------------------------------------------------------------------

#define B_SZ 32
#define C_SZ 1536
#define HW   1024
#define HID  512
#define L_D  128
#define M_CL 64
#define G_D  256
#define EPSV 1e-12f

// Scratch (device globals; allocation-free rule)
__device__ __align__(256) __half g_H[(size_t)B_SZ * 1024 * HW];      // H [b][k][n] fp16
__device__ __align__(256) float g_F[(size_t)B_SZ * L_D * HW];        // [B][128][HW]
__device__ __align__(256) float g_Z[(size_t)B_SZ * (M_CL + 1) * HW]; // [B][65][HW]
__device__ __align__(256) float g_AGG[(size_t)B_SZ * L_D * M_CL];
__device__ __align__(256) float g_TKH[(size_t)B_SZ * HID];
__device__ __align__(256) float g_TK[(size_t)B_SZ * G_D];

// fp16 operands
__device__ __align__(256) __half g_X[(size_t)B_SZ * C_SZ * HW]; // x [b][c][n] fp16
__device__ __align__(256) __half g_W1[(size_t)1024 * C_SZ];     // [cf_w1; sc_w1]
__device__ __align__(256) __half g_W2[(size_t)192 * HID];       // [cf_w2; sc_w2]
__device__ __align__(256) float g_B1c[1024];                    // [cf_b1; sc_b1]
__device__ __align__(256) float g_B2c[192];                     // [cf_b2; sc_b2]

// ---------------------------------------------------------------------------
// PTX helpers (family-common only)
// ---------------------------------------------------------------------------
__device__ __forceinline__ uint32_t smem_u32(const void* p) {
    uint32_t a;
    asm("{ .reg .u64 t; cvta.to.shared.u64 t, %1; cvt.u32.u64 %0, t; }"
        : "=r"(a) : "l"(p));
    return a;
}

__device__ __forceinline__ void cp16(uint32_t saddr, const void* gaddr) {
    asm volatile("cp.async.cg.shared.global [%0], [%1], 16;"
                 :: "r"(saddr), "l"(gaddr) : "memory");
}

#define LDSM_X4(r0, r1, r2, r3, addr) \
    asm volatile("ldmatrix.sync.aligned.m8n8.x4.shared.b16 {%0,%1,%2,%3}, [%4];" \
                 : "=r"(r0), "=r"(r1), "=r"(r2), "=r"(r3) : "r"(addr))

#define LDSM_X4_T(r0, r1, r2, r3, addr) \
    asm volatile("ldmatrix.sync.aligned.m8n8.x4.trans.shared.b16 {%0,%1,%2,%3}, [%4];" \
                 : "=r"(r0), "=r"(r1), "=r"(r2), "=r"(r3) : "r"(addr))

#define MMA_F16(d, a, b0, b1) \
    asm volatile("mma.sync.aligned.m16n8k16.row.col.f32.f16.f16.f32 " \
                 "{%0,%1,%2,%3}, {%4,%5,%6,%7}, {%8,%9}, {%0,%1,%2,%3};" \
                 : "+f"((d)[0]), "+f"((d)[1]), "+f"((d)[2]), "+f"((d)[3]) \
                 : "r"((a)[0]), "r"((a)[1]), "r"((a)[2]), "r"((a)[3]), \
                   "r"(b0), "r"(b1))

// ---------------------------------------------------------------------------
// Conversions: fp32 -> fp16
// ---------------------------------------------------------------------------
__global__ __launch_bounds__(256)
void convert_w_kernel(const float* __restrict__ cf_w1, const float* __restrict__ sc_w1,
                      const float* __restrict__ cf_b1, const float* __restrict__ sc_b1)
{
    size_t idx = (size_t)blockIdx.x * 256 + threadIdx.x;
    const size_t total = (size_t)1024 * C_SZ;
    if (idx < total) {
        size_t row = idx / C_SZ;
        float v = (row < HID) ? cf_w1[idx] : sc_w1[idx - (size_t)HID * C_SZ];
        g_W1[idx] = __float2half_rn(v);
    }
    if (idx < 1024)
        g_B1c[idx] = (idx < HID) ? cf_b1[idx] : sc_b1[idx - HID];
}

__global__ __launch_bounds__(256)
void convert_w2_kernel(const float* __restrict__ cf_w2, const float* __restrict__ sc_w2,
                       const float* __restrict__ cf_b2, const float* __restrict__ sc_b2)
{
    size_t idx = (size_t)blockIdx.x * 256 + threadIdx.x;
    const size_t total = (size_t)192 * HID;
    if (idx < total) {
        size_t row = idx / HID;
        float v = (row < L_D) ? cf_w2[idx] : sc_w2[idx - (size_t)L_D * HID];
        g_W2[idx] = __float2half_rn(v);
    }
    if (idx < 192)
        g_B2c[idx] = (idx < L_D) ? cf_b2[idx] : sc_b2[idx - L_D];
}

// Streaming cast x fp32 -> fp16 (no transpose; 8 elems/thread)
__global__ __launch_bounds__(256)
void convert_x_kernel(const float4* __restrict__ x)
{
    const size_t i = (size_t)blockIdx.x * 256 + threadIdx.x;
    float4 a = x[2 * i];
    float4 b = x[2 * i + 1];
    __half2 h0 = __floats2half2_rn(a.x, a.y);
    __half2 h1 = __floats2half2_rn(a.z, a.w);
    __half2 h2 = __floats2half2_rn(b.x, b.y);
    __half2 h3 = __floats2half2_rn(b.z, b.w);
    uint4 o;
    o.x = *reinterpret_cast<uint32_t*>(&h0);
    o.y = *reinterpret_cast<uint32_t*>(&h1);
    o.z = *reinterpret_cast<uint32_t*>(&h2);
    o.w = *reinterpret_cast<uint32_t*>(&h3);
    reinterpret_cast<uint4*>(g_X)[i] = o;
}

// ---------------------------------------------------------------------------
// GEMM1 (fp16 HMMA, single product): H[b] = relu(W1 @ X[b] + b1) -> fp16
//   A = W1 [1024][1536] k-major. B = X [b][c=k][n] fed via ldmatrix.trans.
//   CTA tile 128(m) x 256(n), K-chunk 64, 3-stage cp.async pipeline.
//   8 warps: 2(m) x 4(n), warp tile 64x64.
// ---------------------------------------------------------------------------
#define MT 128
#define NT 256
#define KC 64
#define NCHUNK (C_SZ / KC)            // 24
#define OFF_A 0
#define OFF_B (16 * 1024)
#define STAGE_BYTES (48 * 1024)
#define GEMM1_SMEM (3 * STAGE_BYTES)  // 144 KB

__global__ __launch_bounds__(256, 1)
void mma_gemm1_kernel(const __half* __restrict__ W1, const __half* __restrict__ X,
                      const float* __restrict__ bias, __half* __restrict__ H)
{
    extern __shared__ char dsmem[];
    const uint32_t smem_base = smem_u32(dsmem);

    const int tid = threadIdx.x;
    const int b  = blockIdx.z;
    const int n0 = blockIdx.x * NT;
    const int m0 = blockIdx.y * MT;

    const __half* Ag = W1 + (size_t)m0 * C_SZ;
    const __half* Bg = X + (size_t)b * C_SZ * HW + n0;

    const int lane = tid & 31, warp = tid >> 5;
    const int wm = warp >> 2, wn = warp & 3;   // warp tile: rows wm*64, cols wn*64

    const uint32_t lx = (uint32_t)(lane & 7);
    const uint32_t aG = (uint32_t)(lane >> 4);
    const uint32_t aRowOff = (uint32_t)(wm * 64 + (lane & 15)) * 128u;
    const uint32_t bRowOff = (uint32_t)(lane & 15) * 512u;
    const uint32_t bGbase = (uint32_t)(wn * 8) + (uint32_t)(lane >> 4);

    float acc[4][8][4];
    #pragma unroll
    for (int i = 0; i < 4; ++i)
        #pragma unroll
        for (int j = 0; j < 8; ++j)
            #pragma unroll
            for (int q = 0; q < 4; ++q) acc[i][j][q] = 0.f;

    auto load_chunk = [&](int c) {
        const uint32_t sb = smem_base + (uint32_t)(c % 3) * STAGE_BYTES;
        const size_t kk = (size_t)c * KC;
        // A: 128 rows x 8 groups (128B rows)
        #pragma unroll
        for (int i = 0; i < 4; ++i) {
            int idx = tid + 256 * i;
            int r = idx >> 3, g = idx & 7;
            uint32_t so = (uint32_t)r * 128u + (uint32_t)((g ^ (r & 7)) << 4);
            cp16(sb + OFF_A + so, (const char*)(Ag + (size_t)r * C_SZ + kk) + g * 16);
        }
        // B: 64 k-rows x 32 groups (512B rows)
        #pragma unroll
        for (int i = 0; i < 8; ++i) {
            int idx = tid + 256 * i;
            int r = idx >> 5, g = idx & 31;
            uint32_t so = (uint32_t)r * 512u + (uint32_t)((g ^ (r & 7)) << 4);
            cp16(sb + OFF_B + so, (const char*)(Bg + (kk + r) * HW) + g * 16);
        }
        asm volatile("cp.async.commit_group;" ::: "memory");
    };

    load_chunk(0);
    load_chunk(1);

    for (int c = 0; c < NCHUNK; ++c) {
        if (c + 2 < NCHUNK) {
            load_chunk(c + 2);
            asm volatile("cp.async.wait_group 2;" ::: "memory");
        } else if (c + 1 < NCHUNK) {
            asm volatile("cp.async.wait_group 1;" ::: "memory");
        } else {
            asm volatile("cp.async.wait_group 0;" ::: "memory");
        }
        __syncthreads();

        const uint32_t sb = smem_base + (uint32_t)(c % 3) * STAGE_BYTES;

        #pragma unroll
        for (int ks = 0; ks < 4; ++ks) {
            const uint32_t gA = ((uint32_t)(ks * 2) + aG) ^ lx;
            const uint32_t bRow = (uint32_t)(ks * 16) * 512u + bRowOff;

            uint32_t ah[16], bh[16];
            #pragma unroll
            for (int ma = 0; ma < 4; ++ma) {
                uint32_t ad = sb + OFF_A + aRowOff + (uint32_t)(ma * 16 * 128) + (gA << 4);
                LDSM_X4(ah[4*ma+0], ah[4*ma+1], ah[4*ma+2], ah[4*ma+3], ad);
            }
            #pragma unroll
            for (int nb = 0; nb < 4; ++nb) {
                uint32_t gB = (bGbase + (uint32_t)(nb * 2)) ^ lx;
                uint32_t bd = sb + OFF_B + bRow + (gB << 4);
                LDSM_X4_T(bh[4*nb+0], bh[4*nb+1], bh[4*nb+2], bh[4*nb+3], bd);
            }
            #pragma unroll
            for (int ma = 0; ma < 4; ++ma)
                #pragma unroll
                for (int na = 0; na < 8; ++na)
                    MMA_F16(acc[ma][na], &ah[4*ma], bh[2*na], bh[2*na+1]);
        }
        __syncthreads();
    }

    // epilogue: bias + relu -> fp16 store, layout [b][k=row][n]
    const int g  = lane >> 2;
    const int tc = lane & 3;
    #pragma unroll
    for (int ma = 0; ma < 4; ++ma) {
        const int r0 = m0 + wm * 64 + ma * 16 + g;
        const int r1 = r0 + 8;
        const float bb0 = bias[r0];
        const float bb1 = bias[r1];
        const size_t base0 = ((size_t)b * 1024 + r0) * HW + n0 + wn * 64 + tc * 2;
        const size_t base1 = ((size_t)b * 1024 + r1) * HW + n0 + wn * 64 + tc * 2;
        #pragma unroll
        for (int na = 0; na < 8; ++na) {
            float v00 = fmaxf(acc[ma][na][0] + bb0, 0.f);
            float v01 = fmaxf(acc[ma][na][1] + bb0, 0.f);
            float v10 = fmaxf(acc[ma][na][2] + bb1, 0.f);
            float v11 = fmaxf(acc[ma][na][3] + bb1, 0.f);
            *reinterpret_cast<__half2*>(H + base0 + na * 8) = __floats2half2_rn(v00, v01);
            *reinterpret_cast<__half2*>(H + base1 + na * 8) = __floats2half2_rn(v10, v11);
        }
    }
}

// ---------------------------------------------------------------------------
// GEMM2 (fp16 HMMA, single product): [F; Z] = W2 @ H + b2
//   A = W2 [192][512] k-major. B = H [b][k][n] via ldmatrix.trans.
//   CTA tile 64(m) x 256(n), K=512, double buffer. 8 warps along n.
// ---------------------------------------------------------------------------
#define NT2 256
#define NCH2 (HID / KC)               // 8
#define S2_A 0
#define S2_B (8 * 1024)
#define S2_STAGE (40 * 1024)
#define GEMM2_SMEM (2 * S2_STAGE)     // 80 KB

__global__ __launch_bounds__(256, 1)
void mma_gemm2_kernel(const __half* __restrict__ W2, const __half* __restrict__ H,
                      const float* __restrict__ bias,
                      float* __restrict__ Fout, float* __restrict__ Zout)
{
    extern __shared__ char dsmem[];
    const uint32_t smem_base = smem_u32(dsmem);

    const int tid = threadIdx.x;
    const int b  = blockIdx.z;
    const int n0 = blockIdx.x * NT2;
    const int m0 = blockIdx.y * 64;                // 0, 64, 128
    const int koff = (m0 == 128) ? 512 : 0;        // sc hidden rows

    const __half* Ag = W2 + (size_t)m0 * HID;
    const __half* Bg = H + ((size_t)b * 1024 + koff) * HW + n0;

    const int lane = tid & 31, wn = tid >> 5;      // 8 warps along n

    float acc[4][4][4];
    #pragma unroll
    for (int i = 0; i < 4; ++i)
        #pragma unroll
        for (int j = 0; j < 4; ++j)
            #pragma unroll
            for (int q = 0; q < 4; ++q) acc[i][j][q] = 0.f;

    auto load_chunk = [&](int c, uint32_t sb) {
        const int kk = c * KC;
        #pragma unroll
        for (int i = 0; i < 2; ++i) {
            int idx = tid + 256 * i;
            int r = idx >> 3, g = idx & 7;
            uint32_t so = (uint32_t)r * 128u + (uint32_t)((g ^ (r & 7)) << 4);
            cp16(sb + S2_A + so, (const char*)(Ag + (size_t)r * HID + kk) + g * 16);
        }
        #pragma unroll
        for (int i = 0; i < 8; ++i) {
            int idx = tid + 256 * i;
            int r = idx >> 5, g = idx & 31;
            uint32_t so = (uint32_t)r * 512u + (uint32_t)((g ^ (r & 7)) << 4);
            cp16(sb + S2_B + so, (const char*)(Bg + (size_t)(kk + r) * HW) + g * 16);
        }
        asm volatile("cp.async.commit_group;" ::: "memory");
    };

    load_chunk(0, smem_base);

    const uint32_t lx = (uint32_t)(lane & 7);
    const uint32_t aG = (uint32_t)(lane >> 4);
    const uint32_t aRowOff = (uint32_t)(lane & 15) * 128u;
    const uint32_t bRowOff = (uint32_t)(lane & 15) * 512u;
    const uint32_t bGbase = (uint32_t)(wn * 4) + (uint32_t)(lane >> 4);

    for (int c = 0; c < NCH2; ++c) {
        const uint32_t sb = smem_base + (uint32_t)(c & 1) * S2_STAGE;
        if (c + 1 < NCH2) {
            load_chunk(c + 1, smem_base + (uint32_t)((c + 1) & 1) * S2_STAGE);
            asm volatile("cp.async.wait_group 1;" ::: "memory");
        } else {
            asm volatile("cp.async.wait_group 0;" ::: "memory");
        }
        __syncthreads();

        #pragma unroll
        for (int ks = 0; ks < 4; ++ks) {
            const uint32_t gA = ((uint32_t)(ks * 2) + aG) ^ lx;
            const uint32_t bRow = (uint32_t)(ks * 16) * 512u + bRowOff;

            uint32_t ah[16], bh[8];
            #pragma unroll
            for (int ma = 0; ma < 4; ++ma) {
                uint32_t ad = sb + S2_A + aRowOff + (uint32_t)(ma * 16 * 128) + (gA << 4);
                LDSM_X4(ah[4*ma+0], ah[4*ma+1], ah[4*ma+2], ah[4*ma+3], ad);
            }
            #pragma unroll
            for (int nb = 0; nb < 2; ++nb) {
                uint32_t gB = (bGbase + (uint32_t)(nb * 2)) ^ lx;
                uint32_t bd = sb + S2_B + bRow + (gB << 4);
                LDSM_X4_T(bh[4*nb+0], bh[4*nb+1], bh[4*nb+2], bh[4*nb+3], bd);
            }
            #pragma unroll
            for (int ma = 0; ma < 4; ++ma)
                #pragma unroll
                for (int na = 0; na < 4; ++na)
                    MMA_F16(acc[ma][na], &ah[4*ma], bh[2*na], bh[2*na+1]);
        }
        __syncthreads();
    }

    // epilogue: bias + fp32 store into F (rows<128) or Z (rows>=128)
    const int g  = lane >> 2;
    const int tc = lane & 3;
    #pragma unroll
    for (int ma = 0; ma < 4; ++ma) {
        const int r0 = m0 + ma * 16 + g;
        const int r1 = r0 + 8;
        const float bb0 = bias[r0];
        const float bb1 = bias[r1];
        float* p0 = (r0 < L_D)
            ? Fout + ((size_t)b * L_D + r0) * HW
            : Zout + ((size_t)b * (M_CL + 1) + (r0 - L_D)) * HW;
        float* p1 = (r1 < L_D)
            ? Fout + ((size_t)b * L_D + r1) * HW
            : Zout + ((size_t)b * (M_CL + 1) + (r1 - L_D)) * HW;
        p0 += n0 + wn * 32 + tc * 2;
        p1 += n0 + wn * 32 + tc * 2;
        #pragma unroll
        for (int na = 0; na < 4; ++na) {
            float2 v0, v1;
            v0.x = acc[ma][na][0] + bb0;
            v0.y = acc[ma][na][1] + bb0;
            v1.x = acc[ma][na][2] + bb1;
            v1.y = acc[ma][na][3] + bb1;
            *reinterpret_cast<float2*>(p0 + na * 8) = v0;
            *reinterpret_cast<float2*>(p1 + na * 8) = v1;
        }
    }
}

// ---------------------------------------------------------------------------
// Token MLP
// ---------------------------------------------------------------------------
__global__ __launch_bounds__(256)
void token_hidden_kernel(const float* __restrict__ t, const float* __restrict__ w1,
                         const float* __restrict__ b1)
{
    __shared__ float ts[C_SZ];
    const int b = blockIdx.x;
    for (int c = threadIdx.x; c < C_SZ; c += 256) ts[c] = t[(size_t)b * C_SZ + c];
    __syncthreads();
    const int wid = threadIdx.x >> 5, lane = threadIdx.x & 31;
    for (int o = wid; o < HID; o += 8) {
        const float* wr = w1 + (size_t)o * C_SZ;
        float s = 0.f;
        for (int c = lane; c < C_SZ; c += 32) s = fmaf(ts[c], wr[c], s);
        #pragma unroll
        for (int off = 16; off; off >>= 1) s += __shfl_xor_sync(0xFFFFFFFFu, s, off);
        if (lane == 0) g_TKH[(size_t)b * HID + o] = fmaxf(s + b1[o], 0.f);
    }
}

__global__ __launch_bounds__(256)
void token_out_kernel(const float* __restrict__ w2, const float* __restrict__ b2)
{
    __shared__ float hs[HID];
    const int b = blockIdx.x;
    for (int c = threadIdx.x; c < HID; c += 256) hs[c] = g_TKH[(size_t)b * HID + c];
    __syncthreads();
    const int wid = threadIdx.x >> 5, lane = threadIdx.x & 31;
    for (int o = wid; o < G_D; o += 8) {
        const float* wr = w2 + (size_t)o * HID;
        float s = 0.f;
        for (int c = lane; c < HID; c += 32) s = fmaf(hs[c], wr[c], s);
        #pragma unroll
        for (int off = 16; off; off >>= 1) s += __shfl_xor_sync(0xFFFFFFFFu, s, off);
        if (lane == 0) g_TK[(size_t)b * G_D + o] = s + b2[o];
    }
}

// ---------------------------------------------------------------------------
// Sinkhorn (log-space), 1024 threads/block, one block per batch.
// ---------------------------------------------------------------------------
__global__ __launch_bounds__(1024)
void sinkhorn_kernel(const float* __restrict__ alpha_p)
{
    const int b = blockIdx.x;
    float* Zb = g_Z + (size_t)b * (M_CL + 1) * HW;

    __shared__ float u[M_CL + 1];
    __shared__ float wsum[M_CL + 1][33];

    const int j = threadIdx.x;
    const int lane = j & 31, warp = j >> 5;
    const float alpha = *alpha_p;
    const float norm = -logf((float)(M_CL + HW));
    const float log_mu_last = logf((float)(HW - M_CL)) + norm;

    float v = 0.f;

    for (int it = 0; it < 3; ++it) {
        #pragma unroll 4
        for (int i = 0; i <= M_CL; ++i) {
            float z = ((i < M_CL) ? Zb[(size_t)i * HW + j] : alpha) + v;
            float e = __expf(z);
            #pragma unroll
            for (int off = 16; off; off >>= 1) e += __shfl_xor_sync(0xFFFFFFFFu, e, off);
            if (lane == 0) wsum[i][warp] = e;
        }
        __syncthreads();
        if (j <= M_CL) {
            float s = 0.f;
            #pragma unroll
            for (int w = 0; w < 32; ++w) s += wsum[j][w];
            u[j] = ((j < M_CL) ? norm : log_mu_last) - logf(s);
        }
        __syncthreads();

        float s = 0.f;
        #pragma unroll 8
        for (int i = 0; i < M_CL; ++i)
            s += __expf(Zb[(size_t)i * HW + j] + u[i]);
        s += __expf(alpha + u[M_CL]);
        v = norm - logf(s);
    }

    #pragma unroll 8
    for (int i = 0; i < M_CL; ++i)
        Zb[(size_t)i * HW + j] = __expf(Zb[(size_t)i * HW + j] + u[i] + v - norm);
}

// ---------------------------------------------------------------------------
// agg[b][l][m] = sum_n F[b][l][n] * P[b][m][n]; grid (4 l-quads, B)
// ---------------------------------------------------------------------------
__global__ __launch_bounds__(256)
void agg_kernel()
{
    const int b = blockIdx.y;
    const int l0 = blockIdx.x * 32;
    const float* Fb = g_F + (size_t)b * L_D * HW + (size_t)l0 * HW;
    const float* Pb = g_Z + (size_t)b * (M_CL + 1) * HW;
    float*       Cb = g_AGG + (size_t)b * L_D * M_CL + (size_t)l0 * M_CL;

    __shared__ float Fs[32][36];   // [k][l]
    __shared__ float Ps[32][68];   // [k][m]

    const int tid = threadIdx.x;
    const int tx = tid & 15, ty = tid >> 4;   // tx -> m (4 each), ty -> l (2 each)

    float acc[2][4];
    #pragma unroll
    for (int i = 0; i < 2; ++i)
        #pragma unroll
        for (int j = 0; j < 4; ++j) acc[i][j] = 0.f;

    for (int n0 = 0; n0 < HW; n0 += 32) {
        {   // F tile: 32 l x 32 k
            int l = tid >> 3, kq = (tid & 7) << 2;
            float4 fv = *reinterpret_cast<const float4*>(&Fb[(size_t)l * HW + n0 + kq]);
            Fs[kq + 0][l] = fv.x; Fs[kq + 1][l] = fv.y;
            Fs[kq + 2][l] = fv.z; Fs[kq + 3][l] = fv.w;
        }
        #pragma unroll
        for (int r = 0; r < 2; ++r) {   // P tile: 64 m x 32 k
            int id = tid + 256 * r;
            int m = id >> 3, kq = (id & 7) << 2;
            float4 pv = *reinterpret_cast<const float4*>(&Pb[(size_t)m * HW + n0 + kq]);
            Ps[kq + 0][m] = pv.x; Ps[kq + 1][m] = pv.y;
            Ps[kq + 2][m] = pv.z; Ps[kq + 3][m] = pv.w;
        }
        __syncthreads();

        #pragma unroll
        for (int k = 0; k < 32; ++k) {
            float rl[2], rm[4];
            #pragma unroll
            for (int i = 0; i < 2; ++i) rl[i] = Fs[k][ty * 2 + i];
            #pragma unroll
            for (int j = 0; j < 4; ++j) rm[j] = Ps[k][tx * 4 + j];
            #pragma unroll
            for (int i = 0; i < 2; ++i)
                #pragma unroll
                for (int j = 0; j < 4; ++j)
                    acc[i][j] = fmaf(rl[i], rm[j], acc[i][j]);
        }
        __syncthreads();
    }

    #pragma unroll
    for (int i = 0; i < 2; ++i)
        #pragma unroll
        for (int j = 0; j < 4; ++j)
            Cb[(size_t)(ty * 2 + i) * M_CL + tx * 4 + j] = acc[i][j];
}

// ---------------------------------------------------------------------------
// Finalize
// ---------------------------------------------------------------------------
__device__ __forceinline__ float block_sum256(float val, float* red)
{
    const int lane = threadIdx.x & 31, wid = threadIdx.x >> 5;
    #pragma unroll
    for (int off = 16; off; off >>= 1) val += __shfl_xor_sync(0xFFFFFFFFu, val, off);
    if (lane == 0) red[wid] = val;
    __syncthreads();
    float s = red[0] + red[1] + red[2] + red[3] + red[4] + red[5] + red[6] + red[7];
    __syncthreads();
    return s;
}

__global__ __launch_bounds__(256)
void finalize_kernel(float* __restrict__ out)
{
    const int b = blockIdx.x;
    const int tid = threadIdx.x;
    __shared__ float an[L_D * M_CL];
    __shared__ float tkn[G_D];
    __shared__ float cn[M_CL];
    __shared__ float red[8];

    const float* aggb = g_AGG + (size_t)b * L_D * M_CL;

    float tv = g_TK[(size_t)b * G_D + tid];
    float tk_ss = block_sum256(tv * tv, red);
    tkn[tid] = tv / fmaxf(sqrtf(tk_ss), EPSV);

    if (tid < M_CL) {
        float s = 0.f;
        for (int l = 0; l < L_D; ++l) {
            float a = aggb[(size_t)l * M_CL + tid];
            s = fmaf(a, a, s);
        }
        cn[tid] = fmaxf(sqrtf(s), EPSV);
    }
    __syncthreads();

    float gs = tkn[tid] * tkn[tid];
    for (int idx = tid; idx < L_D * M_CL; idx += 256) {
        float a = aggb[idx] / cn[idx & (M_CL - 1)];
        an[idx] = a;
        gs = fmaf(a, a, gs);
    }
    float total = block_sum256(gs, red);
    float scale = 1.f / fmaxf(sqrtf(total), EPSV);

    float* ob = out + (size_t)b * (G_D + L_D * M_CL);
    ob[tid] = tkn[tid] * scale;
    for (int idx = tid; idx < L_D * M_CL; idx += 256)
        ob[G_D + idx] = an[idx] * scale;
}

// ---------------------------------------------------------------------------
// Launch
// ---------------------------------------------------------------------------
extern "C" void kernel_launch(void* const* d_in, const int* in_sizes, int n_in,
                              void* d_out, int out_size)
{
    const float* x      = (const float*)d_in[0];
    const float* t      = (const float*)d_in[1];
    const float* cf_w1  = (const float*)d_in[2];
    const float* cf_b1  = (const float*)d_in[3];
    const float* cf_w2  = (const float*)d_in[4];
    const float* cf_b2  = (const float*)d_in[5];
    const float* sc_w1  = (const float*)d_in[6];
    const float* sc_b1  = (const float*)d_in[7];
    const float* sc_w2  = (const float*)d_in[8];
    const float* sc_b2  = (const float*)d_in[9];
    const float* tk_w1  = (const float*)d_in[10];
    const float* tk_b1  = (const float*)d_in[11];
    const float* tk_w2  = (const float*)d_in[12];
    const float* tk_b2  = (const float*)d_in[13];
    const float* dust   = (const float*)d_in[14];

    float *F, *Z, *B1, *B2;
    __half *X, *W1, *W2, *H;
    cudaGetSymbolAddress((void**)&F,  g_F);
    cudaGetSymbolAddress((void**)&Z,  g_Z);
    cudaGetSymbolAddress((void**)&B1, g_B1c);
    cudaGetSymbolAddress((void**)&B2, g_B2c);
    cudaGetSymbolAddress((void**)&X,  g_X);
    cudaGetSymbolAddress((void**)&W1, g_W1);
    cudaGetSymbolAddress((void**)&W2, g_W2);
    cudaGetSymbolAddress((void**)&H,  g_H);

    cudaFuncSetAttribute(mma_gemm1_kernel,
                         cudaFuncAttributeMaxDynamicSharedMemorySize, GEMM1_SMEM);
    cudaFuncSetAttribute(mma_gemm2_kernel,
                         cudaFuncAttributeMaxDynamicSharedMemorySize, GEMM2_SMEM);

    // conversions
    convert_w_kernel<<<(1024 * C_SZ + 255) / 256, 256>>>(cf_w1, sc_w1, cf_b1, sc_b1);
    convert_w2_kernel<<<(192 * HID + 255) / 256, 256>>>(cf_w2, sc_w2, cf_b2, sc_b2);
    convert_x_kernel<<<(int)(((size_t)B_SZ * C_SZ * HW / 8 + 255) / 256), 256>>>(
        (const float4*)x);

    // GEMM1: hidden layers (cf + sc fused), fp16 HMMA single product
    mma_gemm1_kernel<<<dim3(HW / NT, 1024 / MT, B_SZ), 256, GEMM1_SMEM>>>(
        W1, X, B1, H);

    // GEMM2: F and Z from H, fp16 HMMA single product
    mma_gemm2_kernel<<<dim3(HW / NT2, 3, B_SZ), 256, GEMM2_SMEM>>>(
        W2, H, B2, F, Z);

    // Token MLP
    token_hidden_kernel<<<B_SZ, 256>>>(t, tk_w1, tk_b1);
    token_out_kernel<<<B_SZ, 256>>>(tk_w2, tk_b2);

    // Sinkhorn + aggregation + normalization
    sinkhorn_kernel<<<B_SZ, 1024>>>(dust);
    agg_kernel<<<dim3(4, B_SZ), 256>>>();
    finalize_kernel<<<B_SZ, 256>>>((float*)d_out);
}

// round 8
// speedup vs baseline: 7.0670x; 1.4320x over previous
#include <cuda_runtime.h>
#include <cuda_fp16.h>
#include <math.h>
#include <stdint.h>

// ---------------------------------------------------------------------------
// SALAD pipeline. Round 8:
//   gemm1: fp16 single-product HMMA, 128x128 tile, 2 CTAs/SM (regs<=128)
//   gemm2: unchanged + 2-CTA occupancy hint
//   side-stream overlap: weight converts + fused token MLP || main chain
// Shapes: B=32, C=1536, HW=1024, hidden=512, L=128, M=64 (+dustbin), G=256.
// ---------------------------------------------------------------------------

#define B_SZ 32
#define C_SZ 1536
#define HW   1024
#define HID  512
#define L_D  128
#define M_CL 64
#define G_D  256
#define EPSV 1e-12f

// Scratch (device globals; allocation-free rule)
__device__ __align__(256) __half g_H[(size_t)B_SZ * 1024 * HW];      // H [b][k][n] fp16
__device__ __align__(256) float g_F[(size_t)B_SZ * L_D * HW];        // [B][128][HW]
__device__ __align__(256) float g_Z[(size_t)B_SZ * (M_CL + 1) * HW]; // [B][65][HW]
__device__ __align__(256) float g_AGG[(size_t)B_SZ * L_D * M_CL];
__device__ __align__(256) float g_TK[(size_t)B_SZ * G_D];

// fp16 operands
__device__ __align__(256) __half g_X[(size_t)B_SZ * C_SZ * HW]; // x [b][c][n] fp16
__device__ __align__(256) __half g_W1[(size_t)1024 * C_SZ];     // [cf_w1; sc_w1]
__device__ __align__(256) __half g_W2[(size_t)192 * HID];       // [cf_w2; sc_w2]
__device__ __align__(256) float g_B1c[1024];                    // [cf_b1; sc_b1]
__device__ __align__(256) float g_B2c[192];                     // [cf_b2; sc_b2]

// ---------------------------------------------------------------------------
// PTX helpers (family-common only)
// ---------------------------------------------------------------------------
__device__ __forceinline__ uint32_t smem_u32(const void* p) {
    uint32_t a;
    asm("{ .reg .u64 t; cvta.to.shared.u64 t, %1; cvt.u32.u64 %0, t; }"
        : "=r"(a) : "l"(p));
    return a;
}

__device__ __forceinline__ void cp16(uint32_t saddr, const void* gaddr) {
    asm volatile("cp.async.cg.shared.global [%0], [%1], 16;"
                 :: "r"(saddr), "l"(gaddr) : "memory");
}

#define LDSM_X4(r0, r1, r2, r3, addr) \
    asm volatile("ldmatrix.sync.aligned.m8n8.x4.shared.b16 {%0,%1,%2,%3}, [%4];" \
                 : "=r"(r0), "=r"(r1), "=r"(r2), "=r"(r3) : "r"(addr))

#define LDSM_X4_T(r0, r1, r2, r3, addr) \
    asm volatile("ldmatrix.sync.aligned.m8n8.x4.trans.shared.b16 {%0,%1,%2,%3}, [%4];" \
                 : "=r"(r0), "=r"(r1), "=r"(r2), "=r"(r3) : "r"(addr))

#define MMA_F16(d, a, b0, b1) \
    asm volatile("mma.sync.aligned.m16n8k16.row.col.f32.f16.f16.f32 " \
                 "{%0,%1,%2,%3}, {%4,%5,%6,%7}, {%8,%9}, {%0,%1,%2,%3};" \
                 : "+f"((d)[0]), "+f"((d)[1]), "+f"((d)[2]), "+f"((d)[3]) \
                 : "r"((a)[0]), "r"((a)[1]), "r"((a)[2]), "r"((a)[3]), \
                   "r"(b0), "r"(b1))

// ---------------------------------------------------------------------------
// Conversions: fp32 -> fp16
// ---------------------------------------------------------------------------
__global__ __launch_bounds__(256)
void convert_w_kernel(const float* __restrict__ cf_w1, const float* __restrict__ sc_w1,
                      const float* __restrict__ cf_b1, const float* __restrict__ sc_b1)
{
    size_t idx = (size_t)blockIdx.x * 256 + threadIdx.x;
    const size_t total = (size_t)1024 * C_SZ;
    if (idx < total) {
        size_t row = idx / C_SZ;
        float v = (row < HID) ? cf_w1[idx] : sc_w1[idx - (size_t)HID * C_SZ];
        g_W1[idx] = __float2half_rn(v);
    }
    if (idx < 1024)
        g_B1c[idx] = (idx < HID) ? cf_b1[idx] : sc_b1[idx - HID];
}

__global__ __launch_bounds__(256)
void convert_w2_kernel(const float* __restrict__ cf_w2, const float* __restrict__ sc_w2,
                       const float* __restrict__ cf_b2, const float* __restrict__ sc_b2)
{
    size_t idx = (size_t)blockIdx.x * 256 + threadIdx.x;
    const size_t total = (size_t)192 * HID;
    if (idx < total) {
        size_t row = idx / HID;
        float v = (row < L_D) ? cf_w2[idx] : sc_w2[idx - (size_t)L_D * HID];
        g_W2[idx] = __float2half_rn(v);
    }
    if (idx < 192)
        g_B2c[idx] = (idx < L_D) ? cf_b2[idx] : sc_b2[idx - L_D];
}

// Streaming cast x fp32 -> fp16 (no transpose; 8 elems/thread)
__global__ __launch_bounds__(256)
void convert_x_kernel(const float4* __restrict__ x)
{
    const size_t i = (size_t)blockIdx.x * 256 + threadIdx.x;
    float4 a = x[2 * i];
    float4 b = x[2 * i + 1];
    __half2 h0 = __floats2half2_rn(a.x, a.y);
    __half2 h1 = __floats2half2_rn(a.z, a.w);
    __half2 h2 = __floats2half2_rn(b.x, b.y);
    __half2 h3 = __floats2half2_rn(b.z, b.w);
    uint4 o;
    o.x = *reinterpret_cast<uint32_t*>(&h0);
    o.y = *reinterpret_cast<uint32_t*>(&h1);
    o.z = *reinterpret_cast<uint32_t*>(&h2);
    o.w = *reinterpret_cast<uint32_t*>(&h3);
    reinterpret_cast<uint4*>(g_X)[i] = o;
}

// ---------------------------------------------------------------------------
// GEMM1 (fp16 HMMA, single product): H[b] = relu(W1 @ X[b] + b1) -> fp16
//   A = W1 [1024][1536] k-major. B = X [b][c=k][n] via ldmatrix.trans.
//   CTA tile 128(m) x 128(n), K-chunk 64, 3-stage cp.async, 2 CTAs/SM.
//   8 warps: 2(m) x 4(n), warp tile 64x32.
// ---------------------------------------------------------------------------
#define MT 128
#define NT 128
#define KC 64
#define NCHUNK (C_SZ / KC)            // 24
#define OFF_A 0
#define OFF_B (16 * 1024)
#define STAGE_BYTES (32 * 1024)
#define GEMM1_SMEM (3 * STAGE_BYTES)  // 96 KB -> 2 CTAs/SM = 192 KB

__global__ __launch_bounds__(256, 2)
void mma_gemm1_kernel(const __half* __restrict__ W1, const __half* __restrict__ X,
                      const float* __restrict__ bias, __half* __restrict__ H)
{
    extern __shared__ char dsmem[];
    const uint32_t smem_base = smem_u32(dsmem);

    const int tid = threadIdx.x;
    const int b  = blockIdx.z;
    const int n0 = blockIdx.x * NT;
    const int m0 = blockIdx.y * MT;

    const __half* Ag = W1 + (size_t)m0 * C_SZ;
    const __half* Bg = X + (size_t)b * C_SZ * HW + n0;

    const int lane = tid & 31, warp = tid >> 5;
    const int wm = warp >> 2, wn = warp & 3;   // warp tile: rows wm*64, cols wn*32

    const uint32_t lx = (uint32_t)(lane & 7);
    const uint32_t aG = (uint32_t)(lane >> 4);
    const uint32_t aRowOff = (uint32_t)(wm * 64 + (lane & 15)) * 128u;
    const uint32_t bRowOff = (uint32_t)(lane & 15) * 256u;
    const uint32_t bGbase = (uint32_t)(wn * 4) + (uint32_t)(lane >> 4);

    float acc[4][4][4];
    #pragma unroll
    for (int i = 0; i < 4; ++i)
        #pragma unroll
        for (int j = 0; j < 4; ++j)
            #pragma unroll
            for (int q = 0; q < 4; ++q) acc[i][j][q] = 0.f;

    auto load_chunk = [&](int c) {
        const uint32_t sb = smem_base + (uint32_t)(c % 3) * STAGE_BYTES;
        const size_t kk = (size_t)c * KC;
        // A: 128 rows x 8 groups (128B rows) = 1024 cp16
        #pragma unroll
        for (int i = 0; i < 4; ++i) {
            int idx = tid + 256 * i;
            int r = idx >> 3, g = idx & 7;
            uint32_t so = (uint32_t)r * 128u + (uint32_t)((g ^ (r & 7)) << 4);
            cp16(sb + OFF_A + so, (const char*)(Ag + (size_t)r * C_SZ + kk) + g * 16);
        }
        // B: 64 k-rows x 16 groups (256B rows) = 1024 cp16
        #pragma unroll
        for (int i = 0; i < 4; ++i) {
            int idx = tid + 256 * i;
            int r = idx >> 4, g = idx & 15;
            uint32_t so = (uint32_t)r * 256u + (uint32_t)((g ^ (r & 7)) << 4);
            cp16(sb + OFF_B + so, (const char*)(Bg + (kk + r) * HW) + g * 16);
        }
        asm volatile("cp.async.commit_group;" ::: "memory");
    };

    load_chunk(0);
    load_chunk(1);

    for (int c = 0; c < NCHUNK; ++c) {
        if (c + 2 < NCHUNK) {
            load_chunk(c + 2);
            asm volatile("cp.async.wait_group 2;" ::: "memory");
        } else if (c + 1 < NCHUNK) {
            asm volatile("cp.async.wait_group 1;" ::: "memory");
        } else {
            asm volatile("cp.async.wait_group 0;" ::: "memory");
        }
        __syncthreads();

        const uint32_t sb = smem_base + (uint32_t)(c % 3) * STAGE_BYTES;

        #pragma unroll
        for (int ks = 0; ks < 4; ++ks) {
            const uint32_t gA = ((uint32_t)(ks * 2) + aG) ^ lx;
            const uint32_t bRow = (uint32_t)(ks * 16) * 256u + bRowOff;

            uint32_t ah[16], bh[8];
            #pragma unroll
            for (int ma = 0; ma < 4; ++ma) {
                uint32_t ad = sb + OFF_A + aRowOff + (uint32_t)(ma * 16 * 128) + (gA << 4);
                LDSM_X4(ah[4*ma+0], ah[4*ma+1], ah[4*ma+2], ah[4*ma+3], ad);
            }
            #pragma unroll
            for (int nb = 0; nb < 2; ++nb) {
                uint32_t gB = (bGbase + (uint32_t)(nb * 2)) ^ lx;
                uint32_t bd = sb + OFF_B + bRow + (gB << 4);
                LDSM_X4_T(bh[4*nb+0], bh[4*nb+1], bh[4*nb+2], bh[4*nb+3], bd);
            }
            #pragma unroll
            for (int ma = 0; ma < 4; ++ma)
                #pragma unroll
                for (int na = 0; na < 4; ++na)
                    MMA_F16(acc[ma][na], &ah[4*ma], bh[2*na], bh[2*na+1]);
        }
        __syncthreads();
    }

    // epilogue: bias + relu -> fp16 store, layout [b][k=row][n]
    const int g  = lane >> 2;
    const int tc = lane & 3;
    #pragma unroll
    for (int ma = 0; ma < 4; ++ma) {
        const int r0 = m0 + wm * 64 + ma * 16 + g;
        const int r1 = r0 + 8;
        const float bb0 = bias[r0];
        const float bb1 = bias[r1];
        const size_t base0 = ((size_t)b * 1024 + r0) * HW + n0 + wn * 32 + tc * 2;
        const size_t base1 = ((size_t)b * 1024 + r1) * HW + n0 + wn * 32 + tc * 2;
        #pragma unroll
        for (int na = 0; na < 4; ++na) {
            float v00 = fmaxf(acc[ma][na][0] + bb0, 0.f);
            float v01 = fmaxf(acc[ma][na][1] + bb0, 0.f);
            float v10 = fmaxf(acc[ma][na][2] + bb1, 0.f);
            float v11 = fmaxf(acc[ma][na][3] + bb1, 0.f);
            *reinterpret_cast<__half2*>(H + base0 + na * 8) = __floats2half2_rn(v00, v01);
            *reinterpret_cast<__half2*>(H + base1 + na * 8) = __floats2half2_rn(v10, v11);
        }
    }
}

// ---------------------------------------------------------------------------
// GEMM2 (fp16 HMMA, single product): [F; Z] = W2 @ H + b2
//   CTA tile 64(m) x 256(n), K=512, double buffer. 8 warps along n.
// ---------------------------------------------------------------------------
#define NT2 256
#define NCH2 (HID / KC)               // 8
#define S2_A 0
#define S2_B (8 * 1024)
#define S2_STAGE (40 * 1024)
#define GEMM2_SMEM (2 * S2_STAGE)     // 80 KB -> 2 CTAs/SM = 160 KB

__global__ __launch_bounds__(256, 2)
void mma_gemm2_kernel(const __half* __restrict__ W2, const __half* __restrict__ H,
                      const float* __restrict__ bias,
                      float* __restrict__ Fout, float* __restrict__ Zout)
{
    extern __shared__ char dsmem[];
    const uint32_t smem_base = smem_u32(dsmem);

    const int tid = threadIdx.x;
    const int b  = blockIdx.z;
    const int n0 = blockIdx.x * NT2;
    const int m0 = blockIdx.y * 64;                // 0, 64, 128
    const int koff = (m0 == 128) ? 512 : 0;        // sc hidden rows

    const __half* Ag = W2 + (size_t)m0 * HID;
    const __half* Bg = H + ((size_t)b * 1024 + koff) * HW + n0;

    const int lane = tid & 31, wn = tid >> 5;      // 8 warps along n

    float acc[4][4][4];
    #pragma unroll
    for (int i = 0; i < 4; ++i)
        #pragma unroll
        for (int j = 0; j < 4; ++j)
            #pragma unroll
            for (int q = 0; q < 4; ++q) acc[i][j][q] = 0.f;

    auto load_chunk = [&](int c, uint32_t sb) {
        const int kk = c * KC;
        #pragma unroll
        for (int i = 0; i < 2; ++i) {
            int idx = tid + 256 * i;
            int r = idx >> 3, g = idx & 7;
            uint32_t so = (uint32_t)r * 128u + (uint32_t)((g ^ (r & 7)) << 4);
            cp16(sb + S2_A + so, (const char*)(Ag + (size_t)r * HID + kk) + g * 16);
        }
        #pragma unroll
        for (int i = 0; i < 8; ++i) {
            int idx = tid + 256 * i;
            int r = idx >> 5, g = idx & 31;
            uint32_t so = (uint32_t)r * 512u + (uint32_t)((g ^ (r & 7)) << 4);
            cp16(sb + S2_B + so, (const char*)(Bg + (size_t)(kk + r) * HW) + g * 16);
        }
        asm volatile("cp.async.commit_group;" ::: "memory");
    };

    load_chunk(0, smem_base);

    const uint32_t lx = (uint32_t)(lane & 7);
    const uint32_t aG = (uint32_t)(lane >> 4);
    const uint32_t aRowOff = (uint32_t)(lane & 15) * 128u;
    const uint32_t bRowOff = (uint32_t)(lane & 15) * 512u;
    const uint32_t bGbase = (uint32_t)(wn * 4) + (uint32_t)(lane >> 4);

    for (int c = 0; c < NCH2; ++c) {
        const uint32_t sb = smem_base + (uint32_t)(c & 1) * S2_STAGE;
        if (c + 1 < NCH2) {
            load_chunk(c + 1, smem_base + (uint32_t)((c + 1) & 1) * S2_STAGE);
            asm volatile("cp.async.wait_group 1;" ::: "memory");
        } else {
            asm volatile("cp.async.wait_group 0;" ::: "memory");
        }
        __syncthreads();

        #pragma unroll
        for (int ks = 0; ks < 4; ++ks) {
            const uint32_t gA = ((uint32_t)(ks * 2) + aG) ^ lx;
            const uint32_t bRow = (uint32_t)(ks * 16) * 512u + bRowOff;

            uint32_t ah[16], bh[8];
            #pragma unroll
            for (int ma = 0; ma < 4; ++ma) {
                uint32_t ad = sb + S2_A + aRowOff + (uint32_t)(ma * 16 * 128) + (gA << 4);
                LDSM_X4(ah[4*ma+0], ah[4*ma+1], ah[4*ma+2], ah[4*ma+3], ad);
            }
            #pragma unroll
            for (int nb = 0; nb < 2; ++nb) {
                uint32_t gB = (bGbase + (uint32_t)(nb * 2)) ^ lx;
                uint32_t bd = sb + S2_B + bRow + (gB << 4);
                LDSM_X4_T(bh[4*nb+0], bh[4*nb+1], bh[4*nb+2], bh[4*nb+3], bd);
            }
            #pragma unroll
            for (int ma = 0; ma < 4; ++ma)
                #pragma unroll
                for (int na = 0; na < 4; ++na)
                    MMA_F16(acc[ma][na], &ah[4*ma], bh[2*na], bh[2*na+1]);
        }
        __syncthreads();
    }

    // epilogue: bias + fp32 store into F (rows<128) or Z (rows>=128)
    const int g  = lane >> 2;
    const int tc = lane & 3;
    #pragma unroll
    for (int ma = 0; ma < 4; ++ma) {
        const int r0 = m0 + ma * 16 + g;
        const int r1 = r0 + 8;
        const float bb0 = bias[r0];
        const float bb1 = bias[r1];
        float* p0 = (r0 < L_D)
            ? Fout + ((size_t)b * L_D + r0) * HW
            : Zout + ((size_t)b * (M_CL + 1) + (r0 - L_D)) * HW;
        float* p1 = (r1 < L_D)
            ? Fout + ((size_t)b * L_D + r1) * HW
            : Zout + ((size_t)b * (M_CL + 1) + (r1 - L_D)) * HW;
        p0 += n0 + wn * 32 + tc * 2;
        p1 += n0 + wn * 32 + tc * 2;
        #pragma unroll
        for (int na = 0; na < 4; ++na) {
            float2 v0, v1;
            v0.x = acc[ma][na][0] + bb0;
            v0.y = acc[ma][na][1] + bb0;
            v1.x = acc[ma][na][2] + bb1;
            v1.y = acc[ma][na][3] + bb1;
            *reinterpret_cast<float2*>(p0 + na * 8) = v0;
            *reinterpret_cast<float2*>(p1 + na * 8) = v1;
        }
    }
}

// ---------------------------------------------------------------------------
// Fused token MLP: tk = relu(t @ W1^T + b1) @ W2^T + b2. Block per batch.
// ---------------------------------------------------------------------------
__global__ __launch_bounds__(256)
void token_kernel(const float* __restrict__ t,
                  const float* __restrict__ w1, const float* __restrict__ b1,
                  const float* __restrict__ w2, const float* __restrict__ b2)
{
    __shared__ float ts[C_SZ];
    __shared__ float hs[HID];
    const int b = blockIdx.x;
    for (int c = threadIdx.x; c < C_SZ; c += 256) ts[c] = t[(size_t)b * C_SZ + c];
    __syncthreads();
    const int wid = threadIdx.x >> 5, lane = threadIdx.x & 31;
    for (int o = wid; o < HID; o += 8) {
        const float* wr = w1 + (size_t)o * C_SZ;
        float s = 0.f;
        for (int c = lane; c < C_SZ; c += 32) s = fmaf(ts[c], wr[c], s);
        #pragma unroll
        for (int off = 16; off; off >>= 1) s += __shfl_xor_sync(0xFFFFFFFFu, s, off);
        if (lane == 0) hs[o] = fmaxf(s + b1[o], 0.f);
    }
    __syncthreads();
    for (int o = wid; o < G_D; o += 8) {
        const float* wr = w2 + (size_t)o * HID;
        float s = 0.f;
        for (int c = lane; c < HID; c += 32) s = fmaf(hs[c], wr[c], s);
        #pragma unroll
        for (int off = 16; off; off >>= 1) s += __shfl_xor_sync(0xFFFFFFFFu, s, off);
        if (lane == 0) g_TK[(size_t)b * G_D + o] = s + b2[o];
    }
}

// ---------------------------------------------------------------------------
// Sinkhorn (log-space), 1024 threads/block, one block per batch.
// ---------------------------------------------------------------------------
__global__ __launch_bounds__(1024)
void sinkhorn_kernel(const float* __restrict__ alpha_p)
{
    const int b = blockIdx.x;
    float* Zb = g_Z + (size_t)b * (M_CL + 1) * HW;

    __shared__ float u[M_CL + 1];
    __shared__ float wsum[M_CL + 1][33];

    const int j = threadIdx.x;
    const int lane = j & 31, warp = j >> 5;
    const float alpha = *alpha_p;
    const float norm = -logf((float)(M_CL + HW));
    const float log_mu_last = logf((float)(HW - M_CL)) + norm;

    float v = 0.f;

    for (int it = 0; it < 3; ++it) {
        #pragma unroll 4
        for (int i = 0; i <= M_CL; ++i) {
            float z = ((i < M_CL) ? Zb[(size_t)i * HW + j] : alpha) + v;
            float e = __expf(z);
            #pragma unroll
            for (int off = 16; off; off >>= 1) e += __shfl_xor_sync(0xFFFFFFFFu, e, off);
            if (lane == 0) wsum[i][warp] = e;
        }
        __syncthreads();
        if (j <= M_CL) {
            float s = 0.f;
            #pragma unroll
            for (int w = 0; w < 32; ++w) s += wsum[j][w];
            u[j] = ((j < M_CL) ? norm : log_mu_last) - logf(s);
        }
        __syncthreads();

        float s = 0.f;
        #pragma unroll 8
        for (int i = 0; i < M_CL; ++i)
            s += __expf(Zb[(size_t)i * HW + j] + u[i]);
        s += __expf(alpha + u[M_CL]);
        v = norm - logf(s);
    }

    #pragma unroll 8
    for (int i = 0; i < M_CL; ++i)
        Zb[(size_t)i * HW + j] = __expf(Zb[(size_t)i * HW + j] + u[i] + v - norm);
}

// ---------------------------------------------------------------------------
// agg[b][l][m] = sum_n F[b][l][n] * P[b][m][n]; grid (4 l-quads, B)
// ---------------------------------------------------------------------------
__global__ __launch_bounds__(256)
void agg_kernel()
{
    const int b = blockIdx.y;
    const int l0 = blockIdx.x * 32;
    const float* Fb = g_F + (size_t)b * L_D * HW + (size_t)l0 * HW;
    const float* Pb = g_Z + (size_t)b * (M_CL + 1) * HW;
    float*       Cb = g_AGG + (size_t)b * L_D * M_CL + (size_t)l0 * M_CL;

    __shared__ float Fs[32][36];   // [k][l]
    __shared__ float Ps[32][68];   // [k][m]

    const int tid = threadIdx.x;
    const int tx = tid & 15, ty = tid >> 4;   // tx -> m (4 each), ty -> l (2 each)

    float acc[2][4];
    #pragma unroll
    for (int i = 0; i < 2; ++i)
        #pragma unroll
        for (int j = 0; j < 4; ++j) acc[i][j] = 0.f;

    for (int n0 = 0; n0 < HW; n0 += 32) {
        {   // F tile: 32 l x 32 k
            int l = tid >> 3, kq = (tid & 7) << 2;
            float4 fv = *reinterpret_cast<const float4*>(&Fb[(size_t)l * HW + n0 + kq]);
            Fs[kq + 0][l] = fv.x; Fs[kq + 1][l] = fv.y;
            Fs[kq + 2][l] = fv.z; Fs[kq + 3][l] = fv.w;
        }
        #pragma unroll
        for (int r = 0; r < 2; ++r) {   // P tile: 64 m x 32 k
            int id = tid + 256 * r;
            int m = id >> 3, kq = (id & 7) << 2;
            float4 pv = *reinterpret_cast<const float4*>(&Pb[(size_t)m * HW + n0 + kq]);
            Ps[kq + 0][m] = pv.x; Ps[kq + 1][m] = pv.y;
            Ps[kq + 2][m] = pv.z; Ps[kq + 3][m] = pv.w;
        }
        __syncthreads();

        #pragma unroll
        for (int k = 0; k < 32; ++k) {
            float rl[2], rm[4];
            #pragma unroll
            for (int i = 0; i < 2; ++i) rl[i] = Fs[k][ty * 2 + i];
            #pragma unroll
            for (int j = 0; j < 4; ++j) rm[j] = Ps[k][tx * 4 + j];
            #pragma unroll
            for (int i = 0; i < 2; ++i)
                #pragma unroll
                for (int j = 0; j < 4; ++j)
                    acc[i][j] = fmaf(rl[i], rm[j], acc[i][j]);
        }
        __syncthreads();
    }

    #pragma unroll
    for (int i = 0; i < 2; ++i)
        #pragma unroll
        for (int j = 0; j < 4; ++j)
            Cb[(size_t)(ty * 2 + i) * M_CL + tx * 4 + j] = acc[i][j];
}

// ---------------------------------------------------------------------------
// Finalize
// ---------------------------------------------------------------------------
__device__ __forceinline__ float block_sum256(float val, float* red)
{
    const int lane = threadIdx.x & 31, wid = threadIdx.x >> 5;
    #pragma unroll
    for (int off = 16; off; off >>= 1) val += __shfl_xor_sync(0xFFFFFFFFu, val, off);
    if (lane == 0) red[wid] = val;
    __syncthreads();
    float s = red[0] + red[1] + red[2] + red[3] + red[4] + red[5] + red[6] + red[7];
    __syncthreads();
    return s;
}

__global__ __launch_bounds__(256)
void finalize_kernel(float* __restrict__ out)
{
    const int b = blockIdx.x;
    const int tid = threadIdx.x;
    __shared__ float an[L_D * M_CL];
    __shared__ float tkn[G_D];
    __shared__ float cn[M_CL];
    __shared__ float red[8];

    const float* aggb = g_AGG + (size_t)b * L_D * M_CL;

    float tv = g_TK[(size_t)b * G_D + tid];
    float tk_ss = block_sum256(tv * tv, red);
    tkn[tid] = tv / fmaxf(sqrtf(tk_ss), EPSV);

    if (tid < M_CL) {
        float s = 0.f;
        for (int l = 0; l < L_D; ++l) {
            float a = aggb[(size_t)l * M_CL + tid];
            s = fmaf(a, a, s);
        }
        cn[tid] = fmaxf(sqrtf(s), EPSV);
    }
    __syncthreads();

    float gs = tkn[tid] * tkn[tid];
    for (int idx = tid; idx < L_D * M_CL; idx += 256) {
        float a = aggb[idx] / cn[idx & (M_CL - 1)];
        an[idx] = a;
        gs = fmaf(a, a, gs);
    }
    float total = block_sum256(gs, red);
    float scale = 1.f / fmaxf(sqrtf(total), EPSV);

    float* ob = out + (size_t)b * (G_D + L_D * M_CL);
    ob[tid] = tkn[tid] * scale;
    for (int idx = tid; idx < L_D * M_CL; idx += 256)
        ob[G_D + idx] = an[idx] * scale;
}

// ---------------------------------------------------------------------------
// Launch (fork-join side stream for weight converts + token MLP)
// ---------------------------------------------------------------------------
extern "C" void kernel_launch(void* const* d_in, const int* in_sizes, int n_in,
                              void* d_out, int out_size)
{
    const float* x      = (const float*)d_in[0];
    const float* t      = (const float*)d_in[1];
    const float* cf_w1  = (const float*)d_in[2];
    const float* cf_b1  = (const float*)d_in[3];
    const float* cf_w2  = (const float*)d_in[4];
    const float* cf_b2  = (const float*)d_in[5];
    const float* sc_w1  = (const float*)d_in[6];
    const float* sc_b1  = (const float*)d_in[7];
    const float* sc_w2  = (const float*)d_in[8];
    const float* sc_b2  = (const float*)d_in[9];
    const float* tk_w1  = (const float*)d_in[10];
    const float* tk_b1  = (const float*)d_in[11];
    const float* tk_w2  = (const float*)d_in[12];
    const float* tk_b2  = (const float*)d_in[13];
    const float* dust   = (const float*)d_in[14];

    float *F, *Z, *B1, *B2;
    __half *X, *W1, *W2, *H;
    cudaGetSymbolAddress((void**)&F,  g_F);
    cudaGetSymbolAddress((void**)&Z,  g_Z);
    cudaGetSymbolAddress((void**)&B1, g_B1c);
    cudaGetSymbolAddress((void**)&B2, g_B2c);
    cudaGetSymbolAddress((void**)&X,  g_X);
    cudaGetSymbolAddress((void**)&W1, g_W1);
    cudaGetSymbolAddress((void**)&W2, g_W2);
    cudaGetSymbolAddress((void**)&H,  g_H);

    // One-time setup (host-side objects only; created on the un-captured
    // correctness call, reused thereafter).
    static cudaStream_t s_side = nullptr;
    static cudaEvent_t ev_fork = nullptr, ev_w = nullptr, ev_tok = nullptr;
    if (!s_side) {
        cudaStreamCreateWithFlags(&s_side, cudaStreamNonBlocking);
        cudaEventCreateWithFlags(&ev_fork, cudaEventDisableTiming);
        cudaEventCreateWithFlags(&ev_w,    cudaEventDisableTiming);
        cudaEventCreateWithFlags(&ev_tok,  cudaEventDisableTiming);
        cudaFuncSetAttribute(mma_gemm1_kernel,
                             cudaFuncAttributeMaxDynamicSharedMemorySize, GEMM1_SMEM);
        cudaFuncSetAttribute(mma_gemm2_kernel,
                             cudaFuncAttributeMaxDynamicSharedMemorySize, GEMM2_SMEM);
    }

    // fork: side stream handles weight converts + token MLP
    cudaEventRecord(ev_fork, 0);
    cudaStreamWaitEvent(s_side, ev_fork, 0);

    convert_w_kernel<<<(1024 * C_SZ + 255) / 256, 256, 0, s_side>>>(
        cf_w1, sc_w1, cf_b1, sc_b1);
    convert_w2_kernel<<<(192 * HID + 255) / 256, 256, 0, s_side>>>(
        cf_w2, sc_w2, cf_b2, sc_b2);
    cudaEventRecord(ev_w, s_side);
    token_kernel<<<B_SZ, 256, 0, s_side>>>(t, tk_w1, tk_b1, tk_w2, tk_b2);
    cudaEventRecord(ev_tok, s_side);

    // main stream: x cast runs concurrently with the side stream
    convert_x_kernel<<<(int)(((size_t)B_SZ * C_SZ * HW / 8 + 255) / 256), 256>>>(
        (const float4*)x);

    cudaStreamWaitEvent(0, ev_w, 0);   // gemm1 needs W1/B1 (and W2/B2 for gemm2)

    // GEMM1: hidden layers (cf + sc fused), fp16 HMMA single product
    mma_gemm1_kernel<<<dim3(HW / NT, 1024 / MT, B_SZ), 256, GEMM1_SMEM>>>(
        W1, X, B1, H);

    // GEMM2: F and Z from H, fp16 HMMA single product
    mma_gemm2_kernel<<<dim3(HW / NT2, 3, B_SZ), 256, GEMM2_SMEM>>>(
        W2, H, B2, F, Z);

    // Sinkhorn + aggregation
    sinkhorn_kernel<<<B_SZ, 1024>>>(dust);
    agg_kernel<<<dim3(4, B_SZ), 256>>>();

    // join: finalize needs g_TK from the side stream
    cudaStreamWaitEvent(0, ev_tok, 0);
    finalize_kernel<<<B_SZ, 256>>>((float*)d_out);
}

// round 9
// speedup vs baseline: 7.1414x; 1.0105x over previous
#include <cuda_runtime.h>
#include <cuda_fp16.h>
#include <math.h>
#include <stdint.h>

// ---------------------------------------------------------------------------
// SALAD pipeline. Round 9: batch-halves pipelining across two streams.
//   chain(h) = convert_x(h) -> gemm1(h) -> gemm2(h) -> sinkhorn(h) -> agg(h)
//              -> finalize(h);  h=0 on stream 0, h=1 on side stream.
//   convert_x(h1) overlaps gemm1(h0); h0 tail overlaps gemm1(h1).
// Shapes: B=32, C=1536, HW=1024, hidden=512, L=128, M=64 (+dustbin), G=256.
// ---------------------------------------------------------------------------

#define B_SZ 32
#define BH   16                      // batches per chunk (2 chunks)
#define C_SZ 1536
#define HW   1024
#define HID  512
#define L_D  128
#define M_CL 64
#define G_D  256
#define EPSV 1e-12f

// Scratch (device globals; allocation-free rule)
__device__ __align__(256) __half g_H[(size_t)B_SZ * 1024 * HW];      // H [b][k][n] fp16
__device__ __align__(256) float g_F[(size_t)B_SZ * L_D * HW];        // [B][128][HW]
__device__ __align__(256) float g_Z[(size_t)B_SZ * (M_CL + 1) * HW]; // [B][65][HW]
__device__ __align__(256) float g_AGG[(size_t)B_SZ * L_D * M_CL];
__device__ __align__(256) float g_TK[(size_t)B_SZ * G_D];

// fp16 operands
__device__ __align__(256) __half g_X[(size_t)B_SZ * C_SZ * HW]; // x [b][c][n] fp16
__device__ __align__(256) __half g_W1[(size_t)1024 * C_SZ];     // [cf_w1; sc_w1]
__device__ __align__(256) __half g_W2[(size_t)192 * HID];       // [cf_w2; sc_w2]
__device__ __align__(256) float g_B1c[1024];                    // [cf_b1; sc_b1]
__device__ __align__(256) float g_B2c[192];                     // [cf_b2; sc_b2]

// ---------------------------------------------------------------------------
// PTX helpers (family-common only)
// ---------------------------------------------------------------------------
__device__ __forceinline__ uint32_t smem_u32(const void* p) {
    uint32_t a;
    asm("{ .reg .u64 t; cvta.to.shared.u64 t, %1; cvt.u32.u64 %0, t; }"
        : "=r"(a) : "l"(p));
    return a;
}

__device__ __forceinline__ void cp16(uint32_t saddr, const void* gaddr) {
    asm volatile("cp.async.cg.shared.global [%0], [%1], 16;"
                 :: "r"(saddr), "l"(gaddr) : "memory");
}

#define LDSM_X4(r0, r1, r2, r3, addr) \
    asm volatile("ldmatrix.sync.aligned.m8n8.x4.shared.b16 {%0,%1,%2,%3}, [%4];" \
                 : "=r"(r0), "=r"(r1), "=r"(r2), "=r"(r3) : "r"(addr))

#define LDSM_X4_T(r0, r1, r2, r3, addr) \
    asm volatile("ldmatrix.sync.aligned.m8n8.x4.trans.shared.b16 {%0,%1,%2,%3}, [%4];" \
                 : "=r"(r0), "=r"(r1), "=r"(r2), "=r"(r3) : "r"(addr))

#define MMA_F16(d, a, b0, b1) \
    asm volatile("mma.sync.aligned.m16n8k16.row.col.f32.f16.f16.f32 " \
                 "{%0,%1,%2,%3}, {%4,%5,%6,%7}, {%8,%9}, {%0,%1,%2,%3};" \
                 : "+f"((d)[0]), "+f"((d)[1]), "+f"((d)[2]), "+f"((d)[3]) \
                 : "r"((a)[0]), "r"((a)[1]), "r"((a)[2]), "r"((a)[3]), \
                   "r"(b0), "r"(b1))

// ---------------------------------------------------------------------------
// Conversions: fp32 -> fp16
// ---------------------------------------------------------------------------
__global__ __launch_bounds__(256)
void convert_w_kernel(const float* __restrict__ cf_w1, const float* __restrict__ sc_w1,
                      const float* __restrict__ cf_b1, const float* __restrict__ sc_b1)
{
    size_t idx = (size_t)blockIdx.x * 256 + threadIdx.x;
    const size_t total = (size_t)1024 * C_SZ;
    if (idx < total) {
        size_t row = idx / C_SZ;
        float v = (row < HID) ? cf_w1[idx] : sc_w1[idx - (size_t)HID * C_SZ];
        g_W1[idx] = __float2half_rn(v);
    }
    if (idx < 1024)
        g_B1c[idx] = (idx < HID) ? cf_b1[idx] : sc_b1[idx - HID];
}

__global__ __launch_bounds__(256)
void convert_w2_kernel(const float* __restrict__ cf_w2, const float* __restrict__ sc_w2,
                       const float* __restrict__ cf_b2, const float* __restrict__ sc_b2)
{
    size_t idx = (size_t)blockIdx.x * 256 + threadIdx.x;
    const size_t total = (size_t)192 * HID;
    if (idx < total) {
        size_t row = idx / HID;
        float v = (row < L_D) ? cf_w2[idx] : sc_w2[idx - (size_t)L_D * HID];
        g_W2[idx] = __float2half_rn(v);
    }
    if (idx < 192)
        g_B2c[idx] = (idx < L_D) ? cf_b2[idx] : sc_b2[idx - L_D];
}

// Streaming cast x fp32 -> fp16 for one batch chunk (8 elems/thread)
__global__ __launch_bounds__(256)
void convert_x_kernel(const float4* __restrict__ x, size_t elem0)
{
    const size_t i = elem0 / 8 + (size_t)blockIdx.x * 256 + threadIdx.x;
    float4 a = x[2 * i];
    float4 b = x[2 * i + 1];
    __half2 h0 = __floats2half2_rn(a.x, a.y);
    __half2 h1 = __floats2half2_rn(a.z, a.w);
    __half2 h2 = __floats2half2_rn(b.x, b.y);
    __half2 h3 = __floats2half2_rn(b.z, b.w);
    uint4 o;
    o.x = *reinterpret_cast<uint32_t*>(&h0);
    o.y = *reinterpret_cast<uint32_t*>(&h1);
    o.z = *reinterpret_cast<uint32_t*>(&h2);
    o.w = *reinterpret_cast<uint32_t*>(&h3);
    reinterpret_cast<uint4*>(g_X)[i] = o;
}

// ---------------------------------------------------------------------------
// GEMM1 (fp16 HMMA, single product): H[b] = relu(W1 @ X[b] + b1) -> fp16
//   CTA tile 128(m) x 128(n), K-chunk 64, 3-stage cp.async, 2 CTAs/SM.
// ---------------------------------------------------------------------------
#define MT 128
#define NT 128
#define KC 64
#define NCHUNK (C_SZ / KC)            // 24
#define OFF_A 0
#define OFF_B (16 * 1024)
#define STAGE_BYTES (32 * 1024)
#define GEMM1_SMEM (3 * STAGE_BYTES)  // 96 KB -> 2 CTAs/SM

__global__ __launch_bounds__(256, 2)
void mma_gemm1_kernel(const __half* __restrict__ W1, const __half* __restrict__ X,
                      const float* __restrict__ bias, __half* __restrict__ H, int b0)
{
    extern __shared__ char dsmem[];
    const uint32_t smem_base = smem_u32(dsmem);

    const int tid = threadIdx.x;
    const int b  = b0 + blockIdx.z;
    const int n0 = blockIdx.x * NT;
    const int m0 = blockIdx.y * MT;

    const __half* Ag = W1 + (size_t)m0 * C_SZ;
    const __half* Bg = X + (size_t)b * C_SZ * HW + n0;

    const int lane = tid & 31, warp = tid >> 5;
    const int wm = warp >> 2, wn = warp & 3;   // warp tile: rows wm*64, cols wn*32

    const uint32_t lx = (uint32_t)(lane & 7);
    const uint32_t aG = (uint32_t)(lane >> 4);
    const uint32_t aRowOff = (uint32_t)(wm * 64 + (lane & 15)) * 128u;
    const uint32_t bRowOff = (uint32_t)(lane & 15) * 256u;
    const uint32_t bGbase = (uint32_t)(wn * 4) + (uint32_t)(lane >> 4);

    float acc[4][4][4];
    #pragma unroll
    for (int i = 0; i < 4; ++i)
        #pragma unroll
        for (int j = 0; j < 4; ++j)
            #pragma unroll
            for (int q = 0; q < 4; ++q) acc[i][j][q] = 0.f;

    auto load_chunk = [&](int c) {
        const uint32_t sb = smem_base + (uint32_t)(c % 3) * STAGE_BYTES;
        const size_t kk = (size_t)c * KC;
        #pragma unroll
        for (int i = 0; i < 4; ++i) {
            int idx = tid + 256 * i;
            int r = idx >> 3, g = idx & 7;
            uint32_t so = (uint32_t)r * 128u + (uint32_t)((g ^ (r & 7)) << 4);
            cp16(sb + OFF_A + so, (const char*)(Ag + (size_t)r * C_SZ + kk) + g * 16);
        }
        #pragma unroll
        for (int i = 0; i < 4; ++i) {
            int idx = tid + 256 * i;
            int r = idx >> 4, g = idx & 15;
            uint32_t so = (uint32_t)r * 256u + (uint32_t)((g ^ (r & 7)) << 4);
            cp16(sb + OFF_B + so, (const char*)(Bg + (kk + r) * HW) + g * 16);
        }
        asm volatile("cp.async.commit_group;" ::: "memory");
    };

    load_chunk(0);
    load_chunk(1);

    for (int c = 0; c < NCHUNK; ++c) {
        if (c + 2 < NCHUNK) {
            load_chunk(c + 2);
            asm volatile("cp.async.wait_group 2;" ::: "memory");
        } else if (c + 1 < NCHUNK) {
            asm volatile("cp.async.wait_group 1;" ::: "memory");
        } else {
            asm volatile("cp.async.wait_group 0;" ::: "memory");
        }
        __syncthreads();

        const uint32_t sb = smem_base + (uint32_t)(c % 3) * STAGE_BYTES;

        #pragma unroll
        for (int ks = 0; ks < 4; ++ks) {
            const uint32_t gA = ((uint32_t)(ks * 2) + aG) ^ lx;
            const uint32_t bRow = (uint32_t)(ks * 16) * 256u + bRowOff;

            uint32_t ah[16], bh[8];
            #pragma unroll
            for (int ma = 0; ma < 4; ++ma) {
                uint32_t ad = sb + OFF_A + aRowOff + (uint32_t)(ma * 16 * 128) + (gA << 4);
                LDSM_X4(ah[4*ma+0], ah[4*ma+1], ah[4*ma+2], ah[4*ma+3], ad);
            }
            #pragma unroll
            for (int nb = 0; nb < 2; ++nb) {
                uint32_t gB = (bGbase + (uint32_t)(nb * 2)) ^ lx;
                uint32_t bd = sb + OFF_B + bRow + (gB << 4);
                LDSM_X4_T(bh[4*nb+0], bh[4*nb+1], bh[4*nb+2], bh[4*nb+3], bd);
            }
            #pragma unroll
            for (int ma = 0; ma < 4; ++ma)
                #pragma unroll
                for (int na = 0; na < 4; ++na)
                    MMA_F16(acc[ma][na], &ah[4*ma], bh[2*na], bh[2*na+1]);
        }
        __syncthreads();
    }

    // epilogue: bias + relu -> fp16 store, layout [b][k=row][n]
    const int g  = lane >> 2;
    const int tc = lane & 3;
    #pragma unroll
    for (int ma = 0; ma < 4; ++ma) {
        const int r0 = m0 + wm * 64 + ma * 16 + g;
        const int r1 = r0 + 8;
        const float bb0 = bias[r0];
        const float bb1 = bias[r1];
        const size_t base0 = ((size_t)b * 1024 + r0) * HW + n0 + wn * 32 + tc * 2;
        const size_t base1 = ((size_t)b * 1024 + r1) * HW + n0 + wn * 32 + tc * 2;
        #pragma unroll
        for (int na = 0; na < 4; ++na) {
            float v00 = fmaxf(acc[ma][na][0] + bb0, 0.f);
            float v01 = fmaxf(acc[ma][na][1] + bb0, 0.f);
            float v10 = fmaxf(acc[ma][na][2] + bb1, 0.f);
            float v11 = fmaxf(acc[ma][na][3] + bb1, 0.f);
            *reinterpret_cast<__half2*>(H + base0 + na * 8) = __floats2half2_rn(v00, v01);
            *reinterpret_cast<__half2*>(H + base1 + na * 8) = __floats2half2_rn(v10, v11);
        }
    }
}

// ---------------------------------------------------------------------------
// GEMM2 (fp16 HMMA, single product): [F; Z] = W2 @ H + b2
// ---------------------------------------------------------------------------
#define NT2 256
#define NCH2 (HID / KC)               // 8
#define S2_A 0
#define S2_B (8 * 1024)
#define S2_STAGE (40 * 1024)
#define GEMM2_SMEM (2 * S2_STAGE)     // 80 KB

__global__ __launch_bounds__(256, 2)
void mma_gemm2_kernel(const __half* __restrict__ W2, const __half* __restrict__ H,
                      const float* __restrict__ bias,
                      float* __restrict__ Fout, float* __restrict__ Zout, int b0)
{
    extern __shared__ char dsmem[];
    const uint32_t smem_base = smem_u32(dsmem);

    const int tid = threadIdx.x;
    const int b  = b0 + blockIdx.z;
    const int n0 = blockIdx.x * NT2;
    const int m0 = blockIdx.y * 64;                // 0, 64, 128
    const int koff = (m0 == 128) ? 512 : 0;        // sc hidden rows

    const __half* Ag = W2 + (size_t)m0 * HID;
    const __half* Bg = H + ((size_t)b * 1024 + koff) * HW + n0;

    const int lane = tid & 31, wn = tid >> 5;      // 8 warps along n

    float acc[4][4][4];
    #pragma unroll
    for (int i = 0; i < 4; ++i)
        #pragma unroll
        for (int j = 0; j < 4; ++j)
            #pragma unroll
            for (int q = 0; q < 4; ++q) acc[i][j][q] = 0.f;

    auto load_chunk = [&](int c, uint32_t sb) {
        const int kk = c * KC;
        #pragma unroll
        for (int i = 0; i < 2; ++i) {
            int idx = tid + 256 * i;
            int r = idx >> 3, g = idx & 7;
            uint32_t so = (uint32_t)r * 128u + (uint32_t)((g ^ (r & 7)) << 4);
            cp16(sb + S2_A + so, (const char*)(Ag + (size_t)r * HID + kk) + g * 16);
        }
        #pragma unroll
        for (int i = 0; i < 8; ++i) {
            int idx = tid + 256 * i;
            int r = idx >> 5, g = idx & 31;
            uint32_t so = (uint32_t)r * 512u + (uint32_t)((g ^ (r & 7)) << 4);
            cp16(sb + S2_B + so, (const char*)(Bg + (size_t)(kk + r) * HW) + g * 16);
        }
        asm volatile("cp.async.commit_group;" ::: "memory");
    };

    load_chunk(0, smem_base);

    const uint32_t lx = (uint32_t)(lane & 7);
    const uint32_t aG = (uint32_t)(lane >> 4);
    const uint32_t aRowOff = (uint32_t)(lane & 15) * 128u;
    const uint32_t bRowOff = (uint32_t)(lane & 15) * 512u;
    const uint32_t bGbase = (uint32_t)(wn * 4) + (uint32_t)(lane >> 4);

    for (int c = 0; c < NCH2; ++c) {
        const uint32_t sb = smem_base + (uint32_t)(c & 1) * S2_STAGE;
        if (c + 1 < NCH2) {
            load_chunk(c + 1, smem_base + (uint32_t)((c + 1) & 1) * S2_STAGE);
            asm volatile("cp.async.wait_group 1;" ::: "memory");
        } else {
            asm volatile("cp.async.wait_group 0;" ::: "memory");
        }
        __syncthreads();

        #pragma unroll
        for (int ks = 0; ks < 4; ++ks) {
            const uint32_t gA = ((uint32_t)(ks * 2) + aG) ^ lx;
            const uint32_t bRow = (uint32_t)(ks * 16) * 512u + bRowOff;

            uint32_t ah[16], bh[8];
            #pragma unroll
            for (int ma = 0; ma < 4; ++ma) {
                uint32_t ad = sb + S2_A + aRowOff + (uint32_t)(ma * 16 * 128) + (gA << 4);
                LDSM_X4(ah[4*ma+0], ah[4*ma+1], ah[4*ma+2], ah[4*ma+3], ad);
            }
            #pragma unroll
            for (int nb = 0; nb < 2; ++nb) {
                uint32_t gB = (bGbase + (uint32_t)(nb * 2)) ^ lx;
                uint32_t bd = sb + S2_B + bRow + (gB << 4);
                LDSM_X4_T(bh[4*nb+0], bh[4*nb+1], bh[4*nb+2], bh[4*nb+3], bd);
            }
            #pragma unroll
            for (int ma = 0; ma < 4; ++ma)
                #pragma unroll
                for (int na = 0; na < 4; ++na)
                    MMA_F16(acc[ma][na], &ah[4*ma], bh[2*na], bh[2*na+1]);
        }
        __syncthreads();
    }

    // epilogue: bias + fp32 store into F (rows<128) or Z (rows>=128)
    const int g  = lane >> 2;
    const int tc = lane & 3;
    #pragma unroll
    for (int ma = 0; ma < 4; ++ma) {
        const int r0 = m0 + ma * 16 + g;
        const int r1 = r0 + 8;
        const float bb0 = bias[r0];
        const float bb1 = bias[r1];
        float* p0 = (r0 < L_D)
            ? Fout + ((size_t)b * L_D + r0) * HW
            : Zout + ((size_t)b * (M_CL + 1) + (r0 - L_D)) * HW;
        float* p1 = (r1 < L_D)
            ? Fout + ((size_t)b * L_D + r1) * HW
            : Zout + ((size_t)b * (M_CL + 1) + (r1 - L_D)) * HW;
        p0 += n0 + wn * 32 + tc * 2;
        p1 += n0 + wn * 32 + tc * 2;
        #pragma unroll
        for (int na = 0; na < 4; ++na) {
            float2 v0, v1;
            v0.x = acc[ma][na][0] + bb0;
            v0.y = acc[ma][na][1] + bb0;
            v1.x = acc[ma][na][2] + bb1;
            v1.y = acc[ma][na][3] + bb1;
            *reinterpret_cast<float2*>(p0 + na * 8) = v0;
            *reinterpret_cast<float2*>(p1 + na * 8) = v1;
        }
    }
}

// ---------------------------------------------------------------------------
// Fused token MLP: tk = relu(t @ W1^T + b1) @ W2^T + b2. Block per batch.
// ---------------------------------------------------------------------------
__global__ __launch_bounds__(256)
void token_kernel(const float* __restrict__ t,
                  const float* __restrict__ w1, const float* __restrict__ b1,
                  const float* __restrict__ w2, const float* __restrict__ b2)
{
    __shared__ float ts[C_SZ];
    __shared__ float hs[HID];
    const int b = blockIdx.x;
    for (int c = threadIdx.x; c < C_SZ; c += 256) ts[c] = t[(size_t)b * C_SZ + c];
    __syncthreads();
    const int wid = threadIdx.x >> 5, lane = threadIdx.x & 31;
    for (int o = wid; o < HID; o += 8) {
        const float* wr = w1 + (size_t)o * C_SZ;
        float s = 0.f;
        for (int c = lane; c < C_SZ; c += 32) s = fmaf(ts[c], wr[c], s);
        #pragma unroll
        for (int off = 16; off; off >>= 1) s += __shfl_xor_sync(0xFFFFFFFFu, s, off);
        if (lane == 0) hs[o] = fmaxf(s + b1[o], 0.f);
    }
    __syncthreads();
    for (int o = wid; o < G_D; o += 8) {
        const float* wr = w2 + (size_t)o * HID;
        float s = 0.f;
        for (int c = lane; c < HID; c += 32) s = fmaf(hs[c], wr[c], s);
        #pragma unroll
        for (int off = 16; off; off >>= 1) s += __shfl_xor_sync(0xFFFFFFFFu, s, off);
        if (lane == 0) g_TK[(size_t)b * G_D + o] = s + b2[o];
    }
}

// ---------------------------------------------------------------------------
// Sinkhorn (log-space), 1024 threads/block, one block per batch.
// ---------------------------------------------------------------------------
__global__ __launch_bounds__(1024)
void sinkhorn_kernel(const float* __restrict__ alpha_p, int b0)
{
    const int b = b0 + blockIdx.x;
    float* Zb = g_Z + (size_t)b * (M_CL + 1) * HW;

    __shared__ float u[M_CL + 1];
    __shared__ float wsum[M_CL + 1][33];

    const int j = threadIdx.x;
    const int lane = j & 31, warp = j >> 5;
    const float alpha = *alpha_p;
    const float norm = -logf((float)(M_CL + HW));
    const float log_mu_last = logf((float)(HW - M_CL)) + norm;

    float v = 0.f;

    for (int it = 0; it < 3; ++it) {
        #pragma unroll 4
        for (int i = 0; i <= M_CL; ++i) {
            float z = ((i < M_CL) ? Zb[(size_t)i * HW + j] : alpha) + v;
            float e = __expf(z);
            #pragma unroll
            for (int off = 16; off; off >>= 1) e += __shfl_xor_sync(0xFFFFFFFFu, e, off);
            if (lane == 0) wsum[i][warp] = e;
        }
        __syncthreads();
        if (j <= M_CL) {
            float s = 0.f;
            #pragma unroll
            for (int w = 0; w < 32; ++w) s += wsum[j][w];
            u[j] = ((j < M_CL) ? norm : log_mu_last) - logf(s);
        }
        __syncthreads();

        float s = 0.f;
        #pragma unroll 8
        for (int i = 0; i < M_CL; ++i)
            s += __expf(Zb[(size_t)i * HW + j] + u[i]);
        s += __expf(alpha + u[M_CL]);
        v = norm - logf(s);
    }

    #pragma unroll 8
    for (int i = 0; i < M_CL; ++i)
        Zb[(size_t)i * HW + j] = __expf(Zb[(size_t)i * HW + j] + u[i] + v - norm);
}

// ---------------------------------------------------------------------------
// agg[b][l][m] = sum_n F[b][l][n] * P[b][m][n]; grid (4 l-quads, BH)
// ---------------------------------------------------------------------------
__global__ __launch_bounds__(256)
void agg_kernel(int b0)
{
    const int b = b0 + blockIdx.y;
    const int l0 = blockIdx.x * 32;
    const float* Fb = g_F + (size_t)b * L_D * HW + (size_t)l0 * HW;
    const float* Pb = g_Z + (size_t)b * (M_CL + 1) * HW;
    float*       Cb = g_AGG + (size_t)b * L_D * M_CL + (size_t)l0 * M_CL;

    __shared__ float Fs[32][36];   // [k][l]
    __shared__ float Ps[32][68];   // [k][m]

    const int tid = threadIdx.x;
    const int tx = tid & 15, ty = tid >> 4;

    float acc[2][4];
    #pragma unroll
    for (int i = 0; i < 2; ++i)
        #pragma unroll
        for (int j = 0; j < 4; ++j) acc[i][j] = 0.f;

    for (int n0 = 0; n0 < HW; n0 += 32) {
        {
            int l = tid >> 3, kq = (tid & 7) << 2;
            float4 fv = *reinterpret_cast<const float4*>(&Fb[(size_t)l * HW + n0 + kq]);
            Fs[kq + 0][l] = fv.x; Fs[kq + 1][l] = fv.y;
            Fs[kq + 2][l] = fv.z; Fs[kq + 3][l] = fv.w;
        }
        #pragma unroll
        for (int r = 0; r < 2; ++r) {
            int id = tid + 256 * r;
            int m = id >> 3, kq = (id & 7) << 2;
            float4 pv = *reinterpret_cast<const float4*>(&Pb[(size_t)m * HW + n0 + kq]);
            Ps[kq + 0][m] = pv.x; Ps[kq + 1][m] = pv.y;
            Ps[kq + 2][m] = pv.z; Ps[kq + 3][m] = pv.w;
        }
        __syncthreads();

        #pragma unroll
        for (int k = 0; k < 32; ++k) {
            float rl[2], rm[4];
            #pragma unroll
            for (int i = 0; i < 2; ++i) rl[i] = Fs[k][ty * 2 + i];
            #pragma unroll
            for (int j = 0; j < 4; ++j) rm[j] = Ps[k][tx * 4 + j];
            #pragma unroll
            for (int i = 0; i < 2; ++i)
                #pragma unroll
                for (int j = 0; j < 4; ++j)
                    acc[i][j] = fmaf(rl[i], rm[j], acc[i][j]);
        }
        __syncthreads();
    }

    #pragma unroll
    for (int i = 0; i < 2; ++i)
        #pragma unroll
        for (int j = 0; j < 4; ++j)
            Cb[(size_t)(ty * 2 + i) * M_CL + tx * 4 + j] = acc[i][j];
}

// ---------------------------------------------------------------------------
// Finalize
// ---------------------------------------------------------------------------
__device__ __forceinline__ float block_sum256(float val, float* red)
{
    const int lane = threadIdx.x & 31, wid = threadIdx.x >> 5;
    #pragma unroll
    for (int off = 16; off; off >>= 1) val += __shfl_xor_sync(0xFFFFFFFFu, val, off);
    if (lane == 0) red[wid] = val;
    __syncthreads();
    float s = red[0] + red[1] + red[2] + red[3] + red[4] + red[5] + red[6] + red[7];
    __syncthreads();
    return s;
}

__global__ __launch_bounds__(256)
void finalize_kernel(float* __restrict__ out, int b0)
{
    const int b = b0 + blockIdx.x;
    const int tid = threadIdx.x;
    __shared__ float an[L_D * M_CL];
    __shared__ float tkn[G_D];
    __shared__ float cn[M_CL];
    __shared__ float red[8];

    const float* aggb = g_AGG + (size_t)b * L_D * M_CL;

    float tv = g_TK[(size_t)b * G_D + tid];
    float tk_ss = block_sum256(tv * tv, red);
    tkn[tid] = tv / fmaxf(sqrtf(tk_ss), EPSV);

    if (tid < M_CL) {
        float s = 0.f;
        for (int l = 0; l < L_D; ++l) {
            float a = aggb[(size_t)l * M_CL + tid];
            s = fmaf(a, a, s);
        }
        cn[tid] = fmaxf(sqrtf(s), EPSV);
    }
    __syncthreads();

    float gs = tkn[tid] * tkn[tid];
    for (int idx = tid; idx < L_D * M_CL; idx += 256) {
        float a = aggb[idx] / cn[idx & (M_CL - 1)];
        an[idx] = a;
        gs = fmaf(a, a, gs);
    }
    float total = block_sum256(gs, red);
    float scale = 1.f / fmaxf(sqrtf(total), EPSV);

    float* ob = out + (size_t)b * (G_D + L_D * M_CL);
    ob[tid] = tkn[tid] * scale;
    for (int idx = tid; idx < L_D * M_CL; idx += 256)
        ob[G_D + idx] = an[idx] * scale;
}

// ---------------------------------------------------------------------------
// Launch: two batch-half chains on two streams + weight/token side stream
// ---------------------------------------------------------------------------
extern "C" void kernel_launch(void* const* d_in, const int* in_sizes, int n_in,
                              void* d_out, int out_size)
{
    const float* x      = (const float*)d_in[0];
    const float* t      = (const float*)d_in[1];
    const float* cf_w1  = (const float*)d_in[2];
    const float* cf_b1  = (const float*)d_in[3];
    const float* cf_w2  = (const float*)d_in[4];
    const float* cf_b2  = (const float*)d_in[5];
    const float* sc_w1  = (const float*)d_in[6];
    const float* sc_b1  = (const float*)d_in[7];
    const float* sc_w2  = (const float*)d_in[8];
    const float* sc_b2  = (const float*)d_in[9];
    const float* tk_w1  = (const float*)d_in[10];
    const float* tk_b1  = (const float*)d_in[11];
    const float* tk_w2  = (const float*)d_in[12];
    const float* tk_b2  = (const float*)d_in[13];
    const float* dust   = (const float*)d_in[14];

    float *F, *Z, *B1, *B2;
    __half *X, *W1, *W2, *H;
    cudaGetSymbolAddress((void**)&F,  g_F);
    cudaGetSymbolAddress((void**)&Z,  g_Z);
    cudaGetSymbolAddress((void**)&B1, g_B1c);
    cudaGetSymbolAddress((void**)&B2, g_B2c);
    cudaGetSymbolAddress((void**)&X,  g_X);
    cudaGetSymbolAddress((void**)&W1, g_W1);
    cudaGetSymbolAddress((void**)&W2, g_W2);
    cudaGetSymbolAddress((void**)&H,  g_H);

    static cudaStream_t s_side = nullptr, s_b = nullptr;
    static cudaEvent_t ev_fork = nullptr, ev_w = nullptr, ev_tok = nullptr,
                       ev_bdone = nullptr;
    if (!s_side) {
        cudaStreamCreateWithFlags(&s_side, cudaStreamNonBlocking);
        cudaStreamCreateWithFlags(&s_b,    cudaStreamNonBlocking);
        cudaEventCreateWithFlags(&ev_fork,  cudaEventDisableTiming);
        cudaEventCreateWithFlags(&ev_w,     cudaEventDisableTiming);
        cudaEventCreateWithFlags(&ev_tok,   cudaEventDisableTiming);
        cudaEventCreateWithFlags(&ev_bdone, cudaEventDisableTiming);
        cudaFuncSetAttribute(mma_gemm1_kernel,
                             cudaFuncAttributeMaxDynamicSharedMemorySize, GEMM1_SMEM);
        cudaFuncSetAttribute(mma_gemm2_kernel,
                             cudaFuncAttributeMaxDynamicSharedMemorySize, GEMM2_SMEM);
    }

    const size_t elemsPerHalf = (size_t)BH * C_SZ * HW;   // fp32 elements
    const int cxBlocks = (int)(elemsPerHalf / 8 / 256);

    // fork
    cudaEventRecord(ev_fork, 0);
    cudaStreamWaitEvent(s_side, ev_fork, 0);
    cudaStreamWaitEvent(s_b,    ev_fork, 0);

    // side stream: weight converts, then token MLP
    convert_w_kernel<<<(1024 * C_SZ + 255) / 256, 256, 0, s_side>>>(
        cf_w1, sc_w1, cf_b1, sc_b1);
    convert_w2_kernel<<<(192 * HID + 255) / 256, 256, 0, s_side>>>(
        cf_w2, sc_w2, cf_b2, sc_b2);
    cudaEventRecord(ev_w, s_side);
    token_kernel<<<B_SZ, 256, 0, s_side>>>(t, tk_w1, tk_b1, tk_w2, tk_b2);
    cudaEventRecord(ev_tok, s_side);

    // ---- chain h0 on stream 0 ----
    convert_x_kernel<<<cxBlocks, 256>>>((const float4*)x, 0);
    cudaStreamWaitEvent(0, ev_w, 0);
    mma_gemm1_kernel<<<dim3(HW / NT, 1024 / MT, BH), 256, GEMM1_SMEM>>>(
        W1, X, B1, H, 0);
    mma_gemm2_kernel<<<dim3(HW / NT2, 3, BH), 256, GEMM2_SMEM>>>(
        W2, H, B2, F, Z, 0);
    sinkhorn_kernel<<<BH, 1024>>>(dust, 0);
    agg_kernel<<<dim3(4, BH), 256>>>(0);
    cudaStreamWaitEvent(0, ev_tok, 0);
    finalize_kernel<<<BH, 256>>>((float*)d_out, 0);

    // ---- chain h1 on s_b ----
    convert_x_kernel<<<cxBlocks, 256, 0, s_b>>>((const float4*)x, elemsPerHalf);
    cudaStreamWaitEvent(s_b, ev_w, 0);
    mma_gemm1_kernel<<<dim3(HW / NT, 1024 / MT, BH), 256, GEMM1_SMEM, s_b>>>(
        W1, X, B1, H, BH);
    mma_gemm2_kernel<<<dim3(HW / NT2, 3, BH), 256, GEMM2_SMEM, s_b>>>(
        W2, H, B2, F, Z, BH);
    sinkhorn_kernel<<<BH, 1024, 0, s_b>>>(dust, BH);
    agg_kernel<<<dim3(4, BH), 256, 0, s_b>>>(BH);
    cudaStreamWaitEvent(s_b, ev_tok, 0);
    finalize_kernel<<<BH, 256, 0, s_b>>>((float*)d_out, BH);
    cudaEventRecord(ev_bdone, s_b);

    // join everything into stream 0
    cudaStreamWaitEvent(0, ev_bdone, 0);
}

// round 11
// speedup vs baseline: 7.7238x; 1.0816x over previous
#include <cuda_runtime.h>
#include <cuda_fp16.h>
#include <math.h>
#include <stdint.h>

// ---------------------------------------------------------------------------
// SALAD pipeline. Round 11: minimal launch count (8 kernels), gemm2 rebuilt
// as a gemm1-clone (128x128, 2 CTAs/SM, padded W2), single side stream (R8
// structure). Precision frozen at R7 level (fp16 single-product HMMA).
// ---------------------------------------------------------------------------

#define B_SZ 32
#define C_SZ 1536
#define HW   1024
#define HID  512
#define L_D  128
#define M_CL 64
#define G_D  256
#define EPSV 1e-12f

__device__ __align__(256) __half g_H[(size_t)B_SZ * 1024 * HW];      // H [b][k][n]
__device__ __align__(256) float g_F[(size_t)B_SZ * L_D * HW];
__device__ __align__(256) float g_Z[(size_t)B_SZ * (M_CL + 1) * HW];
__device__ __align__(256) float g_AGG[(size_t)B_SZ * L_D * M_CL];
__device__ __align__(256) float g_TK[(size_t)B_SZ * G_D];

__device__ __align__(256) __half g_X[(size_t)B_SZ * C_SZ * HW];  // x [b][c][n]
__device__ __align__(256) __half g_W1[(size_t)1024 * C_SZ];      // [cf_w1; sc_w1]
__device__ __align__(256) __half g_W2[(size_t)256 * HID];        // [cf_w2; sc_w2; 0pad]
__device__ __align__(256) float g_B1c[1024];
__device__ __align__(256) float g_B2c[256];                      // padded

// ---------------------------------------------------------------------------
__device__ __forceinline__ uint32_t smem_u32(const void* p) {
    uint32_t a;
    asm("{ .reg .u64 t; cvta.to.shared.u64 t, %1; cvt.u32.u64 %0, t; }"
        : "=r"(a) : "l"(p));
    return a;
}

__device__ __forceinline__ void cp16(uint32_t saddr, const void* gaddr) {
    asm volatile("cp.async.cg.shared.global [%0], [%1], 16;"
                 :: "r"(saddr), "l"(gaddr) : "memory");
}

#define LDSM_X4(r0, r1, r2, r3, addr) \
    asm volatile("ldmatrix.sync.aligned.m8n8.x4.shared.b16 {%0,%1,%2,%3}, [%4];" \
                 : "=r"(r0), "=r"(r1), "=r"(r2), "=r"(r3) : "r"(addr))

#define LDSM_X4_T(r0, r1, r2, r3, addr) \
    asm volatile("ldmatrix.sync.aligned.m8n8.x4.trans.shared.b16 {%0,%1,%2,%3}, [%4];" \
                 : "=r"(r0), "=r"(r1), "=r"(r2), "=r"(r3) : "r"(addr))

#define MMA_F16(d, a, b0, b1) \
    asm volatile("mma.sync.aligned.m16n8k16.row.col.f32.f16.f16.f32 " \
                 "{%0,%1,%2,%3}, {%4,%5,%6,%7}, {%8,%9}, {%0,%1,%2,%3};" \
                 : "+f"((d)[0]), "+f"((d)[1]), "+f"((d)[2]), "+f"((d)[3]) \
                 : "r"((a)[0]), "r"((a)[1]), "r"((a)[2]), "r"((a)[3]), \
                   "r"(b0), "r"(b1))

// ---------------------------------------------------------------------------
// Merged weight conversion: W1, W2(padded), b1, b2 in one kernel.
// ---------------------------------------------------------------------------
__global__ __launch_bounds__(256)
void convert_all_kernel(const float* __restrict__ cf_w1, const float* __restrict__ sc_w1,
                        const float* __restrict__ cf_b1, const float* __restrict__ sc_b1,
                        const float* __restrict__ cf_w2, const float* __restrict__ sc_w2,
                        const float* __restrict__ cf_b2, const float* __restrict__ sc_b2)
{
    size_t idx = (size_t)blockIdx.x * 256 + threadIdx.x;
    const size_t totalW1 = (size_t)1024 * C_SZ;
    if (idx < totalW1) {
        float v = (idx < (size_t)HID * C_SZ) ? cf_w1[idx]
                                             : sc_w1[idx - (size_t)HID * C_SZ];
        g_W1[idx] = __float2half_rn(v);
    }
    if (idx < (size_t)256 * HID) {
        size_t row = idx / HID;
        float v = 0.f;
        if (row < L_D)      v = cf_w2[idx];
        else if (row < 192) v = sc_w2[idx - (size_t)L_D * HID];
        g_W2[idx] = __float2half_rn(v);
    }
    if (idx < 1024)
        g_B1c[idx] = (idx < HID) ? cf_b1[idx] : sc_b1[idx - HID];
    if (idx < 256)
        g_B2c[idx] = (idx < L_D) ? cf_b2[idx]
                   : (idx < 192) ? sc_b2[idx - L_D] : 0.f;
}

// Streaming cast x fp32 -> fp16 (8 elems/thread)
__global__ __launch_bounds__(256)
void convert_x_kernel(const float4* __restrict__ x)
{
    const size_t i = (size_t)blockIdx.x * 256 + threadIdx.x;
    float4 a = x[2 * i];
    float4 b = x[2 * i + 1];
    __half2 h0 = __floats2half2_rn(a.x, a.y);
    __half2 h1 = __floats2half2_rn(a.z, a.w);
    __half2 h2 = __floats2half2_rn(b.x, b.y);
    __half2 h3 = __floats2half2_rn(b.z, b.w);
    uint4 o;
    o.x = *reinterpret_cast<uint32_t*>(&h0);
    o.y = *reinterpret_cast<uint32_t*>(&h1);
    o.z = *reinterpret_cast<uint32_t*>(&h2);
    o.w = *reinterpret_cast<uint32_t*>(&h3);
    reinterpret_cast<uint4*>(g_X)[i] = o;
}

// ---------------------------------------------------------------------------
// GEMM1 (fp16 HMMA): H[b] = relu(W1 @ X[b] + b1) -> fp16
//   CTA 128x128, K-chunk 64, 3-stage cp.async, 2 CTAs/SM.
// ---------------------------------------------------------------------------
#define MT 128
#define NT 128
#define KC 64
#define NK1 (C_SZ / KC)               // 24
#define OFF_A 0
#define OFF_B (16 * 1024)
#define STAGE_BYTES (32 * 1024)
#define GEMM_SMEM (3 * STAGE_BYTES)   // 96 KB

__global__ __launch_bounds__(256, 2)
void mma_gemm1_kernel(const __half* __restrict__ W1, const __half* __restrict__ X,
                      const float* __restrict__ bias, __half* __restrict__ H)
{
    extern __shared__ char dsmem[];
    const uint32_t smem_base = smem_u32(dsmem);

    const int tid = threadIdx.x;
    const int b  = blockIdx.z;
    const int n0 = blockIdx.x * NT;
    const int m0 = blockIdx.y * MT;

    const __half* Ag = W1 + (size_t)m0 * C_SZ;
    const __half* Bg = X + (size_t)b * C_SZ * HW + n0;

    const int lane = tid & 31, warp = tid >> 5;
    const int wm = warp >> 2, wn = warp & 3;

    const uint32_t lx = (uint32_t)(lane & 7);
    const uint32_t aG = (uint32_t)(lane >> 4);
    const uint32_t aRowOff = (uint32_t)(wm * 64 + (lane & 15)) * 128u;
    const uint32_t bRowOff = (uint32_t)(lane & 15) * 256u;
    const uint32_t bGbase = (uint32_t)(wn * 4) + (uint32_t)(lane >> 4);

    float acc[4][4][4];
    #pragma unroll
    for (int i = 0; i < 4; ++i)
        #pragma unroll
        for (int j = 0; j < 4; ++j)
            #pragma unroll
            for (int q = 0; q < 4; ++q) acc[i][j][q] = 0.f;

    auto load_chunk = [&](int c) {
        const uint32_t sb = smem_base + (uint32_t)(c % 3) * STAGE_BYTES;
        const size_t kk = (size_t)c * KC;
        #pragma unroll
        for (int i = 0; i < 4; ++i) {
            int idx = tid + 256 * i;
            int r = idx >> 3, g = idx & 7;
            uint32_t so = (uint32_t)r * 128u + (uint32_t)((g ^ (r & 7)) << 4);
            cp16(sb + OFF_A + so, (const char*)(Ag + (size_t)r * C_SZ + kk) + g * 16);
        }
        #pragma unroll
        for (int i = 0; i < 4; ++i) {
            int idx = tid + 256 * i;
            int r = idx >> 4, g = idx & 15;
            uint32_t so = (uint32_t)r * 256u + (uint32_t)((g ^ (r & 7)) << 4);
            cp16(sb + OFF_B + so, (const char*)(Bg + (kk + r) * HW) + g * 16);
        }
        asm volatile("cp.async.commit_group;" ::: "memory");
    };

    load_chunk(0);
    load_chunk(1);

    for (int c = 0; c < NK1; ++c) {
        if (c + 2 < NK1) {
            load_chunk(c + 2);
            asm volatile("cp.async.wait_group 2;" ::: "memory");
        } else if (c + 1 < NK1) {
            asm volatile("cp.async.wait_group 1;" ::: "memory");
        } else {
            asm volatile("cp.async.wait_group 0;" ::: "memory");
        }
        __syncthreads();

        const uint32_t sb = smem_base + (uint32_t)(c % 3) * STAGE_BYTES;

        #pragma unroll
        for (int ks = 0; ks < 4; ++ks) {
            const uint32_t gA = ((uint32_t)(ks * 2) + aG) ^ lx;
            const uint32_t bRow = (uint32_t)(ks * 16) * 256u + bRowOff;

            uint32_t ah[16], bh[8];
            #pragma unroll
            for (int ma = 0; ma < 4; ++ma) {
                uint32_t ad = sb + OFF_A + aRowOff + (uint32_t)(ma * 16 * 128) + (gA << 4);
                LDSM_X4(ah[4*ma+0], ah[4*ma+1], ah[4*ma+2], ah[4*ma+3], ad);
            }
            #pragma unroll
            for (int nb = 0; nb < 2; ++nb) {
                uint32_t gB = (bGbase + (uint32_t)(nb * 2)) ^ lx;
                uint32_t bd = sb + OFF_B + bRow + (gB << 4);
                LDSM_X4_T(bh[4*nb+0], bh[4*nb+1], bh[4*nb+2], bh[4*nb+3], bd);
            }
            #pragma unroll
            for (int ma = 0; ma < 4; ++ma)
                #pragma unroll
                for (int na = 0; na < 4; ++na)
                    MMA_F16(acc[ma][na], &ah[4*ma], bh[2*na], bh[2*na+1]);
        }
        __syncthreads();
    }

    const int g  = lane >> 2;
    const int tc = lane & 3;
    #pragma unroll
    for (int ma = 0; ma < 4; ++ma) {
        const int r0 = m0 + wm * 64 + ma * 16 + g;
        const int r1 = r0 + 8;
        const float bb0 = bias[r0];
        const float bb1 = bias[r1];
        const size_t base0 = ((size_t)b * 1024 + r0) * HW + n0 + wn * 32 + tc * 2;
        const size_t base1 = ((size_t)b * 1024 + r1) * HW + n0 + wn * 32 + tc * 2;
        #pragma unroll
        for (int na = 0; na < 4; ++na) {
            float v00 = fmaxf(acc[ma][na][0] + bb0, 0.f);
            float v01 = fmaxf(acc[ma][na][1] + bb0, 0.f);
            float v10 = fmaxf(acc[ma][na][2] + bb1, 0.f);
            float v11 = fmaxf(acc[ma][na][3] + bb1, 0.f);
            *reinterpret_cast<__half2*>(H + base0 + na * 8) = __floats2half2_rn(v00, v01);
            *reinterpret_cast<__half2*>(H + base1 + na * 8) = __floats2half2_rn(v10, v11);
        }
    }
}

// ---------------------------------------------------------------------------
// GEMM2 (fp16 HMMA), gemm1-clone: [F; Z] = W2p @ H + b2p
//   W2p: [256][512] padded (rows 192-255 zero). blockIdx.y: 0 -> rows 0-127
//   (F, cf hidden k=0..511), 1 -> rows 128-255 (Z + pad, sc hidden k=512..1023).
//   CTA 128x128, K=512 (8 chunks), 3-stage, 2 CTAs/SM.
// ---------------------------------------------------------------------------
#define NK2 (HID / KC)                // 8

__global__ __launch_bounds__(256, 2)
void mma_gemm2_kernel(const __half* __restrict__ W2p, const __half* __restrict__ H,
                      const float* __restrict__ bias,
                      float* __restrict__ Fout, float* __restrict__ Zout)
{
    extern __shared__ char dsmem[];
    const uint32_t smem_base = smem_u32(dsmem);

    const int tid = threadIdx.x;
    const int b  = blockIdx.z;
    const int n0 = blockIdx.x * NT;
    const int m0 = blockIdx.y * MT;                // 0 or 128
    const int koff = (m0 == 128) ? 512 : 0;

    const __half* Ag = W2p + (size_t)m0 * HID;
    const __half* Bg = H + ((size_t)b * 1024 + koff) * HW + n0;

    const int lane = tid & 31, warp = tid >> 5;
    const int wm = warp >> 2, wn = warp & 3;

    const uint32_t lx = (uint32_t)(lane & 7);
    const uint32_t aG = (uint32_t)(lane >> 4);
    const uint32_t aRowOff = (uint32_t)(wm * 64 + (lane & 15)) * 128u;
    const uint32_t bRowOff = (uint32_t)(lane & 15) * 256u;
    const uint32_t bGbase = (uint32_t)(wn * 4) + (uint32_t)(lane >> 4);

    float acc[4][4][4];
    #pragma unroll
    for (int i = 0; i < 4; ++i)
        #pragma unroll
        for (int j = 0; j < 4; ++j)
            #pragma unroll
            for (int q = 0; q < 4; ++q) acc[i][j][q] = 0.f;

    auto load_chunk = [&](int c) {
        const uint32_t sb = smem_base + (uint32_t)(c % 3) * STAGE_BYTES;
        const size_t kk = (size_t)c * KC;
        #pragma unroll
        for (int i = 0; i < 4; ++i) {
            int idx = tid + 256 * i;
            int r = idx >> 3, g = idx & 7;
            uint32_t so = (uint32_t)r * 128u + (uint32_t)((g ^ (r & 7)) << 4);
            cp16(sb + OFF_A + so, (const char*)(Ag + (size_t)r * HID + kk) + g * 16);
        }
        #pragma unroll
        for (int i = 0; i < 4; ++i) {
            int idx = tid + 256 * i;
            int r = idx >> 4, g = idx & 15;
            uint32_t so = (uint32_t)r * 256u + (uint32_t)((g ^ (r & 7)) << 4);
            cp16(sb + OFF_B + so, (const char*)(Bg + (kk + r) * HW) + g * 16);
        }
        asm volatile("cp.async.commit_group;" ::: "memory");
    };

    load_chunk(0);
    load_chunk(1);

    for (int c = 0; c < NK2; ++c) {
        if (c + 2 < NK2) {
            load_chunk(c + 2);
            asm volatile("cp.async.wait_group 2;" ::: "memory");
        } else if (c + 1 < NK2) {
            asm volatile("cp.async.wait_group 1;" ::: "memory");
        } else {
            asm volatile("cp.async.wait_group 0;" ::: "memory");
        }
        __syncthreads();

        const uint32_t sb = smem_base + (uint32_t)(c % 3) * STAGE_BYTES;

        #pragma unroll
        for (int ks = 0; ks < 4; ++ks) {
            const uint32_t gA = ((uint32_t)(ks * 2) + aG) ^ lx;
            const uint32_t bRow = (uint32_t)(ks * 16) * 256u + bRowOff;

            uint32_t ah[16], bh[8];
            #pragma unroll
            for (int ma = 0; ma < 4; ++ma) {
                uint32_t ad = sb + OFF_A + aRowOff + (uint32_t)(ma * 16 * 128) + (gA << 4);
                LDSM_X4(ah[4*ma+0], ah[4*ma+1], ah[4*ma+2], ah[4*ma+3], ad);
            }
            #pragma unroll
            for (int nb = 0; nb < 2; ++nb) {
                uint32_t gB = (bGbase + (uint32_t)(nb * 2)) ^ lx;
                uint32_t bd = sb + OFF_B + bRow + (gB << 4);
                LDSM_X4_T(bh[4*nb+0], bh[4*nb+1], bh[4*nb+2], bh[4*nb+3], bd);
            }
            #pragma unroll
            for (int ma = 0; ma < 4; ++ma)
                #pragma unroll
                for (int na = 0; na < 4; ++na)
                    MMA_F16(acc[ma][na], &ah[4*ma], bh[2*na], bh[2*na+1]);
        }
        __syncthreads();
    }

    // epilogue: rows 0-127 -> F, 128-191 -> Z, 192-255 discarded
    const int g  = lane >> 2;
    const int tc = lane & 3;
    #pragma unroll
    for (int ma = 0; ma < 4; ++ma) {
        const int r0 = m0 + wm * 64 + ma * 16 + g;
        const int r1 = r0 + 8;
        const float bb0 = bias[r0];
        const float bb1 = bias[r1];
        float* p0 = nullptr;
        float* p1 = nullptr;
        if (r0 < L_D)      p0 = Fout + ((size_t)b * L_D + r0) * HW;
        else if (r0 < 192) p0 = Zout + ((size_t)b * (M_CL + 1) + (r0 - L_D)) * HW;
        if (r1 < L_D)      p1 = Fout + ((size_t)b * L_D + r1) * HW;
        else if (r1 < 192) p1 = Zout + ((size_t)b * (M_CL + 1) + (r1 - L_D)) * HW;
        const int coff = n0 + wn * 32 + tc * 2;
        #pragma unroll
        for (int na = 0; na < 4; ++na) {
            if (p0) {
                float2 v0;
                v0.x = acc[ma][na][0] + bb0;
                v0.y = acc[ma][na][1] + bb0;
                *reinterpret_cast<float2*>(p0 + coff + na * 8) = v0;
            }
            if (p1) {
                float2 v1;
                v1.x = acc[ma][na][2] + bb1;
                v1.y = acc[ma][na][3] + bb1;
                *reinterpret_cast<float2*>(p1 + coff + na * 8) = v1;
            }
        }
    }
}

// ---------------------------------------------------------------------------
// Fused token MLP
// ---------------------------------------------------------------------------
__global__ __launch_bounds__(256)
void token_kernel(const float* __restrict__ t,
                  const float* __restrict__ w1, const float* __restrict__ b1,
                  const float* __restrict__ w2, const float* __restrict__ b2)
{
    __shared__ float ts[C_SZ];
    __shared__ float hs[HID];
    const int b = blockIdx.x;
    for (int c = threadIdx.x; c < C_SZ; c += 256) ts[c] = t[(size_t)b * C_SZ + c];
    __syncthreads();
    const int wid = threadIdx.x >> 5, lane = threadIdx.x & 31;
    for (int o = wid; o < HID; o += 8) {
        const float* wr = w1 + (size_t)o * C_SZ;
        float s = 0.f;
        for (int c = lane; c < C_SZ; c += 32) s = fmaf(ts[c], wr[c], s);
        #pragma unroll
        for (int off = 16; off; off >>= 1) s += __shfl_xor_sync(0xFFFFFFFFu, s, off);
        if (lane == 0) hs[o] = fmaxf(s + b1[o], 0.f);
    }
    __syncthreads();
    for (int o = wid; o < G_D; o += 8) {
        const float* wr = w2 + (size_t)o * HID;
        float s = 0.f;
        for (int c = lane; c < HID; c += 32) s = fmaf(hs[c], wr[c], s);
        #pragma unroll
        for (int off = 16; off; off >>= 1) s += __shfl_xor_sync(0xFFFFFFFFu, s, off);
        if (lane == 0) g_TK[(size_t)b * G_D + o] = s + b2[o];
    }
}

// ---------------------------------------------------------------------------
// Sinkhorn, 512 threads (2 columns/thread), one block per batch.
// ---------------------------------------------------------------------------
__global__ __launch_bounds__(512)
void sinkhorn_kernel(const float* __restrict__ alpha_p)
{
    const int b = blockIdx.x;
    float* Zb = g_Z + (size_t)b * (M_CL + 1) * HW;

    __shared__ float u[M_CL + 1];
    __shared__ float wsum[M_CL + 1][17];

    const int j = threadIdx.x;
    const int lane = j & 31, warp = j >> 5;   // 16 warps
    const float alpha = *alpha_p;
    const float norm = -logf((float)(M_CL + HW));
    const float log_mu_last = logf((float)(HW - M_CL)) + norm;

    float v0 = 0.f, v1 = 0.f;

    for (int it = 0; it < 3; ++it) {
        #pragma unroll 4
        for (int i = 0; i <= M_CL; ++i) {
            float z0, z1;
            if (i < M_CL) {
                z0 = Zb[(size_t)i * HW + j] + v0;
                z1 = Zb[(size_t)i * HW + j + 512] + v1;
            } else {
                z0 = alpha + v0;
                z1 = alpha + v1;
            }
            float e = __expf(z0) + __expf(z1);
            #pragma unroll
            for (int off = 16; off; off >>= 1) e += __shfl_xor_sync(0xFFFFFFFFu, e, off);
            if (lane == 0) wsum[i][warp] = e;
        }
        __syncthreads();
        if (j <= M_CL) {
            float s = 0.f;
            #pragma unroll
            for (int w = 0; w < 16; ++w) s += wsum[j][w];
            u[j] = ((j < M_CL) ? norm : log_mu_last) - logf(s);
        }
        __syncthreads();

        float s0 = 0.f, s1 = 0.f;
        #pragma unroll 8
        for (int i = 0; i < M_CL; ++i) {
            s0 += __expf(Zb[(size_t)i * HW + j] + u[i]);
            s1 += __expf(Zb[(size_t)i * HW + j + 512] + u[i]);
        }
        s0 += __expf(alpha + u[M_CL]);
        s1 += __expf(alpha + u[M_CL]);
        v0 = norm - logf(s0);
        v1 = norm - logf(s1);
    }

    #pragma unroll 8
    for (int i = 0; i < M_CL; ++i) {
        Zb[(size_t)i * HW + j]       = __expf(Zb[(size_t)i * HW + j] + u[i] + v0 - norm);
        Zb[(size_t)i * HW + j + 512] = __expf(Zb[(size_t)i * HW + j + 512] + u[i] + v1 - norm);
    }
}

// ---------------------------------------------------------------------------
// agg[b][l][m] = sum_n F[b][l][n] * P[b][m][n]; grid (4 l-quads, B)
// ---------------------------------------------------------------------------
__global__ __launch_bounds__(256)
void agg_kernel()
{
    const int b = blockIdx.y;
    const int l0 = blockIdx.x * 32;
    const float* Fb = g_F + (size_t)b * L_D * HW + (size_t)l0 * HW;
    const float* Pb = g_Z + (size_t)b * (M_CL + 1) * HW;
    float*       Cb = g_AGG + (size_t)b * L_D * M_CL + (size_t)l0 * M_CL;

    __shared__ float Fs[32][36];
    __shared__ float Ps[32][68];

    const int tid = threadIdx.x;
    const int tx = tid & 15, ty = tid >> 4;

    float acc[2][4];
    #pragma unroll
    for (int i = 0; i < 2; ++i)
        #pragma unroll
        for (int j = 0; j < 4; ++j) acc[i][j] = 0.f;

    for (int n0 = 0; n0 < HW; n0 += 32) {
        {
            int l = tid >> 3, kq = (tid & 7) << 2;
            float4 fv = *reinterpret_cast<const float4*>(&Fb[(size_t)l * HW + n0 + kq]);
            Fs[kq + 0][l] = fv.x; Fs[kq + 1][l] = fv.y;
            Fs[kq + 2][l] = fv.z; Fs[kq + 3][l] = fv.w;
        }
        #pragma unroll
        for (int r = 0; r < 2; ++r) {
            int id = tid + 256 * r;
            int m = id >> 3, kq = (id & 7) << 2;
            float4 pv = *reinterpret_cast<const float4*>(&Pb[(size_t)m * HW + n0 + kq]);
            Ps[kq + 0][m] = pv.x; Ps[kq + 1][m] = pv.y;
            Ps[kq + 2][m] = pv.z; Ps[kq + 3][m] = pv.w;
        }
        __syncthreads();

        #pragma unroll
        for (int k = 0; k < 32; ++k) {
            float rl[2], rm[4];
            #pragma unroll
            for (int i = 0; i < 2; ++i) rl[i] = Fs[k][ty * 2 + i];
            #pragma unroll
            for (int j = 0; j < 4; ++j) rm[j] = Ps[k][tx * 4 + j];
            #pragma unroll
            for (int i = 0; i < 2; ++i)
                #pragma unroll
                for (int j = 0; j < 4; ++j)
                    acc[i][j] = fmaf(rl[i], rm[j], acc[i][j]);
        }
        __syncthreads();
    }

    #pragma unroll
    for (int i = 0; i < 2; ++i)
        #pragma unroll
        for (int j = 0; j < 4; ++j)
            Cb[(size_t)(ty * 2 + i) * M_CL + tx * 4 + j] = acc[i][j];
}

// ---------------------------------------------------------------------------
// Finalize (low smem)
// ---------------------------------------------------------------------------
__device__ __forceinline__ float block_sum256(float val, float* red)
{
    const int lane = threadIdx.x & 31, wid = threadIdx.x >> 5;
    #pragma unroll
    for (int off = 16; off; off >>= 1) val += __shfl_xor_sync(0xFFFFFFFFu, val, off);
    if (lane == 0) red[wid] = val;
    __syncthreads();
    float s = red[0] + red[1] + red[2] + red[3] + red[4] + red[5] + red[6] + red[7];
    __syncthreads();
    return s;
}

__global__ __launch_bounds__(256)
void finalize_kernel(float* __restrict__ out)
{
    const int b = blockIdx.x;
    const int tid = threadIdx.x;
    __shared__ float tkn[G_D];
    __shared__ float cn[M_CL];
    __shared__ float red[8];

    const float* aggb = g_AGG + (size_t)b * L_D * M_CL;

    float tv = g_TK[(size_t)b * G_D + tid];
    float tk_ss = block_sum256(tv * tv, red);
    tkn[tid] = tv / fmaxf(sqrtf(tk_ss), EPSV);

    if (tid < M_CL) {
        float s = 0.f;
        for (int l = 0; l < L_D; ++l) {
            float a = aggb[(size_t)l * M_CL + tid];
            s = fmaf(a, a, s);
        }
        cn[tid] = fmaxf(sqrtf(s), EPSV);
    }
    __syncthreads();

    float gs = tkn[tid] * tkn[tid];
    for (int idx = tid; idx < L_D * M_CL; idx += 256) {
        float a = aggb[idx] / cn[idx & (M_CL - 1)];
        gs = fmaf(a, a, gs);
    }
    float total = block_sum256(gs, red);
    float scale = 1.f / fmaxf(sqrtf(total), EPSV);

    float* ob = out + (size_t)b * (G_D + L_D * M_CL);
    ob[tid] = tkn[tid] * scale;
    for (int idx = tid; idx < L_D * M_CL; idx += 256)
        ob[G_D + idx] = (aggb[idx] / cn[idx & (M_CL - 1)]) * scale;
}

// ---------------------------------------------------------------------------
// Launch: single main chain + one side stream (weights + token MLP)
// ---------------------------------------------------------------------------
extern "C" void kernel_launch(void* const* d_in, const int* in_sizes, int n_in,
                              void* d_out, int out_size)
{
    const float* x      = (const float*)d_in[0];
    const float* t      = (const float*)d_in[1];
    const float* cf_w1  = (const float*)d_in[2];
    const float* cf_b1  = (const float*)d_in[3];
    const float* cf_w2  = (const float*)d_in[4];
    const float* cf_b2  = (const float*)d_in[5];
    const float* sc_w1  = (const float*)d_in[6];
    const float* sc_b1  = (const float*)d_in[7];
    const float* sc_w2  = (const float*)d_in[8];
    const float* sc_b2  = (const float*)d_in[9];
    const float* tk_w1  = (const float*)d_in[10];
    const float* tk_b1  = (const float*)d_in[11];
    const float* tk_w2  = (const float*)d_in[12];
    const float* tk_b2  = (const float*)d_in[13];
    const float* dust   = (const float*)d_in[14];

    float *F, *Z, *B1, *B2;
    __half *X, *W1, *W2, *H;
    cudaGetSymbolAddress((void**)&F,  g_F);
    cudaGetSymbolAddress((void**)&Z,  g_Z);
    cudaGetSymbolAddress((void**)&B1, g_B1c);
    cudaGetSymbolAddress((void**)&B2, g_B2c);
    cudaGetSymbolAddress((void**)&X,  g_X);
    cudaGetSymbolAddress((void**)&W1, g_W1);
    cudaGetSymbolAddress((void**)&W2, g_W2);
    cudaGetSymbolAddress((void**)&H,  g_H);

    static cudaStream_t s_side = nullptr;
    static cudaEvent_t ev_fork = nullptr, ev_w = nullptr, ev_tok = nullptr;
    if (!s_side) {
        cudaStreamCreateWithFlags(&s_side, cudaStreamNonBlocking);
        cudaEventCreateWithFlags(&ev_fork, cudaEventDisableTiming);
        cudaEventCreateWithFlags(&ev_w,    cudaEventDisableTiming);
        cudaEventCreateWithFlags(&ev_tok,  cudaEventDisableTiming);
        cudaFuncSetAttribute(mma_gemm1_kernel,
                             cudaFuncAttributeMaxDynamicSharedMemorySize, GEMM_SMEM);
        cudaFuncSetAttribute(mma_gemm2_kernel,
                             cudaFuncAttributeMaxDynamicSharedMemorySize, GEMM_SMEM);
    }

    // fork
    cudaEventRecord(ev_fork, 0);
    cudaStreamWaitEvent(s_side, ev_fork, 0);

    // side: merged weight conversion, then token MLP (overlaps convert_x)
    convert_all_kernel<<<(1024 * C_SZ + 255) / 256, 256, 0, s_side>>>(
        cf_w1, sc_w1, cf_b1, sc_b1, cf_w2, sc_w2, cf_b2, sc_b2);
    cudaEventRecord(ev_w, s_side);
    token_kernel<<<B_SZ, 256, 0, s_side>>>(t, tk_w1, tk_b1, tk_w2, tk_b2);
    cudaEventRecord(ev_tok, s_side);

    // main chain
    convert_x_kernel<<<(int)(((size_t)B_SZ * C_SZ * HW / 8 + 255) / 256), 256>>>(
        (const float4*)x);
    cudaStreamWaitEvent(0, ev_w, 0);
    mma_gemm1_kernel<<<dim3(HW / NT, 1024 / MT, B_SZ), 256, GEMM_SMEM>>>(
        W1, X, B1, H);
    mma_gemm2_kernel<<<dim3(HW / NT, 2, B_SZ), 256, GEMM_SMEM>>>(
        W2, H, B2, F, Z);
    sinkhorn_kernel<<<B_SZ, 512>>>(dust);
    agg_kernel<<<dim3(4, B_SZ), 256>>>();
    cudaStreamWaitEvent(0, ev_tok, 0);
    finalize_kernel<<<B_SZ, 256>>>((float*)d_out);
}